// round 2
// baseline (speedup 1.0000x reference)
#include <cuda_runtime.h>
#include <cstdint>
#include <cstddef>

// Problem shape (fixed): B=4, S=2048, D=1024, H=4
#define TOK    8192          // B*S
#define DIM    1024
#define NHEAD  4
#define SEQ    2048
#define NBATCH 4

// ---------------------------------------------------------------------------
// Scratch: ONE device-global symbol, 640 MB, with buffer aliasing.
//   [0      , 33.5M )  q      [h][t][d]            -> later reused as heads
//   [33.5M  , 67.1M )  k      [h][t][d]            -> later reused as proj/y/z2
//   [67.1M  , 100.7M)  v      [h][t][d]
//   [100.7M , 167.8M)  scores [z=h*4+b][s][t]
// Aliasing is hazard-free: heads is written only after q's last read (QK^T);
// proj/y/z2 are written only after k's last read (QK^T).
// ---------------------------------------------------------------------------
#define OFF_Q  ((size_t)0)
#define OFF_K  ((size_t)33554432)
#define OFF_V  ((size_t)67108864)
#define OFF_SC ((size_t)100663296)
#define SCRATCH_FLOATS ((size_t)167772160)

__device__ float g_scratch[SCRATCH_FLOATS];

// ---------------------------------------------------------------------------
// Helpers
// ---------------------------------------------------------------------------
__device__ __forceinline__ uint32_t f2tf(float x) {
    uint32_t y;
    asm("cvt.rna.tf32.f32 %0, %1;" : "=r"(y) : "f"(x));
    return y;
}

__device__ __forceinline__ void mma_tf32(float acc[4], const uint32_t a[4], const uint32_t b[2]) {
    asm volatile(
        "mma.sync.aligned.m16n8k8.row.col.f32.tf32.tf32.f32 "
        "{%0,%1,%2,%3}, {%4,%5,%6,%7}, {%8,%9}, {%0,%1,%2,%3};\n"
        : "+f"(acc[0]), "+f"(acc[1]), "+f"(acc[2]), "+f"(acc[3])
        : "r"(a[0]), "r"(a[1]), "r"(a[2]), "r"(a[3]), "r"(b[0]), "r"(b[1]));
}

__device__ __forceinline__ float warpReduceSum(float v) {
    #pragma unroll
    for (int o = 16; o > 0; o >>= 1) v += __shfl_xor_sync(0xffffffffu, v, o);
    return v;
}
__device__ __forceinline__ float warpReduceMax(float v) {
    #pragma unroll
    for (int o = 16; o > 0; o >>= 1) v = fmaxf(v, __shfl_xor_sync(0xffffffffu, v, o));
    return v;
}

// ---------------------------------------------------------------------------
// Generic TF32 GEMM: C[z] = alpha * A[z] @ op(B[z]) + bias[z]
//   A: row-major [M,K] (or gather over heads-concat [t][h*D] when GATHER)
//   BNT=0: B row-major [K,N]   (NN)
//   BNT=1: B row-major [N,K]   (NT, i.e. C = A @ B^T)
// Tiles: BM=BN=128, BK=16; 256 threads; warp tile 32x64 via m16n8k8.
// All dims are exact multiples of the tile sizes for every call here.
// ---------------------------------------------------------------------------
template<int BNT, bool GATHER>
__global__ void __launch_bounds__(256)
gemm_tf32(const float* __restrict__ A, long long sA,
          const float* __restrict__ B, long long sB,
          const float* __restrict__ bias, long long sBias,
          float* __restrict__ C, long long sC,
          int K, int lda, int ldb, int ldc, float alpha)
{
    __shared__ uint32_t As[2][16][132];
    __shared__ uint32_t Bs[2][16][132];

    const int z = blockIdx.z;
    A += (size_t)z * sA;
    B += (size_t)z * sB;
    C += (size_t)z * sC;
    const float* bptr = bias ? bias + (size_t)z * sBias : nullptr;

    const int tid = threadIdx.x;
    const int m0 = blockIdx.y * 128;
    const int n0 = blockIdx.x * 128;

    float4 ra[2], rb[2];
    const int NKT = K >> 4;

    auto fetch = [&](int kt) {
        #pragma unroll
        for (int t = 0; t < 2; t++) {
            int id = tid + t * 256;
            int row = id >> 2, kq = (id & 3) << 2;
            int kk = kt * 16 + kq;
            const float* p;
            if (GATHER) {
                // A is the logical [TOK, H*D] concat of heads stored as
                // [h][t][d]: col kk -> head kk>>10, inner d = kk & 1023.
                p = A + ((size_t)(kk >> 10)) * ((size_t)TOK * DIM)
                      + (size_t)(m0 + row) * DIM + (kk & (DIM - 1));
            } else {
                p = A + (size_t)(m0 + row) * lda + kk;
            }
            ra[t] = *(const float4*)p;
        }
        #pragma unroll
        for (int t = 0; t < 2; t++) {
            int id = tid + t * 256;
            if (BNT == 0) {
                int k = id >> 5, nq = (id & 31) << 2;
                rb[t] = *(const float4*)(B + (size_t)(kt * 16 + k) * ldb + n0 + nq);
            } else {
                int n = id >> 2, kq = (id & 3) << 2;
                rb[t] = *(const float4*)(B + (size_t)(n0 + n) * ldb + kt * 16 + kq);
            }
        }
    };

    auto stage = [&](int buf) {
        #pragma unroll
        for (int t = 0; t < 2; t++) {
            int id = tid + t * 256;
            int row = id >> 2, kq = (id & 3) << 2;
            As[buf][kq + 0][row] = f2tf(ra[t].x);
            As[buf][kq + 1][row] = f2tf(ra[t].y);
            As[buf][kq + 2][row] = f2tf(ra[t].z);
            As[buf][kq + 3][row] = f2tf(ra[t].w);
        }
        #pragma unroll
        for (int t = 0; t < 2; t++) {
            int id = tid + t * 256;
            if (BNT == 0) {
                int k = id >> 5, nq = (id & 31) << 2;
                Bs[buf][k][nq + 0] = f2tf(rb[t].x);
                Bs[buf][k][nq + 1] = f2tf(rb[t].y);
                Bs[buf][k][nq + 2] = f2tf(rb[t].z);
                Bs[buf][k][nq + 3] = f2tf(rb[t].w);
            } else {
                int n = id >> 2, kq = (id & 3) << 2;
                Bs[buf][kq + 0][n] = f2tf(rb[t].x);
                Bs[buf][kq + 1][n] = f2tf(rb[t].y);
                Bs[buf][kq + 2][n] = f2tf(rb[t].z);
                Bs[buf][kq + 3][n] = f2tf(rb[t].w);
            }
        }
    };

    const int lane = tid & 31, warp = tid >> 5;
    const int wm = warp >> 1, wn = warp & 1;     // 4x2 warp grid -> 32x64 per warp
    const int g = lane >> 2, tg = lane & 3;

    float acc[2][8][4];
    #pragma unroll
    for (int i = 0; i < 2; i++)
        #pragma unroll
        for (int j = 0; j < 8; j++)
            #pragma unroll
            for (int r = 0; r < 4; r++) acc[i][j][r] = 0.f;

    fetch(0);
    stage(0);
    __syncthreads();
    int cur = 0;
    for (int kt = 0; kt < NKT; kt++) {
        if (kt + 1 < NKT) fetch(kt + 1);
        #pragma unroll
        for (int ks = 0; ks < 2; ks++) {
            const int kk = ks * 8;
            uint32_t af[2][4], bf[8][2];
            #pragma unroll
            for (int mt = 0; mt < 2; mt++) {
                int r = wm * 32 + mt * 16 + g;
                af[mt][0] = As[cur][kk + tg][r];
                af[mt][1] = As[cur][kk + tg][r + 8];
                af[mt][2] = As[cur][kk + tg + 4][r];
                af[mt][3] = As[cur][kk + tg + 4][r + 8];
            }
            #pragma unroll
            for (int nt = 0; nt < 8; nt++) {
                int c = wn * 64 + nt * 8 + g;
                bf[nt][0] = Bs[cur][kk + tg][c];
                bf[nt][1] = Bs[cur][kk + tg + 4][c];
            }
            #pragma unroll
            for (int mt = 0; mt < 2; mt++)
                #pragma unroll
                for (int nt = 0; nt < 8; nt++)
                    mma_tf32(acc[mt][nt], af[mt], bf[nt]);
        }
        if (kt + 1 < NKT) stage(cur ^ 1);
        __syncthreads();
        cur ^= 1;
    }

    // Epilogue: C = alpha*acc + bias
    #pragma unroll
    for (int mt = 0; mt < 2; mt++) {
        int r0 = m0 + wm * 32 + mt * 16 + g;
        #pragma unroll
        for (int nt = 0; nt < 8; nt++) {
            int c = n0 + wn * 64 + nt * 8 + tg * 2;
            float b0 = 0.f, b1 = 0.f;
            if (bptr) { b0 = bptr[c]; b1 = bptr[c + 1]; }
            float2 vv;
            vv.x = alpha * acc[mt][nt][0] + b0;
            vv.y = alpha * acc[mt][nt][1] + b1;
            *(float2*)(C + (size_t)r0 * ldc + c) = vv;
            vv.x = alpha * acc[mt][nt][2] + b0;
            vv.y = alpha * acc[mt][nt][3] + b1;
            *(float2*)(C + (size_t)(r0 + 8) * ldc + c) = vv;
        }
    }
}

// ---------------------------------------------------------------------------
// Row softmax over 2048 cols, in place. One block (256 thr) per row.
// ---------------------------------------------------------------------------
__global__ void __launch_bounds__(256) softmax_kernel(float* __restrict__ S)
{
    __shared__ float sh[32];
    __shared__ float bval;
    float* row = S + (size_t)blockIdx.x * SEQ;
    const int tid = threadIdx.x;

    float4 v0 = ((float4*)row)[tid];
    float4 v1 = ((float4*)row)[tid + 256];

    float m = fmaxf(fmaxf(fmaxf(v0.x, v0.y), fmaxf(v0.z, v0.w)),
                    fmaxf(fmaxf(v1.x, v1.y), fmaxf(v1.z, v1.w)));
    m = warpReduceMax(m);
    if ((tid & 31) == 0) sh[tid >> 5] = m;
    __syncthreads();
    if (tid < 32) {
        float t = (tid < 8) ? sh[tid] : -3.4e38f;
        t = warpReduceMax(t);
        if (tid == 0) bval = t;
    }
    __syncthreads();
    m = bval;

    v0.x = __expf(v0.x - m); v0.y = __expf(v0.y - m);
    v0.z = __expf(v0.z - m); v0.w = __expf(v0.w - m);
    v1.x = __expf(v1.x - m); v1.y = __expf(v1.y - m);
    v1.z = __expf(v1.z - m); v1.w = __expf(v1.w - m);
    float s = v0.x + v0.y + v0.z + v0.w + v1.x + v1.y + v1.z + v1.w;
    s = warpReduceSum(s);
    if ((tid & 31) == 0) sh[tid >> 5] = s;
    __syncthreads();
    if (tid < 32) {
        float t = (tid < 8) ? sh[tid] : 0.f;
        t = warpReduceSum(t);
        if (tid == 0) bval = 1.0f / t;
    }
    __syncthreads();
    const float inv = bval;

    v0.x *= inv; v0.y *= inv; v0.z *= inv; v0.w *= inv;
    v1.x *= inv; v1.y *= inv; v1.z *= inv; v1.w *= inv;
    ((float4*)row)[tid] = v0;
    ((float4*)row)[tid + 256] = v1;
}

// ---------------------------------------------------------------------------
// out = LayerNorm(a + b) * gamma + beta   (rows of D=1024; biased var, eps=1e-5)
// ---------------------------------------------------------------------------
__global__ void __launch_bounds__(256) add_ln_kernel(
    const float* __restrict__ A, const float* __restrict__ Bv,
    const float* __restrict__ gamma, const float* __restrict__ beta,
    float* __restrict__ O)
{
    __shared__ float sh1[32], sh2[32];
    __shared__ float2 stats;
    const size_t base = (size_t)blockIdx.x * DIM;
    const int tid = threadIdx.x;

    float4 a = ((const float4*)(A + base))[tid];
    float4 b = ((const float4*)(Bv + base))[tid];
    float s0 = a.x + b.x, s1 = a.y + b.y, s2 = a.z + b.z, s3 = a.w + b.w;

    float sum = s0 + s1 + s2 + s3;
    float sq = s0 * s0 + s1 * s1 + s2 * s2 + s3 * s3;
    sum = warpReduceSum(sum);
    sq = warpReduceSum(sq);
    if ((tid & 31) == 0) { sh1[tid >> 5] = sum; sh2[tid >> 5] = sq; }
    __syncthreads();
    if (tid < 32) {
        float t1 = (tid < 8) ? sh1[tid] : 0.f;
        float t2 = (tid < 8) ? sh2[tid] : 0.f;
        t1 = warpReduceSum(t1);
        t2 = warpReduceSum(t2);
        if (tid == 0) {
            float mean = t1 * (1.0f / DIM);
            float var = t2 * (1.0f / DIM) - mean * mean;
            stats.x = mean;
            stats.y = rsqrtf(var + 1e-5f);
        }
    }
    __syncthreads();
    const float mean = stats.x, rs = stats.y;

    float4 gg = ((const float4*)gamma)[tid];
    float4 bb = ((const float4*)beta)[tid];
    float4 o;
    o.x = (s0 - mean) * rs * gg.x + bb.x;
    o.y = (s1 - mean) * rs * gg.y + bb.y;
    o.z = (s2 - mean) * rs * gg.z + bb.z;
    o.w = (s3 - mean) * rs * gg.w + bb.w;
    ((float4*)(O + base))[tid] = o;
}

// ---------------------------------------------------------------------------
// Launch
// ---------------------------------------------------------------------------
extern "C" void kernel_launch(void* const* d_in, const int* in_sizes, int n_in,
                              void* d_out, int out_size)
{
    (void)in_sizes; (void)n_in; (void)out_size;
    const float* x   = (const float*)d_in[0];
    const float* Wq  = (const float*)d_in[1];
    const float* bq  = (const float*)d_in[2];
    const float* Wk  = (const float*)d_in[3];
    const float* bk  = (const float*)d_in[4];
    const float* Wv  = (const float*)d_in[5];
    const float* bv  = (const float*)d_in[6];
    const float* W1  = (const float*)d_in[7];
    const float* b1  = (const float*)d_in[8];
    const float* g1  = (const float*)d_in[9];
    const float* be1 = (const float*)d_in[10];
    const float* W2  = (const float*)d_in[11];
    const float* b2  = (const float*)d_in[12];
    const float* g2  = (const float*)d_in[13];
    const float* be2 = (const float*)d_in[14];
    float* out = (float*)d_out;

    float* base;
    cudaGetSymbolAddress((void**)&base, g_scratch);
    float* q  = base + OFF_Q;
    float* k  = base + OFF_K;
    float* v  = base + OFF_V;
    float* sc = base + OFF_SC;
    // Aliases (see layout comment): q dead after QK^T, k dead after QK^T.
    float* hd = base + OFF_Q;                         // heads  [h][t][d]
    float* pj = base + OFF_K;                         // proj   [t][d]
    float* y  = base + OFF_K + (size_t)TOK * DIM;     // y      [t][d]
    float* z2 = base + OFF_K + (size_t)2 * TOK * DIM; // z2     [t][d]

    const long long HEAD_QKV = (long long)TOK * DIM;   // per-head q/k/v stride
    const long long BLK_ATT  = (long long)SEQ * DIM;   // per-z attention block
    const long long BLK_SC   = (long long)SEQ * SEQ;   // per-z score block
    dim3 blk(256);

    // QKV projections: z = head, C[h] = x @ Wq[h] + bq[h]
    gemm_tf32<0, false><<<dim3(8, 64, 4), blk>>>(x, 0, Wq, (long long)DIM * DIM, bq, DIM,
                                                 q, HEAD_QKV, DIM, DIM, DIM, DIM, 1.0f);
    gemm_tf32<0, false><<<dim3(8, 64, 4), blk>>>(x, 0, Wk, (long long)DIM * DIM, bk, DIM,
                                                 k, HEAD_QKV, DIM, DIM, DIM, DIM, 1.0f);
    gemm_tf32<0, false><<<dim3(8, 64, 4), blk>>>(x, 0, Wv, (long long)DIM * DIM, bv, DIM,
                                                 v, HEAD_QKV, DIM, DIM, DIM, DIM, 1.0f);

    // scores[z] = (q[z] @ k[z]^T) * (1/sqrt(D)) ; z = h*4+b
    gemm_tf32<1, false><<<dim3(16, 16, 16), blk>>>(q, BLK_ATT, k, BLK_ATT, nullptr, 0,
                                                   sc, BLK_SC, DIM, DIM, DIM, SEQ, 0.03125f);

    // row softmax (in place)
    softmax_kernel<<<NHEAD * NBATCH * SEQ, blk>>>(sc);

    // heads[z] = attn[z] @ v[z]   (writes into the q buffer — q is dead)
    gemm_tf32<0, false><<<dim3(8, 16, 16), blk>>>(sc, BLK_SC, v, BLK_ATT, nullptr, 0,
                                                  hd, BLK_ATT, SEQ, SEQ, DIM, DIM, 1.0f);

    // proj = concat(heads) @ W1 + b1   (gather fuses the [B,S,H*D] concat)
    gemm_tf32<0, true><<<dim3(8, 64, 1), blk>>>(hd, 0, W1, 0, b1, 0,
                                                pj, 0, NHEAD * DIM, 0, DIM, DIM, 1.0f);

    // y = LN(x + proj)
    add_ln_kernel<<<TOK, blk>>>(x, pj, g1, be1, y);

    // z2 = y @ W2 + b2
    gemm_tf32<0, false><<<dim3(8, 64, 1), blk>>>(y, 0, W2, 0, b2, 0,
                                                 z2, 0, DIM, DIM, DIM, DIM, 1.0f);

    // out = LN(y + z2)
    add_ln_kernel<<<TOK, blk>>>(y, z2, g2, be2, out);
}

// round 4
// speedup vs baseline: 1.3380x; 1.3380x over previous
#include <cuda_runtime.h>
#include <cstdint>
#include <cstddef>

// Problem shape (fixed): B=4, S=2048, D=1024, H=4
#define TOK    8192
#define DIM    1024
#define NHEAD  4
#define SEQ    2048
#define NBATCH 4

// ---------------------------------------------------------------------------
// Scratch: ONE device-global symbol, 640 MB, with buffer aliasing.
//   [OFF_Q )  q      [h][t][d]   -> reused as heads after QK^T
//   [OFF_K )  k      [h][t][d]   -> reused as proj/y/z2 after QK^T
//   [OFF_V )  v      [h][t][d]
//   [OFF_SC)  scores [z=h*4+b][s][t]
// ---------------------------------------------------------------------------
#define OFF_Q  ((size_t)0)
#define OFF_K  ((size_t)33554432)
#define OFF_V  ((size_t)67108864)
#define OFF_SC ((size_t)100663296)
#define SCRATCH_FLOATS ((size_t)167772160)
__device__ float g_scratch[SCRATCH_FLOATS];

// ---------------------------------------------------------------------------
// Helpers
// ---------------------------------------------------------------------------
__device__ __forceinline__ uint32_t f2tf(float x) {
    uint32_t y;
    asm("cvt.rna.tf32.f32 %0, %1;" : "=r"(y) : "f"(x));
    return y;
}

__device__ __forceinline__ void mma_tf32(float acc[4], const uint32_t a[4], const uint32_t b[2]) {
    asm volatile(
        "mma.sync.aligned.m16n8k8.row.col.f32.tf32.tf32.f32 "
        "{%0,%1,%2,%3}, {%4,%5,%6,%7}, {%8,%9}, {%0,%1,%2,%3};\n"
        : "+f"(acc[0]), "+f"(acc[1]), "+f"(acc[2]), "+f"(acc[3])
        : "r"(a[0]), "r"(a[1]), "r"(a[2]), "r"(a[3]), "r"(b[0]), "r"(b[1]));
}

__device__ __forceinline__ uint32_t smaddr(const void* p) {
    return (uint32_t)__cvta_generic_to_shared(p);
}

__device__ __forceinline__ void cpasync16(uint32_t dst, const float* src) {
    asm volatile("cp.async.cg.shared.global [%0], [%1], 16;" :: "r"(dst), "l"(src));
}
#define CP_COMMIT() asm volatile("cp.async.commit_group;" ::: "memory")
#define CP_WAIT2()  asm volatile("cp.async.wait_group 2;"  ::: "memory")

__device__ __forceinline__ float warpReduceSum(float v) {
    #pragma unroll
    for (int o = 16; o > 0; o >>= 1) v += __shfl_xor_sync(0xffffffffu, v, o);
    return v;
}
__device__ __forceinline__ float warpReduceMax(float v) {
    #pragma unroll
    for (int o = 16; o > 0; o >>= 1) v = fmaxf(v, __shfl_xor_sync(0xffffffffu, v, o));
    return v;
}

// ---------------------------------------------------------------------------
// TF32 mma.sync GEMM: C[z] = alpha * A[z] @ op(B[z]) + bias[z]
//   A gmem: [M][K] row-major (K contiguous); GATHER = heads-concat over k.
//   BNT=0:  B gmem [K][N] (N contiguous)  -> C = A @ B        (NN)
//   BNT=1:  B gmem [N][K] (K contiguous)  -> C = A @ B^T      (NT)
// CTA tile 128(M) x 256(N), BK=16, 256 threads, 8 warps (2x4), warp 64x64.
// 4-stage cp.async pipeline, direct global->shared, no register staging.
// Padded smem layouts (A [m][20], B-NN [k][264], B-NT [n][20]):
// all fragment LDS patterns are bank-conflict-free.
// ---------------------------------------------------------------------------
#define AS_FLOATS 2560                     // 128 * 20
#define BS_FLOATS_NN 4224                  // 16 * 264
#define BS_FLOATS_NT 5120                  // 256 * 20

template<int BNT, bool GATHER>
__global__ void __launch_bounds__(256)
tc_gemm(const float* __restrict__ A, long long sA,
        const float* __restrict__ B, long long sB,
        const float* __restrict__ bias, long long sBias,
        float* __restrict__ C, long long sC,
        int K, int lda, int ldb, int ldc, float alpha)
{
    constexpr int BS_FLOATS = BNT ? BS_FLOATS_NT : BS_FLOATS_NN;
    constexpr int STAGE_FLOATS = AS_FLOATS + BS_FLOATS;

    extern __shared__ float sm[];

    const int tid = threadIdx.x;
    const int z = blockIdx.z;
    if (!GATHER) A += (size_t)z * sA;
    B += (size_t)z * sB;
    C += (size_t)z * sC;
    const float* bp = bias ? bias + (size_t)z * sBias : nullptr;

    const int m0 = blockIdx.y * 128;
    const int n0 = blockIdx.x * 256;
    const int NKT = K >> 4;

    const int lane = tid & 31, warp = tid >> 5;
    const int wm = warp >> 2;          // 0..1 : 64-row group
    const int wn = warp & 3;           // 0..3 : 64-col group
    const int g = lane >> 2, tg = lane & 3;

    auto load_stage = [&](int kt, int st) {
        float* as = sm + st * STAGE_FLOATS;
        float* bs = as + AS_FLOATS;
        const int kbase = kt * 16;
        #pragma unroll
        for (int i = 0; i < 2; i++) {                // A: 128 x 16
            int id = tid + i * 256;
            int m = id >> 2, c4 = (id & 3) << 2;
            const float* src;
            if (GATHER) {
                int kk = kbase + c4;
                src = A + ((size_t)(kk >> 10)) * ((size_t)TOK * DIM)
                        + (size_t)(m0 + m) * DIM + (kk & (DIM - 1));
            } else {
                src = A + (size_t)(m0 + m) * lda + kbase + c4;
            }
            cpasync16(smaddr(as + m * 20 + c4), src);
        }
        #pragma unroll
        for (int i = 0; i < 4; i++) {                // B: 16 x 256 (or 256 x 16)
            int id = tid + i * 256;
            if (BNT) {
                int n = id >> 2, c4 = (id & 3) << 2;
                cpasync16(smaddr(bs + n * 20 + c4),
                          B + (size_t)(n0 + n) * ldb + kbase + c4);
            } else {
                int kr = id >> 6, nc = (id & 63) << 2;
                cpasync16(smaddr(bs + kr * 264 + nc),
                          B + (size_t)(kbase + kr) * ldb + n0 + nc);
            }
        }
    };

    float acc[4][8][4];
    #pragma unroll
    for (int mt = 0; mt < 4; mt++)
        #pragma unroll
        for (int nt = 0; nt < 8; nt++)
            #pragma unroll
            for (int r = 0; r < 4; r++) acc[mt][nt][r] = 0.f;

    // Prologue: fill 3 stages (NKT >= 64 for all calls here)
    load_stage(0, 0); CP_COMMIT();
    load_stage(1, 1); CP_COMMIT();
    load_stage(2, 2); CP_COMMIT();

    for (int kt = 0; kt < NKT; kt++) {
        CP_WAIT2();                  // stage kt's group complete
        __syncthreads();             // all warps done with stage (kt-1)%4

        const float* as = sm + (kt & 3) * STAGE_FLOATS;
        const float* bs = as + AS_FLOATS;

        #pragma unroll
        for (int ks = 0; ks < 2; ks++) {
            const int kk = ks * 8;
            uint32_t af[4][4], bf[8][2];
            #pragma unroll
            for (int mt = 0; mt < 4; mt++) {
                int r = wm * 64 + mt * 16 + g;
                af[mt][0] = f2tf(as[r * 20 + kk + tg]);
                af[mt][1] = f2tf(as[(r + 8) * 20 + kk + tg]);
                af[mt][2] = f2tf(as[r * 20 + kk + tg + 4]);
                af[mt][3] = f2tf(as[(r + 8) * 20 + kk + tg + 4]);
            }
            #pragma unroll
            for (int nt = 0; nt < 8; nt++) {
                int c = wn * 64 + nt * 8 + g;
                if (BNT) {
                    bf[nt][0] = f2tf(bs[c * 20 + kk + tg]);
                    bf[nt][1] = f2tf(bs[c * 20 + kk + tg + 4]);
                } else {
                    bf[nt][0] = f2tf(bs[(kk + tg) * 264 + c]);
                    bf[nt][1] = f2tf(bs[(kk + tg + 4) * 264 + c]);
                }
            }
            #pragma unroll
            for (int mt = 0; mt < 4; mt++)
                #pragma unroll
                for (int nt = 0; nt < 8; nt++)
                    mma_tf32(acc[mt][nt], af[mt], bf[nt]);
        }

        if (kt + 3 < NKT) load_stage(kt + 3, (kt + 3) & 3);
        CP_COMMIT();                 // one group per iteration (may be empty)
    }

    // Epilogue: alpha + bias, direct gmem stores
    #pragma unroll
    for (int nt = 0; nt < 8; nt++) {
        const int c = n0 + wn * 64 + nt * 8 + tg * 2;
        float b0 = 0.f, b1 = 0.f;
        if (bp) { b0 = bp[c]; b1 = bp[c + 1]; }
        #pragma unroll
        for (int mt = 0; mt < 4; mt++) {
            const int r0 = m0 + wm * 64 + mt * 16 + g;
            float2 v0, v1;
            v0.x = alpha * acc[mt][nt][0] + b0;
            v0.y = alpha * acc[mt][nt][1] + b1;
            v1.x = alpha * acc[mt][nt][2] + b0;
            v1.y = alpha * acc[mt][nt][3] + b1;
            *(float2*)(C + (size_t)r0 * ldc + c) = v0;
            *(float2*)(C + (size_t)(r0 + 8) * ldc + c) = v1;
        }
    }
}

// ---------------------------------------------------------------------------
// Row softmax over 2048 cols, in place. One block (256 thr) per row.
// ---------------------------------------------------------------------------
__global__ void __launch_bounds__(256) softmax_kernel(float* __restrict__ S)
{
    __shared__ float sh[32];
    __shared__ float bval;
    float* row = S + (size_t)blockIdx.x * SEQ;
    const int tid = threadIdx.x;

    float4 v0 = ((float4*)row)[tid];
    float4 v1 = ((float4*)row)[tid + 256];

    float m = fmaxf(fmaxf(fmaxf(v0.x, v0.y), fmaxf(v0.z, v0.w)),
                    fmaxf(fmaxf(v1.x, v1.y), fmaxf(v1.z, v1.w)));
    m = warpReduceMax(m);
    if ((tid & 31) == 0) sh[tid >> 5] = m;
    __syncthreads();
    if (tid < 32) {
        float t = (tid < 8) ? sh[tid] : -3.4e38f;
        t = warpReduceMax(t);
        if (tid == 0) bval = t;
    }
    __syncthreads();
    m = bval;

    v0.x = __expf(v0.x - m); v0.y = __expf(v0.y - m);
    v0.z = __expf(v0.z - m); v0.w = __expf(v0.w - m);
    v1.x = __expf(v1.x - m); v1.y = __expf(v1.y - m);
    v1.z = __expf(v1.z - m); v1.w = __expf(v1.w - m);
    float s = v0.x + v0.y + v0.z + v0.w + v1.x + v1.y + v1.z + v1.w;
    s = warpReduceSum(s);
    if ((tid & 31) == 0) sh[tid >> 5] = s;
    __syncthreads();
    if (tid < 32) {
        float t = (tid < 8) ? sh[tid] : 0.f;
        t = warpReduceSum(t);
        if (tid == 0) bval = 1.0f / t;
    }
    __syncthreads();
    const float inv = bval;

    v0.x *= inv; v0.y *= inv; v0.z *= inv; v0.w *= inv;
    v1.x *= inv; v1.y *= inv; v1.z *= inv; v1.w *= inv;
    ((float4*)row)[tid] = v0;
    ((float4*)row)[tid + 256] = v1;
}

// ---------------------------------------------------------------------------
// out = LayerNorm(a + b) * gamma + beta  (rows of D=1024, biased var, eps=1e-5)
// ---------------------------------------------------------------------------
__global__ void __launch_bounds__(256) add_ln_kernel(
    const float* __restrict__ A, const float* __restrict__ Bv,
    const float* __restrict__ gamma, const float* __restrict__ beta,
    float* __restrict__ O)
{
    __shared__ float sh1[32], sh2[32];
    __shared__ float2 stats;
    const size_t base = (size_t)blockIdx.x * DIM;
    const int tid = threadIdx.x;

    float4 a = ((const float4*)(A + base))[tid];
    float4 b = ((const float4*)(Bv + base))[tid];
    float s0 = a.x + b.x, s1 = a.y + b.y, s2 = a.z + b.z, s3 = a.w + b.w;

    float sum = s0 + s1 + s2 + s3;
    float sq = s0 * s0 + s1 * s1 + s2 * s2 + s3 * s3;
    sum = warpReduceSum(sum);
    sq = warpReduceSum(sq);
    if ((tid & 31) == 0) { sh1[tid >> 5] = sum; sh2[tid >> 5] = sq; }
    __syncthreads();
    if (tid < 32) {
        float t1 = (tid < 8) ? sh1[tid] : 0.f;
        float t2 = (tid < 8) ? sh2[tid] : 0.f;
        t1 = warpReduceSum(t1);
        t2 = warpReduceSum(t2);
        if (tid == 0) {
            float mean = t1 * (1.0f / DIM);
            float var = t2 * (1.0f / DIM) - mean * mean;
            stats.x = mean;
            stats.y = rsqrtf(var + 1e-5f);
        }
    }
    __syncthreads();
    const float mean = stats.x, rs = stats.y;

    float4 gg = ((const float4*)gamma)[tid];
    float4 bb = ((const float4*)beta)[tid];
    float4 o;
    o.x = (s0 - mean) * rs * gg.x + bb.x;
    o.y = (s1 - mean) * rs * gg.y + bb.y;
    o.z = (s2 - mean) * rs * gg.z + bb.z;
    o.w = (s3 - mean) * rs * gg.w + bb.w;
    ((float4*)(O + base))[tid] = o;
}

// ---------------------------------------------------------------------------
// Launch
// ---------------------------------------------------------------------------
#define SMEM_NN ((AS_FLOATS + BS_FLOATS_NN) * 4 * 4)   // 108544 B
#define SMEM_NT ((AS_FLOATS + BS_FLOATS_NT) * 4 * 4)   // 122880 B

extern "C" void kernel_launch(void* const* d_in, const int* in_sizes, int n_in,
                              void* d_out, int out_size)
{
    (void)in_sizes; (void)n_in; (void)out_size;
    const float* x   = (const float*)d_in[0];
    const float* Wq  = (const float*)d_in[1];
    const float* bq  = (const float*)d_in[2];
    const float* Wk  = (const float*)d_in[3];
    const float* bk  = (const float*)d_in[4];
    const float* Wv  = (const float*)d_in[5];
    const float* bv  = (const float*)d_in[6];
    const float* W1  = (const float*)d_in[7];
    const float* b1  = (const float*)d_in[8];
    const float* g1  = (const float*)d_in[9];
    const float* be1 = (const float*)d_in[10];
    const float* W2  = (const float*)d_in[11];
    const float* b2  = (const float*)d_in[12];
    const float* g2  = (const float*)d_in[13];
    const float* be2 = (const float*)d_in[14];
    float* out = (float*)d_out;

    float* base1;
    cudaGetSymbolAddress((void**)&base1, g_scratch);
    float* q  = base1 + OFF_Q;
    float* k  = base1 + OFF_K;
    float* v  = base1 + OFF_V;
    float* sc = base1 + OFF_SC;
    float* hd = base1 + OFF_Q;                         // heads (q dead)
    float* pj = base1 + OFF_K;                         // proj  (k dead)
    float* y  = base1 + OFF_K + (size_t)TOK * DIM;
    float* z2 = base1 + OFF_K + (size_t)2 * TOK * DIM;

    cudaFuncSetAttribute(tc_gemm<0, false>,
        cudaFuncAttributeMaxDynamicSharedMemorySize, SMEM_NN);
    cudaFuncSetAttribute(tc_gemm<0, true>,
        cudaFuncAttributeMaxDynamicSharedMemorySize, SMEM_NN);
    cudaFuncSetAttribute(tc_gemm<1, false>,
        cudaFuncAttributeMaxDynamicSharedMemorySize, SMEM_NT);

    const long long MM = (long long)DIM * DIM;
    const long long HEAD_QKV = (long long)TOK * DIM;   // per-head q/k/v stride
    const long long BLK_ATT  = (long long)SEQ * DIM;   // per-z [s][d] block
    const long long BLK_SC   = (long long)SEQ * SEQ;   // per-z score block
    dim3 blk(256);

    // QKV projections (NN): C[h] = x @ W[h] + b[h]
    tc_gemm<0, false><<<dim3(4, 64, 4), blk, SMEM_NN>>>(
        x, 0, Wq, MM, bq, DIM, q, HEAD_QKV, DIM, DIM, DIM, DIM, 1.0f);
    tc_gemm<0, false><<<dim3(4, 64, 4), blk, SMEM_NN>>>(
        x, 0, Wk, MM, bk, DIM, k, HEAD_QKV, DIM, DIM, DIM, DIM, 1.0f);
    tc_gemm<0, false><<<dim3(4, 64, 4), blk, SMEM_NN>>>(
        x, 0, Wv, MM, bv, DIM, v, HEAD_QKV, DIM, DIM, DIM, DIM, 1.0f);

    // scores[z] = (q[z] @ k[z]^T) / 32   (NT)
    tc_gemm<1, false><<<dim3(8, 16, 16), blk, SMEM_NT>>>(
        q, BLK_ATT, k, BLK_ATT, nullptr, 0, sc, BLK_SC, DIM, DIM, DIM, SEQ, 0.03125f);

    // row softmax (in place)
    softmax_kernel<<<NHEAD * NBATCH * SEQ, blk>>>(sc);

    // heads[z] = attn[z] @ v[z]   (NN; no V transpose needed)
    tc_gemm<0, false><<<dim3(4, 16, 16), blk, SMEM_NN>>>(
        sc, BLK_SC, v, BLK_ATT, nullptr, 0, hd, BLK_ATT, SEQ, SEQ, DIM, DIM, 1.0f);

    // proj = concat(heads) @ W1 + b1  (NN with A-gather over the concat)
    tc_gemm<0, true><<<dim3(4, 64, 1), blk, SMEM_NN>>>(
        hd, 0, W1, 0, b1, 0, pj, 0, NHEAD * DIM, 0, DIM, DIM, 1.0f);

    // y = LN(x + proj)
    add_ln_kernel<<<TOK, blk>>>(x, pj, g1, be1, y);

    // z2 = y @ W2 + b2  (NN)
    tc_gemm<0, false><<<dim3(4, 64, 1), blk, SMEM_NN>>>(
        y, 0, W2, 0, b2, 0, z2, 0, DIM, DIM, DIM, DIM, 1.0f);

    // out = LN(y + z2)
    add_ln_kernel<<<TOK, blk>>>(y, z2, g2, be2, out);
}

// round 7
// speedup vs baseline: 1.5596x; 1.1656x over previous
#include <cuda_runtime.h>
#include <cstdint>
#include <cstddef>

// Problem shape (fixed): B=4, S=2048, D=1024, H=4
#define TOK    8192
#define DIM    1024
#define NHEAD  4
#define SEQ    2048
#define NBATCH 4

// ---------------------------------------------------------------------------
// Scratch: ONE device-global symbol, 640 MB (identical shape to the config
// that loaded successfully twice). Aliasing by liveness:
//   [OFF_Q )  q      [h][t][d]   -> reused as heads after QK^T
//   [OFF_K )  k      [h][t][d]   -> reused as proj/y/z2 after QK^T
//   [OFF_V )  v      [h][t][d]
//   [OFF_SC)  scores [z=h*4+b][s][t], 67108864 floats. Also hosts:
//       phase 1 (start -> QKV done, before QK^T writes sc):
//           xr  @ OFF_SC+0         (8388608)
//           wqr @ OFF_SC+8388608   (4194304)
//           wkr @ OFF_SC+12582912  (4194304)
//           wvr @ OFF_SC+16777216  (4194304)
//       phase 3 (after PV GEMM, sc dead):
//           w1r @ OFF_SC+0         (4194304)
//           w2r @ OFF_SC+4194304   (1048576)
// All launches are on one stream; ordering makes every alias hazard-free.
// ---------------------------------------------------------------------------
#define OFF_Q  ((size_t)0)
#define OFF_K  ((size_t)33554432)
#define OFF_V  ((size_t)67108864)
#define OFF_SC ((size_t)100663296)
#define SCRATCH_FLOATS ((size_t)167772160)
__device__ float g_scratch[SCRATCH_FLOATS];

// ---------------------------------------------------------------------------
// Helpers
// ---------------------------------------------------------------------------
__device__ __forceinline__ uint32_t f2tf(float x) {
    uint32_t y;
    asm("cvt.rna.tf32.f32 %0, %1;" : "=r"(y) : "f"(x));
    return y;
}
__device__ __forceinline__ float roundtf(float x) {
    return __uint_as_float(f2tf(x));
}

__device__ __forceinline__ void mma_tf32(float acc[4], const uint32_t a[4], const uint32_t b[2]) {
    asm volatile(
        "mma.sync.aligned.m16n8k8.row.col.f32.tf32.tf32.f32 "
        "{%0,%1,%2,%3}, {%4,%5,%6,%7}, {%8,%9}, {%0,%1,%2,%3};\n"
        : "+f"(acc[0]), "+f"(acc[1]), "+f"(acc[2]), "+f"(acc[3])
        : "r"(a[0]), "r"(a[1]), "r"(a[2]), "r"(a[3]), "r"(b[0]), "r"(b[1]));
}

__device__ __forceinline__ uint32_t smaddr(const void* p) {
    return (uint32_t)__cvta_generic_to_shared(p);
}

__device__ __forceinline__ void cpasync16(uint32_t dst, const float* src) {
    asm volatile("cp.async.cg.shared.global [%0], [%1], 16;" :: "r"(dst), "l"(src));
}
#define CP_COMMIT() asm volatile("cp.async.commit_group;" ::: "memory")
#define CP_WAIT2()  asm volatile("cp.async.wait_group 2;"  ::: "memory")

__device__ __forceinline__ float warpReduceSum(float v) {
    #pragma unroll
    for (int o = 16; o > 0; o >>= 1) v += __shfl_xor_sync(0xffffffffu, v, o);
    return v;
}
__device__ __forceinline__ float warpReduceMax(float v) {
    #pragma unroll
    for (int o = 16; o > 0; o >>= 1) v = fmaxf(v, __shfl_xor_sync(0xffffffffu, v, o));
    return v;
}

// ---------------------------------------------------------------------------
// Elementwise tf32 rounding: out[i] = round_tf32(in[i]).  n4 = count/4.
// ---------------------------------------------------------------------------
__global__ void __launch_bounds__(256) round_kernel(
    const float* __restrict__ in, float* __restrict__ out, int n4)
{
    int i = blockIdx.x * blockDim.x + threadIdx.x;
    if (i < n4) {
        float4 v = ((const float4*)in)[i];
        v.x = roundtf(v.x); v.y = roundtf(v.y);
        v.z = roundtf(v.z); v.w = roundtf(v.w);
        ((float4*)out)[i] = v;
    }
}

// ---------------------------------------------------------------------------
// TF32 mma.sync GEMM: C[z] = alpha * A[z] @ op(B[z]) + bias[z]
// All operands in memory are ALREADY tf32-rounded -> no cvt in mainloop.
//   A gmem: [M][K] row-major (K contiguous); GATHER = heads-concat over k.
//   BNT=0:  B gmem [K][N] (N contiguous)  -> C = A @ B        (NN)
//   BNT=1:  B gmem [N][K] (K contiguous)  -> C = A @ B^T      (NT)
// EPI_ROUND: round output to tf32 (for operands of downstream GEMMs).
// CTA tile 128(M) x 256(N), BK=16, 256 threads, 8 warps (2x4), warp 64x64.
// 4-stage cp.async pipeline. Padded smem: A [m][20], B-NN [k][264], B-NT [n][20].
// ---------------------------------------------------------------------------
#define AS_FLOATS 2560                     // 128 * 20
#define BS_FLOATS_NN 4224                  // 16 * 264
#define BS_FLOATS_NT 5120                  // 256 * 20

template<int BNT, bool GATHER, bool EPI_ROUND>
__global__ void __launch_bounds__(256)
tc_gemm(const float* __restrict__ A, long long sA,
        const float* __restrict__ B, long long sB,
        const float* __restrict__ bias, long long sBias,
        float* __restrict__ C, long long sC,
        int K, int lda, int ldb, int ldc, float alpha)
{
    constexpr int BS_FLOATS = BNT ? BS_FLOATS_NT : BS_FLOATS_NN;
    constexpr int STAGE_FLOATS = AS_FLOATS + BS_FLOATS;

    extern __shared__ float sm[];

    const int tid = threadIdx.x;
    const int z = blockIdx.z;
    if (!GATHER) A += (size_t)z * sA;
    B += (size_t)z * sB;
    C += (size_t)z * sC;
    const float* bp = bias ? bias + (size_t)z * sBias : nullptr;

    const int m0 = blockIdx.y * 128;
    const int n0 = blockIdx.x * 256;
    const int NKT = K >> 4;

    const int lane = tid & 31, warp = tid >> 5;
    const int wm = warp >> 2;          // 0..1 : 64-row group
    const int wn = warp & 3;           // 0..3 : 64-col group
    const int g = lane >> 2, tg = lane & 3;

    auto load_stage = [&](int kt, int st) {
        float* as = sm + st * STAGE_FLOATS;
        float* bs = as + AS_FLOATS;
        const int kbase = kt * 16;
        #pragma unroll
        for (int i = 0; i < 2; i++) {                // A: 128 x 16
            int id = tid + i * 256;
            int m = id >> 2, c4 = (id & 3) << 2;
            const float* src;
            if (GATHER) {
                int kk = kbase + c4;
                src = A + ((size_t)(kk >> 10)) * ((size_t)TOK * DIM)
                        + (size_t)(m0 + m) * DIM + (kk & (DIM - 1));
            } else {
                src = A + (size_t)(m0 + m) * lda + kbase + c4;
            }
            cpasync16(smaddr(as + m * 20 + c4), src);
        }
        #pragma unroll
        for (int i = 0; i < 4; i++) {                // B: 16 x 256 (or 256 x 16)
            int id = tid + i * 256;
            if (BNT) {
                int n = id >> 2, c4 = (id & 3) << 2;
                cpasync16(smaddr(bs + n * 20 + c4),
                          B + (size_t)(n0 + n) * ldb + kbase + c4);
            } else {
                int kr = id >> 6, nc = (id & 63) << 2;
                cpasync16(smaddr(bs + kr * 264 + nc),
                          B + (size_t)(kbase + kr) * ldb + n0 + nc);
            }
        }
    };

    float acc[4][8][4];
    #pragma unroll
    for (int mt = 0; mt < 4; mt++)
        #pragma unroll
        for (int nt = 0; nt < 8; nt++)
            #pragma unroll
            for (int r = 0; r < 4; r++) acc[mt][nt][r] = 0.f;

    // Prologue: fill 3 stages (NKT >= 64 for all calls here)
    load_stage(0, 0); CP_COMMIT();
    load_stage(1, 1); CP_COMMIT();
    load_stage(2, 2); CP_COMMIT();

    for (int kt = 0; kt < NKT; kt++) {
        CP_WAIT2();                  // stage kt's group complete
        __syncthreads();             // all warps done with stage (kt-1)%4

        const uint32_t* as = reinterpret_cast<const uint32_t*>(sm + (kt & 3) * STAGE_FLOATS);
        const uint32_t* bs = as + AS_FLOATS;

        #pragma unroll
        for (int ks = 0; ks < 2; ks++) {
            const int kk = ks * 8;
            uint32_t af[4][4], bf[8][2];
            #pragma unroll
            for (int mt = 0; mt < 4; mt++) {
                int r = wm * 64 + mt * 16 + g;
                af[mt][0] = as[r * 20 + kk + tg];
                af[mt][1] = as[(r + 8) * 20 + kk + tg];
                af[mt][2] = as[r * 20 + kk + tg + 4];
                af[mt][3] = as[(r + 8) * 20 + kk + tg + 4];
            }
            #pragma unroll
            for (int nt = 0; nt < 8; nt++) {
                int c = wn * 64 + nt * 8 + g;
                if (BNT) {
                    bf[nt][0] = bs[c * 20 + kk + tg];
                    bf[nt][1] = bs[c * 20 + kk + tg + 4];
                } else {
                    bf[nt][0] = bs[(kk + tg) * 264 + c];
                    bf[nt][1] = bs[(kk + tg + 4) * 264 + c];
                }
            }
            #pragma unroll
            for (int mt = 0; mt < 4; mt++)
                #pragma unroll
                for (int nt = 0; nt < 8; nt++)
                    mma_tf32(acc[mt][nt], af[mt], bf[nt]);
        }

        if (kt + 3 < NKT) load_stage(kt + 3, (kt + 3) & 3);
        CP_COMMIT();                 // one group per iteration (may be empty)
    }

    // Epilogue: alpha + bias (+ optional tf32 rounding), direct gmem stores
    #pragma unroll
    for (int nt = 0; nt < 8; nt++) {
        const int c = n0 + wn * 64 + nt * 8 + tg * 2;
        float b0 = 0.f, b1 = 0.f;
        if (bp) { b0 = bp[c]; b1 = bp[c + 1]; }
        #pragma unroll
        for (int mt = 0; mt < 4; mt++) {
            const int r0 = m0 + wm * 64 + mt * 16 + g;
            float2 v0, v1;
            v0.x = alpha * acc[mt][nt][0] + b0;
            v0.y = alpha * acc[mt][nt][1] + b1;
            v1.x = alpha * acc[mt][nt][2] + b0;
            v1.y = alpha * acc[mt][nt][3] + b1;
            if (EPI_ROUND) {
                v0.x = roundtf(v0.x); v0.y = roundtf(v0.y);
                v1.x = roundtf(v1.x); v1.y = roundtf(v1.y);
            }
            *(float2*)(C + (size_t)r0 * ldc + c) = v0;
            *(float2*)(C + (size_t)(r0 + 8) * ldc + c) = v1;
        }
    }
}

// ---------------------------------------------------------------------------
// Row softmax over 2048 cols, in place; output tf32-rounded (feeds PV GEMM).
// ---------------------------------------------------------------------------
__global__ void __launch_bounds__(256) softmax_kernel(float* __restrict__ S)
{
    __shared__ float sh[32];
    __shared__ float bval;
    float* row = S + (size_t)blockIdx.x * SEQ;
    const int tid = threadIdx.x;

    float4 v0 = ((float4*)row)[tid];
    float4 v1 = ((float4*)row)[tid + 256];

    float m = fmaxf(fmaxf(fmaxf(v0.x, v0.y), fmaxf(v0.z, v0.w)),
                    fmaxf(fmaxf(v1.x, v1.y), fmaxf(v1.z, v1.w)));
    m = warpReduceMax(m);
    if ((tid & 31) == 0) sh[tid >> 5] = m;
    __syncthreads();
    if (tid < 32) {
        float t = (tid < 8) ? sh[tid] : -3.4e38f;
        t = warpReduceMax(t);
        if (tid == 0) bval = t;
    }
    __syncthreads();
    m = bval;

    v0.x = __expf(v0.x - m); v0.y = __expf(v0.y - m);
    v0.z = __expf(v0.z - m); v0.w = __expf(v0.w - m);
    v1.x = __expf(v1.x - m); v1.y = __expf(v1.y - m);
    v1.z = __expf(v1.z - m); v1.w = __expf(v1.w - m);
    float s = v0.x + v0.y + v0.z + v0.w + v1.x + v1.y + v1.z + v1.w;
    s = warpReduceSum(s);
    if ((tid & 31) == 0) sh[tid >> 5] = s;
    __syncthreads();
    if (tid < 32) {
        float t = (tid < 8) ? sh[tid] : 0.f;
        t = warpReduceSum(t);
        if (tid == 0) bval = 1.0f / t;
    }
    __syncthreads();
    const float inv = bval;

    v0.x = roundtf(v0.x * inv); v0.y = roundtf(v0.y * inv);
    v0.z = roundtf(v0.z * inv); v0.w = roundtf(v0.w * inv);
    v1.x = roundtf(v1.x * inv); v1.y = roundtf(v1.y * inv);
    v1.z = roundtf(v1.z * inv); v1.w = roundtf(v1.w * inv);
    ((float4*)row)[tid] = v0;
    ((float4*)row)[tid + 256] = v1;
}

// ---------------------------------------------------------------------------
// out = LayerNorm(a + b) * gamma + beta  (rows of D=1024, biased var, eps=1e-5)
// ROUND: tf32-round the stored output (when it feeds a GEMM as operand).
// ---------------------------------------------------------------------------
template<bool ROUND>
__global__ void __launch_bounds__(256) add_ln_kernel(
    const float* __restrict__ A, const float* __restrict__ Bv,
    const float* __restrict__ gamma, const float* __restrict__ beta,
    float* __restrict__ O)
{
    __shared__ float sh1[32], sh2[32];
    __shared__ float2 stats;
    const size_t base = (size_t)blockIdx.x * DIM;
    const int tid = threadIdx.x;

    float4 a = ((const float4*)(A + base))[tid];
    float4 b = ((const float4*)(Bv + base))[tid];
    float s0 = a.x + b.x, s1 = a.y + b.y, s2 = a.z + b.z, s3 = a.w + b.w;

    float sum = s0 + s1 + s2 + s3;
    float sq = s0 * s0 + s1 * s1 + s2 * s2 + s3 * s3;
    sum = warpReduceSum(sum);
    sq = warpReduceSum(sq);
    if ((tid & 31) == 0) { sh1[tid >> 5] = sum; sh2[tid >> 5] = sq; }
    __syncthreads();
    if (tid < 32) {
        float t1 = (tid < 8) ? sh1[tid] : 0.f;
        float t2 = (tid < 8) ? sh2[tid] : 0.f;
        t1 = warpReduceSum(t1);
        t2 = warpReduceSum(t2);
        if (tid == 0) {
            float mean = t1 * (1.0f / DIM);
            float var = t2 * (1.0f / DIM) - mean * mean;
            stats.x = mean;
            stats.y = rsqrtf(var + 1e-5f);
        }
    }
    __syncthreads();
    const float mean = stats.x, rs = stats.y;

    float4 gg = ((const float4*)gamma)[tid];
    float4 bb = ((const float4*)beta)[tid];
    float4 o;
    o.x = (s0 - mean) * rs * gg.x + bb.x;
    o.y = (s1 - mean) * rs * gg.y + bb.y;
    o.z = (s2 - mean) * rs * gg.z + bb.z;
    o.w = (s3 - mean) * rs * gg.w + bb.w;
    if (ROUND) {
        o.x = roundtf(o.x); o.y = roundtf(o.y);
        o.z = roundtf(o.z); o.w = roundtf(o.w);
    }
    ((float4*)(O + base))[tid] = o;
}

// ---------------------------------------------------------------------------
// Launch
// ---------------------------------------------------------------------------
#define SMEM_NN ((AS_FLOATS + BS_FLOATS_NN) * 4 * 4)   // 108544 B
#define SMEM_NT ((AS_FLOATS + BS_FLOATS_NT) * 4 * 4)   // 122880 B

extern "C" void kernel_launch(void* const* d_in, const int* in_sizes, int n_in,
                              void* d_out, int out_size)
{
    (void)in_sizes; (void)n_in; (void)out_size;
    const float* x   = (const float*)d_in[0];
    const float* Wq  = (const float*)d_in[1];
    const float* bq  = (const float*)d_in[2];
    const float* Wk  = (const float*)d_in[3];
    const float* bk  = (const float*)d_in[4];
    const float* Wv  = (const float*)d_in[5];
    const float* bv  = (const float*)d_in[6];
    const float* W1  = (const float*)d_in[7];
    const float* b1  = (const float*)d_in[8];
    const float* g1  = (const float*)d_in[9];
    const float* be1 = (const float*)d_in[10];
    const float* W2  = (const float*)d_in[11];
    const float* b2  = (const float*)d_in[12];
    const float* g2  = (const float*)d_in[13];
    const float* be2 = (const float*)d_in[14];
    float* out = (float*)d_out;

    float* base1;
    cudaGetSymbolAddress((void**)&base1, g_scratch);

    float* q  = base1 + OFF_Q;
    float* k  = base1 + OFF_K;
    float* v  = base1 + OFF_V;
    float* sc = base1 + OFF_SC;
    float* hd = base1 + OFF_Q;                         // heads (q dead)
    float* pj = base1 + OFF_K;                         // proj  (k dead)
    float* y  = base1 + OFF_K + (size_t)TOK * DIM;
    float* z2 = base1 + OFF_K + (size_t)2 * TOK * DIM;

    // Phase-1 aliases in the (not-yet-written) scores region:
    float* xr  = base1 + OFF_SC;                       // 8388608
    float* wqr = base1 + OFF_SC + (size_t)8388608;
    float* wkr = base1 + OFF_SC + (size_t)12582912;
    float* wvr = base1 + OFF_SC + (size_t)16777216;
    // Phase-3 aliases (scores dead after PV GEMM):
    float* w1r = base1 + OFF_SC;                       // 4194304
    float* w2r = base1 + OFF_SC + (size_t)4194304;     // 1048576

    cudaFuncSetAttribute(tc_gemm<0, false, true>,
        cudaFuncAttributeMaxDynamicSharedMemorySize, SMEM_NN);
    cudaFuncSetAttribute(tc_gemm<0, false, false>,
        cudaFuncAttributeMaxDynamicSharedMemorySize, SMEM_NN);
    cudaFuncSetAttribute(tc_gemm<0, true, false>,
        cudaFuncAttributeMaxDynamicSharedMemorySize, SMEM_NN);
    cudaFuncSetAttribute(tc_gemm<1, false, false>,
        cudaFuncAttributeMaxDynamicSharedMemorySize, SMEM_NT);

    const long long MM = (long long)DIM * DIM;
    const long long HEAD_QKV = (long long)TOK * DIM;   // per-head q/k/v stride
    const long long BLK_ATT  = (long long)SEQ * DIM;   // per-z [s][d] block
    const long long BLK_SC   = (long long)SEQ * SEQ;   // per-z score block
    dim3 blk(256);

    // ---- Phase 1: tf32 pre-rounding of x, Wq, Wk, Wv (into scores region) ----
    round_kernel<<<8192, 256>>>(x,  xr,  (int)(8388608 / 4));
    round_kernel<<<4096, 256>>>(Wq, wqr, (int)(4194304 / 4));
    round_kernel<<<4096, 256>>>(Wk, wkr, (int)(4194304 / 4));
    round_kernel<<<4096, 256>>>(Wv, wvr, (int)(4194304 / 4));

    // ---- QKV projections (NN, rounded epilogue) ----
    tc_gemm<0, false, true><<<dim3(4, 64, 4), blk, SMEM_NN>>>(
        xr, 0, wqr, MM, bq, DIM, q, HEAD_QKV, DIM, DIM, DIM, DIM, 1.0f);
    tc_gemm<0, false, true><<<dim3(4, 64, 4), blk, SMEM_NN>>>(
        xr, 0, wkr, MM, bk, DIM, k, HEAD_QKV, DIM, DIM, DIM, DIM, 1.0f);
    tc_gemm<0, false, true><<<dim3(4, 64, 4), blk, SMEM_NN>>>(
        xr, 0, wvr, MM, bv, DIM, v, HEAD_QKV, DIM, DIM, DIM, DIM, 1.0f);

    // ---- scores[z] = (q[z] @ k[z]^T) / 32  (NT; overwrites xr/w*r - dead) ----
    tc_gemm<1, false, false><<<dim3(8, 16, 16), blk, SMEM_NT>>>(
        q, BLK_ATT, k, BLK_ATT, nullptr, 0, sc, BLK_SC, DIM, DIM, DIM, SEQ, 0.03125f);

    // ---- row softmax (in place, tf32-rounded output) ----
    softmax_kernel<<<NHEAD * NBATCH * SEQ, blk>>>(sc);

    // ---- heads[z] = attn[z] @ v[z]  (NN, rounded epilogue -> feeds gather) ----
    tc_gemm<0, false, true><<<dim3(4, 16, 16), blk, SMEM_NN>>>(
        sc, BLK_SC, v, BLK_ATT, nullptr, 0, hd, BLK_ATT, SEQ, SEQ, DIM, DIM, 1.0f);

    // ---- Phase 3: round W1, W2 into the now-dead scores region ----
    round_kernel<<<4096, 256>>>(W1, w1r, (int)(4194304 / 4));
    round_kernel<<<1024, 256>>>(W2, w2r, (int)(1048576 / 4));

    // ---- proj = concat(heads) @ W1 + b1  (NN gather; feeds LN, no rounding) ----
    tc_gemm<0, true, false><<<dim3(4, 64, 1), blk, SMEM_NN>>>(
        hd, 0, w1r, 0, b1, 0, pj, 0, NHEAD * DIM, 0, DIM, DIM, 1.0f);

    // ---- y = LN(x + proj), tf32-rounded (feeds W2 GEMM) ----
    add_ln_kernel<true><<<TOK, blk>>>(x, pj, g1, be1, y);

    // ---- z2 = y @ W2 + b2  (NN; feeds final LN, no rounding) ----
    tc_gemm<0, false, false><<<dim3(4, 64, 1), blk, SMEM_NN>>>(
        y, 0, w2r, 0, b2, 0, z2, 0, DIM, DIM, DIM, DIM, 1.0f);

    // ---- out = LN(y + z2) ----
    add_ln_kernel<false><<<TOK, blk>>>(y, z2, g2, be2, out);
}

// round 9
// speedup vs baseline: 1.5965x; 1.0236x over previous
#include <cuda_runtime.h>
#include <cstdint>
#include <cstddef>

// Problem shape (fixed): B=4, S=2048, D=1024, H=4
#define TOK    8192
#define DIM    1024
#define NHEAD  4
#define SEQ    2048
#define NBATCH 4

// ---------------------------------------------------------------------------
// Scratch: ONE device-global symbol, 640 MB. Aliasing by liveness:
//   [OFF_Q )  q      [h][t][d]   -> reused as heads after QK^T
//   [OFF_K )  k      [h][t][d]   -> reused as proj/y/z2 after QK^T
//   [OFF_V )  v      [h][t][d]
//   [OFF_SC)  scores [z=h*4+b][s][t]; also hosts (phase 1) xr/wqr/wkr/wvr
//             and (phase 3, sc dead) w1r/w2r.
// All launches on one stream; ordering makes every alias hazard-free.
// ---------------------------------------------------------------------------
#define OFF_Q  ((size_t)0)
#define OFF_K  ((size_t)33554432)
#define OFF_V  ((size_t)67108864)
#define OFF_SC ((size_t)100663296)
#define SCRATCH_FLOATS ((size_t)167772160)
__device__ float g_scratch[SCRATCH_FLOATS];

// ---------------------------------------------------------------------------
// Helpers
// ---------------------------------------------------------------------------
__device__ __forceinline__ uint32_t f2tf(float x) {
    uint32_t y;
    asm("cvt.rna.tf32.f32 %0, %1;" : "=r"(y) : "f"(x));
    return y;
}
__device__ __forceinline__ float roundtf(float x) {
    return __uint_as_float(f2tf(x));
}

__device__ __forceinline__ void mma_tf32(float acc[4], const uint32_t a[4], const uint32_t b[2]) {
    asm volatile(
        "mma.sync.aligned.m16n8k8.row.col.f32.tf32.tf32.f32 "
        "{%0,%1,%2,%3}, {%4,%5,%6,%7}, {%8,%9}, {%0,%1,%2,%3};\n"
        : "+f"(acc[0]), "+f"(acc[1]), "+f"(acc[2]), "+f"(acc[3])
        : "r"(a[0]), "r"(a[1]), "r"(a[2]), "r"(a[3]), "r"(b[0]), "r"(b[1]));
}

__device__ __forceinline__ uint32_t smaddr(const void* p) {
    return (uint32_t)__cvta_generic_to_shared(p);
}

__device__ __forceinline__ void cpasync16(uint32_t dst, const float* src) {
    asm volatile("cp.async.cg.shared.global [%0], [%1], 16;" :: "r"(dst), "l"(src));
}
#define CP_COMMIT() asm volatile("cp.async.commit_group;" ::: "memory")
#define CP_WAIT2()  asm volatile("cp.async.wait_group 2;"  ::: "memory")

__device__ __forceinline__ float warpReduceSum(float v) {
    #pragma unroll
    for (int o = 16; o > 0; o >>= 1) v += __shfl_xor_sync(0xffffffffu, v, o);
    return v;
}
__device__ __forceinline__ float warpReduceMax(float v) {
    #pragma unroll
    for (int o = 16; o > 0; o >>= 1) v = fmaxf(v, __shfl_xor_sync(0xffffffffu, v, o));
    return v;
}

// ---------------------------------------------------------------------------
// Elementwise tf32 rounding: out[i] = round_tf32(in[i]).  n4 = count/4.
// ---------------------------------------------------------------------------
__global__ void __launch_bounds__(256) round_kernel(
    const float* __restrict__ in, float* __restrict__ out, int n4)
{
    int i = blockIdx.x * blockDim.x + threadIdx.x;
    if (i < n4) {
        float4 v = ((const float4*)in)[i];
        v.x = roundtf(v.x); v.y = roundtf(v.y);
        v.z = roundtf(v.z); v.w = roundtf(v.w);
        ((float4*)out)[i] = v;
    }
}

// ---------------------------------------------------------------------------
// TF32 mma.sync GEMM: C[z] = alpha * A[z] @ op(B[z]) + bias[z]
// All operands in memory are ALREADY tf32-rounded -> no cvt in mainloop.
//   A gmem: [M][K] row-major (K contiguous); GATHER = heads-concat over k.
//   BNT=0:  B gmem [K][N] (N contiguous)  -> C = A @ B        (NN)
//   BNT=1:  B gmem [N][K] (K contiguous)  -> C = A @ B^T      (NT)
// EPI_ROUND: round output to tf32 (for operands of downstream GEMMs).
// CTA tile 128(M) x 128(N), BK=16, 256 threads, 8 warps (4x2), warp 32x64.
// __launch_bounds__(256,2) -> 2 CTAs/SM (16 warps) for latency hiding.
// 4-stage cp.async pipeline. Padded smem: A [m][20], B-NN [k][136], B-NT [n][20].
// All fragment/staging patterns verified bank-conflict-free.
// ---------------------------------------------------------------------------
#define AS_FLOATS 2560                     // 128 * 20
#define BS_FLOATS_NN 2176                  // 16 * 136
#define BS_FLOATS_NT 2560                  // 128 * 20

template<int BNT, bool GATHER, bool EPI_ROUND>
__global__ void __launch_bounds__(256, 2)
tc_gemm(const float* __restrict__ A, long long sA,
        const float* __restrict__ B, long long sB,
        const float* __restrict__ bias, long long sBias,
        float* __restrict__ C, long long sC,
        int K, int lda, int ldb, int ldc, float alpha)
{
    constexpr int BS_FLOATS = BNT ? BS_FLOATS_NT : BS_FLOATS_NN;
    constexpr int STAGE_FLOATS = AS_FLOATS + BS_FLOATS;

    extern __shared__ float sm[];

    const int tid = threadIdx.x;
    const int z = blockIdx.z;
    if (!GATHER) A += (size_t)z * sA;
    B += (size_t)z * sB;
    C += (size_t)z * sC;
    const float* bp = bias ? bias + (size_t)z * sBias : nullptr;

    const int m0 = blockIdx.y * 128;
    const int n0 = blockIdx.x * 128;
    const int NKT = K >> 4;

    const int lane = tid & 31, warp = tid >> 5;
    const int wm = warp >> 1;          // 0..3 : 32-row group
    const int wn = warp & 1;           // 0..1 : 64-col group
    const int g = lane >> 2, tg = lane & 3;

    auto load_stage = [&](int kt, int st) {
        float* as = sm + st * STAGE_FLOATS;
        float* bs = as + AS_FLOATS;
        const int kbase = kt * 16;
        #pragma unroll
        for (int i = 0; i < 2; i++) {                // A: 128 x 16
            int id = tid + i * 256;
            int m = id >> 2, c4 = (id & 3) << 2;
            const float* src;
            if (GATHER) {
                int kk = kbase + c4;
                src = A + ((size_t)(kk >> 10)) * ((size_t)TOK * DIM)
                        + (size_t)(m0 + m) * DIM + (kk & (DIM - 1));
            } else {
                src = A + (size_t)(m0 + m) * lda + kbase + c4;
            }
            cpasync16(smaddr(as + m * 20 + c4), src);
        }
        #pragma unroll
        for (int i = 0; i < 2; i++) {                // B: 16 x 128 (or 128 x 16)
            int id = tid + i * 256;
            if (BNT) {
                int n = id >> 2, c4 = (id & 3) << 2;
                cpasync16(smaddr(bs + n * 20 + c4),
                          B + (size_t)(n0 + n) * ldb + kbase + c4);
            } else {
                int kr = id >> 5, nc = (id & 31) << 2;
                cpasync16(smaddr(bs + kr * 136 + nc),
                          B + (size_t)(kbase + kr) * ldb + n0 + nc);
            }
        }
    };

    float acc[2][8][4];
    #pragma unroll
    for (int mt = 0; mt < 2; mt++)
        #pragma unroll
        for (int nt = 0; nt < 8; nt++)
            #pragma unroll
            for (int r = 0; r < 4; r++) acc[mt][nt][r] = 0.f;

    // Prologue: fill 3 stages (NKT >= 64 for all calls here)
    load_stage(0, 0); CP_COMMIT();
    load_stage(1, 1); CP_COMMIT();
    load_stage(2, 2); CP_COMMIT();

    for (int kt = 0; kt < NKT; kt++) {
        CP_WAIT2();                  // stage kt's group complete
        __syncthreads();             // all warps done with stage (kt-1)%4

        const uint32_t* as = reinterpret_cast<const uint32_t*>(sm + (kt & 3) * STAGE_FLOATS);
        const uint32_t* bs = as + AS_FLOATS;

        #pragma unroll
        for (int ks = 0; ks < 2; ks++) {
            const int kk = ks * 8;
            uint32_t af[2][4], bf[8][2];
            #pragma unroll
            for (int mt = 0; mt < 2; mt++) {
                int r = wm * 32 + mt * 16 + g;
                af[mt][0] = as[r * 20 + kk + tg];
                af[mt][1] = as[(r + 8) * 20 + kk + tg];
                af[mt][2] = as[r * 20 + kk + tg + 4];
                af[mt][3] = as[(r + 8) * 20 + kk + tg + 4];
            }
            #pragma unroll
            for (int nt = 0; nt < 8; nt++) {
                int c = wn * 64 + nt * 8 + g;
                if (BNT) {
                    bf[nt][0] = bs[c * 20 + kk + tg];
                    bf[nt][1] = bs[c * 20 + kk + tg + 4];
                } else {
                    bf[nt][0] = bs[(kk + tg) * 136 + c];
                    bf[nt][1] = bs[(kk + tg + 4) * 136 + c];
                }
            }
            #pragma unroll
            for (int mt = 0; mt < 2; mt++)
                #pragma unroll
                for (int nt = 0; nt < 8; nt++)
                    mma_tf32(acc[mt][nt], af[mt], bf[nt]);
        }

        if (kt + 3 < NKT) load_stage(kt + 3, (kt + 3) & 3);
        CP_COMMIT();                 // one group per iteration (may be empty)
    }

    // Epilogue: alpha + bias (+ optional tf32 rounding), direct gmem stores
    #pragma unroll
    for (int nt = 0; nt < 8; nt++) {
        const int c = n0 + wn * 64 + nt * 8 + tg * 2;
        float b0 = 0.f, b1 = 0.f;
        if (bp) { b0 = bp[c]; b1 = bp[c + 1]; }
        #pragma unroll
        for (int mt = 0; mt < 2; mt++) {
            const int r0 = m0 + wm * 32 + mt * 16 + g;
            float2 v0, v1;
            v0.x = alpha * acc[mt][nt][0] + b0;
            v0.y = alpha * acc[mt][nt][1] + b1;
            v1.x = alpha * acc[mt][nt][2] + b0;
            v1.y = alpha * acc[mt][nt][3] + b1;
            if (EPI_ROUND) {
                v0.x = roundtf(v0.x); v0.y = roundtf(v0.y);
                v1.x = roundtf(v1.x); v1.y = roundtf(v1.y);
            }
            *(float2*)(C + (size_t)r0 * ldc + c) = v0;
            *(float2*)(C + (size_t)(r0 + 8) * ldc + c) = v1;
        }
    }
}

// ---------------------------------------------------------------------------
// Row softmax over 2048 cols, in place; output tf32-rounded (feeds PV GEMM).
// ---------------------------------------------------------------------------
__global__ void __launch_bounds__(256) softmax_kernel(float* __restrict__ S)
{
    __shared__ float sh[32];
    __shared__ float bval;
    float* row = S + (size_t)blockIdx.x * SEQ;
    const int tid = threadIdx.x;

    float4 v0 = ((float4*)row)[tid];
    float4 v1 = ((float4*)row)[tid + 256];

    float m = fmaxf(fmaxf(fmaxf(v0.x, v0.y), fmaxf(v0.z, v0.w)),
                    fmaxf(fmaxf(v1.x, v1.y), fmaxf(v1.z, v1.w)));
    m = warpReduceMax(m);
    if ((tid & 31) == 0) sh[tid >> 5] = m;
    __syncthreads();
    if (tid < 32) {
        float t = (tid < 8) ? sh[tid] : -3.4e38f;
        t = warpReduceMax(t);
        if (tid == 0) bval = t;
    }
    __syncthreads();
    m = bval;

    v0.x = __expf(v0.x - m); v0.y = __expf(v0.y - m);
    v0.z = __expf(v0.z - m); v0.w = __expf(v0.w - m);
    v1.x = __expf(v1.x - m); v1.y = __expf(v1.y - m);
    v1.z = __expf(v1.z - m); v1.w = __expf(v1.w - m);
    float s = v0.x + v0.y + v0.z + v0.w + v1.x + v1.y + v1.z + v1.w;
    s = warpReduceSum(s);
    if ((tid & 31) == 0) sh[tid >> 5] = s;
    __syncthreads();
    if (tid < 32) {
        float t = (tid < 8) ? sh[tid] : 0.f;
        t = warpReduceSum(t);
        if (tid == 0) bval = 1.0f / t;
    }
    __syncthreads();
    const float inv = bval;

    v0.x = roundtf(v0.x * inv); v0.y = roundtf(v0.y * inv);
    v0.z = roundtf(v0.z * inv); v0.w = roundtf(v0.w * inv);
    v1.x = roundtf(v1.x * inv); v1.y = roundtf(v1.y * inv);
    v1.z = roundtf(v1.z * inv); v1.w = roundtf(v1.w * inv);
    ((float4*)row)[tid] = v0;
    ((float4*)row)[tid + 256] = v1;
}

// ---------------------------------------------------------------------------
// out = LayerNorm(a + b) * gamma + beta  (rows of D=1024, biased var, eps=1e-5)
// ROUND: tf32-round the stored output (when it feeds a GEMM as operand).
// ---------------------------------------------------------------------------
template<bool ROUND>
__global__ void __launch_bounds__(256) add_ln_kernel(
    const float* __restrict__ A, const float* __restrict__ Bv,
    const float* __restrict__ gamma, const float* __restrict__ beta,
    float* __restrict__ O)
{
    __shared__ float sh1[32], sh2[32];
    __shared__ float2 stats;
    const size_t base = (size_t)blockIdx.x * DIM;
    const int tid = threadIdx.x;

    float4 a = ((const float4*)(A + base))[tid];
    float4 b = ((const float4*)(Bv + base))[tid];
    float s0 = a.x + b.x, s1 = a.y + b.y, s2 = a.z + b.z, s3 = a.w + b.w;

    float sum = s0 + s1 + s2 + s3;
    float sq = s0 * s0 + s1 * s1 + s2 * s2 + s3 * s3;
    sum = warpReduceSum(sum);
    sq = warpReduceSum(sq);
    if ((tid & 31) == 0) { sh1[tid >> 5] = sum; sh2[tid >> 5] = sq; }
    __syncthreads();
    if (tid < 32) {
        float t1 = (tid < 8) ? sh1[tid] : 0.f;
        float t2 = (tid < 8) ? sh2[tid] : 0.f;
        t1 = warpReduceSum(t1);
        t2 = warpReduceSum(t2);
        if (tid == 0) {
            float mean = t1 * (1.0f / DIM);
            float var = t2 * (1.0f / DIM) - mean * mean;
            stats.x = mean;
            stats.y = rsqrtf(var + 1e-5f);
        }
    }
    __syncthreads();
    const float mean = stats.x, rs = stats.y;

    float4 gg = ((const float4*)gamma)[tid];
    float4 bb = ((const float4*)beta)[tid];
    float4 o;
    o.x = (s0 - mean) * rs * gg.x + bb.x;
    o.y = (s1 - mean) * rs * gg.y + bb.y;
    o.z = (s2 - mean) * rs * gg.z + bb.z;
    o.w = (s3 - mean) * rs * gg.w + bb.w;
    if (ROUND) {
        o.x = roundtf(o.x); o.y = roundtf(o.y);
        o.z = roundtf(o.z); o.w = roundtf(o.w);
    }
    ((float4*)(O + base))[tid] = o;
}

// ---------------------------------------------------------------------------
// Launch
// ---------------------------------------------------------------------------
#define SMEM_NN ((AS_FLOATS + BS_FLOATS_NN) * 4 * 4)   // 75776 B
#define SMEM_NT ((AS_FLOATS + BS_FLOATS_NT) * 4 * 4)   // 81920 B

extern "C" void kernel_launch(void* const* d_in, const int* in_sizes, int n_in,
                              void* d_out, int out_size)
{
    (void)in_sizes; (void)n_in; (void)out_size;
    const float* x   = (const float*)d_in[0];
    const float* Wq  = (const float*)d_in[1];
    const float* bq  = (const float*)d_in[2];
    const float* Wk  = (const float*)d_in[3];
    const float* bk  = (const float*)d_in[4];
    const float* Wv  = (const float*)d_in[5];
    const float* bv  = (const float*)d_in[6];
    const float* W1  = (const float*)d_in[7];
    const float* b1  = (const float*)d_in[8];
    const float* g1  = (const float*)d_in[9];
    const float* be1 = (const float*)d_in[10];
    const float* W2  = (const float*)d_in[11];
    const float* b2  = (const float*)d_in[12];
    const float* g2  = (const float*)d_in[13];
    const float* be2 = (const float*)d_in[14];
    float* out = (float*)d_out;

    float* base1;
    cudaGetSymbolAddress((void**)&base1, g_scratch);

    float* q  = base1 + OFF_Q;
    float* k  = base1 + OFF_K;
    float* v  = base1 + OFF_V;
    float* sc = base1 + OFF_SC;
    float* hd = base1 + OFF_Q;                         // heads (q dead)
    float* pj = base1 + OFF_K;                         // proj  (k dead)
    float* y  = base1 + OFF_K + (size_t)TOK * DIM;
    float* z2 = base1 + OFF_K + (size_t)2 * TOK * DIM;

    // Phase-1 aliases in the (not-yet-written) scores region:
    float* xr  = base1 + OFF_SC;                       // 8388608
    float* wqr = base1 + OFF_SC + (size_t)8388608;
    float* wkr = base1 + OFF_SC + (size_t)12582912;
    float* wvr = base1 + OFF_SC + (size_t)16777216;
    // Phase-3 aliases (scores dead after PV GEMM):
    float* w1r = base1 + OFF_SC;                       // 4194304
    float* w2r = base1 + OFF_SC + (size_t)4194304;     // 1048576

    cudaFuncSetAttribute(tc_gemm<0, false, true>,
        cudaFuncAttributeMaxDynamicSharedMemorySize, SMEM_NN);
    cudaFuncSetAttribute(tc_gemm<0, false, false>,
        cudaFuncAttributeMaxDynamicSharedMemorySize, SMEM_NN);
    cudaFuncSetAttribute(tc_gemm<0, true, false>,
        cudaFuncAttributeMaxDynamicSharedMemorySize, SMEM_NN);
    cudaFuncSetAttribute(tc_gemm<1, false, false>,
        cudaFuncAttributeMaxDynamicSharedMemorySize, SMEM_NT);

    const long long MM = (long long)DIM * DIM;
    const long long HEAD_QKV = (long long)TOK * DIM;   // per-head q/k/v stride
    const long long BLK_ATT  = (long long)SEQ * DIM;   // per-z [s][d] block
    const long long BLK_SC   = (long long)SEQ * SEQ;   // per-z score block
    dim3 blk(256);

    // ---- Phase 1: tf32 pre-rounding of x, Wq, Wk, Wv (into scores region) ----
    round_kernel<<<8192, 256>>>(x,  xr,  (int)(8388608 / 4));
    round_kernel<<<4096, 256>>>(Wq, wqr, (int)(4194304 / 4));
    round_kernel<<<4096, 256>>>(Wk, wkr, (int)(4194304 / 4));
    round_kernel<<<4096, 256>>>(Wv, wvr, (int)(4194304 / 4));

    // ---- QKV projections (NN, rounded epilogue) ----
    tc_gemm<0, false, true><<<dim3(8, 64, 4), blk, SMEM_NN>>>(
        xr, 0, wqr, MM, bq, DIM, q, HEAD_QKV, DIM, DIM, DIM, DIM, 1.0f);
    tc_gemm<0, false, true><<<dim3(8, 64, 4), blk, SMEM_NN>>>(
        xr, 0, wkr, MM, bk, DIM, k, HEAD_QKV, DIM, DIM, DIM, DIM, 1.0f);
    tc_gemm<0, false, true><<<dim3(8, 64, 4), blk, SMEM_NN>>>(
        xr, 0, wvr, MM, bv, DIM, v, HEAD_QKV, DIM, DIM, DIM, DIM, 1.0f);

    // ---- scores[z] = (q[z] @ k[z]^T) / 32  (NT; overwrites xr/w*r - dead) ----
    tc_gemm<1, false, false><<<dim3(16, 16, 16), blk, SMEM_NT>>>(
        q, BLK_ATT, k, BLK_ATT, nullptr, 0, sc, BLK_SC, DIM, DIM, DIM, SEQ, 0.03125f);

    // ---- row softmax (in place, tf32-rounded output) ----
    softmax_kernel<<<NHEAD * NBATCH * SEQ, blk>>>(sc);

    // ---- heads[z] = attn[z] @ v[z]  (NN, rounded epilogue -> feeds gather) ----
    tc_gemm<0, false, true><<<dim3(8, 16, 16), blk, SMEM_NN>>>(
        sc, BLK_SC, v, BLK_ATT, nullptr, 0, hd, BLK_ATT, SEQ, SEQ, DIM, DIM, 1.0f);

    // ---- Phase 3: round W1, W2 into the now-dead scores region ----
    round_kernel<<<4096, 256>>>(W1, w1r, (int)(4194304 / 4));
    round_kernel<<<1024, 256>>>(W2, w2r, (int)(1048576 / 4));

    // ---- proj = concat(heads) @ W1 + b1  (NN gather; feeds LN, no rounding) ----
    tc_gemm<0, true, false><<<dim3(8, 64, 1), blk, SMEM_NN>>>(
        hd, 0, w1r, 0, b1, 0, pj, 0, NHEAD * DIM, 0, DIM, DIM, 1.0f);

    // ---- y = LN(x + proj), tf32-rounded (feeds W2 GEMM) ----
    add_ln_kernel<true><<<TOK, blk>>>(x, pj, g1, be1, y);

    // ---- z2 = y @ W2 + b2  (NN; feeds final LN, no rounding) ----
    tc_gemm<0, false, false><<<dim3(8, 64, 1), blk, SMEM_NN>>>(
        y, 0, w2r, 0, b2, 0, z2, 0, DIM, DIM, DIM, DIM, 1.0f);

    // ---- out = LN(y + z2) ----
    add_ln_kernel<false><<<TOK, blk>>>(y, z2, g2, be2, out);
}

// round 10
// speedup vs baseline: 1.6360x; 1.0248x over previous
#include <cuda_runtime.h>
#include <cstdint>
#include <cstddef>

// Problem shape (fixed): B=4, S=2048, D=1024, H=4
#define TOK    8192
#define DIM    1024
#define NHEAD  4
#define SEQ    2048
#define NBATCH 4

// ---------------------------------------------------------------------------
// Scratch: ONE device-global symbol (640 MB + 128 KB rowsum). Liveness aliasing:
//   [OFF_Q )  q      [h][t][d]   -> reused as heads after QK^T
//   [OFF_K )  k      [h][t][d]   -> reused as proj/y/z2 after QK^T
//   [OFF_V )  v      [h][t][d]
//   [OFF_SC)  scores [z=h*4+b][s][t]; also hosts (phase 1) xr/wqr/wkr/wvr
//             and (phase 3, sc dead) w1r/w2r.
//   [OFF_RS)  rowsum int32 [z][s]  (16*2048 = 32768 entries)
// All launches on one stream; ordering makes every alias hazard-free.
// ---------------------------------------------------------------------------
#define OFF_Q  ((size_t)0)
#define OFF_K  ((size_t)33554432)
#define OFF_V  ((size_t)67108864)
#define OFF_SC ((size_t)100663296)
#define OFF_RS ((size_t)167772160)
#define SCRATCH_FLOATS ((size_t)167804928)
__device__ float g_scratch[SCRATCH_FLOATS];

#define RS_SCALE 16384.0f

// ---------------------------------------------------------------------------
// Helpers
// ---------------------------------------------------------------------------
__device__ __forceinline__ uint32_t f2tf(float x) {
    uint32_t y;
    asm("cvt.rna.tf32.f32 %0, %1;" : "=r"(y) : "f"(x));
    return y;
}
__device__ __forceinline__ float roundtf(float x) {
    return __uint_as_float(f2tf(x));
}

__device__ __forceinline__ void mma_tf32(float acc[4], const uint32_t a[4], const uint32_t b[2]) {
    asm volatile(
        "mma.sync.aligned.m16n8k8.row.col.f32.tf32.tf32.f32 "
        "{%0,%1,%2,%3}, {%4,%5,%6,%7}, {%8,%9}, {%0,%1,%2,%3};\n"
        : "+f"(acc[0]), "+f"(acc[1]), "+f"(acc[2]), "+f"(acc[3])
        : "r"(a[0]), "r"(a[1]), "r"(a[2]), "r"(a[3]), "r"(b[0]), "r"(b[1]));
}

__device__ __forceinline__ uint32_t smaddr(const void* p) {
    return (uint32_t)__cvta_generic_to_shared(p);
}

__device__ __forceinline__ void cpasync16(uint32_t dst, const float* src) {
    asm volatile("cp.async.cg.shared.global [%0], [%1], 16;" :: "r"(dst), "l"(src));
}
#define CP_COMMIT() asm volatile("cp.async.commit_group;" ::: "memory")
#define CP_WAIT2()  asm volatile("cp.async.wait_group 2;"  ::: "memory")

__device__ __forceinline__ float warpReduceSum(float v) {
    #pragma unroll
    for (int o = 16; o > 0; o >>= 1) v += __shfl_xor_sync(0xffffffffu, v, o);
    return v;
}

// ---------------------------------------------------------------------------
// Elementwise tf32 rounding: out[i] = round_tf32(in[i]).  n4 = count/4.
// ---------------------------------------------------------------------------
__global__ void __launch_bounds__(256) round_kernel(
    const float* __restrict__ in, float* __restrict__ out, int n4)
{
    int i = blockIdx.x * blockDim.x + threadIdx.x;
    if (i < n4) {
        float4 v = ((const float4*)in)[i];
        v.x = roundtf(v.x); v.y = roundtf(v.y);
        v.z = roundtf(v.z); v.w = roundtf(v.w);
        ((float4*)out)[i] = v;
    }
}

// Zero an int buffer.
__global__ void __launch_bounds__(256) zero_kernel(int* __restrict__ p, int n)
{
    int i = blockIdx.x * blockDim.x + threadIdx.x;
    if (i < n) p[i] = 0;
}

// ---------------------------------------------------------------------------
// TF32 mma.sync GEMM: C[z] = f( A[z] @ op(B[z]) )
// All memory operands ALREADY tf32-rounded -> no cvt in mainloop.
//   A gmem: [M][K] row-major (K contiguous); GATHER = heads-concat over k.
//   BNT=0: B gmem [K][N] (NN)       BNT=1: B gmem [N][K] (NT; C = A@B^T)
// EMODE epilogue:
//   0: alpha*acc + bias
//   1: roundtf(alpha*acc + bias)
//   2: e = roundtf(exp(alpha*acc)); store e; fixed-point-atomic row sums to rsum
//   3: roundtf(acc * RS_SCALE / rsum[row])        (row-softmax normalization)
// CTA 128x128, BK=16, 128 threads, 4 warps (2x2), warp tile 64x64.
// __launch_bounds__(128,2) -> 2 CTAs/SM; 4-stage cp.async pipeline.
// Padded smem: A [m][20], B-NN [k][136], B-NT [n][20] (all conflict-free).
// ---------------------------------------------------------------------------
#define AS_FLOATS 2560                     // 128 * 20
#define BS_FLOATS_NN 2176                  // 16 * 136
#define BS_FLOATS_NT 2560                  // 128 * 20

template<int BNT, bool GATHER, int EMODE>
__global__ void __launch_bounds__(128, 2)
tc_gemm(const float* __restrict__ A, long long sA,
        const float* __restrict__ B, long long sB,
        const float* __restrict__ bias, long long sBias,
        float* __restrict__ C, long long sC,
        int* __restrict__ rsum,
        int K, int lda, int ldb, int ldc, float alpha)
{
    constexpr int BS_FLOATS = BNT ? BS_FLOATS_NT : BS_FLOATS_NN;
    constexpr int STAGE_FLOATS = AS_FLOATS + BS_FLOATS;

    extern __shared__ float sm[];

    const int tid = threadIdx.x;
    const int z = blockIdx.z;
    if (!GATHER) A += (size_t)z * sA;
    B += (size_t)z * sB;
    C += (size_t)z * sC;
    const float* bp = bias ? bias + (size_t)z * sBias : nullptr;
    int* rs = rsum ? rsum + (size_t)z * SEQ : nullptr;

    const int m0 = blockIdx.y * 128;
    const int n0 = blockIdx.x * 128;
    const int NKT = K >> 4;

    const int lane = tid & 31, warp = tid >> 5;
    const int wm = warp >> 1;          // 0..1 : 64-row group
    const int wn = warp & 1;           // 0..1 : 64-col group
    const int g = lane >> 2, tg = lane & 3;

    auto load_stage = [&](int kt, int st) {
        float* as = sm + st * STAGE_FLOATS;
        float* bs = as + AS_FLOATS;
        const int kbase = kt * 16;
        #pragma unroll
        for (int i = 0; i < 4; i++) {                // A: 128 x 16
            int id = tid + i * 128;
            int m = id >> 2, c4 = (id & 3) << 2;
            const float* src;
            if (GATHER) {
                int kk = kbase + c4;
                src = A + ((size_t)(kk >> 10)) * ((size_t)TOK * DIM)
                        + (size_t)(m0 + m) * DIM + (kk & (DIM - 1));
            } else {
                src = A + (size_t)(m0 + m) * lda + kbase + c4;
            }
            cpasync16(smaddr(as + m * 20 + c4), src);
        }
        #pragma unroll
        for (int i = 0; i < 4; i++) {                // B: 16 x 128 (or 128 x 16)
            int id = tid + i * 128;
            if (BNT) {
                int n = id >> 2, c4 = (id & 3) << 2;
                cpasync16(smaddr(bs + n * 20 + c4),
                          B + (size_t)(n0 + n) * ldb + kbase + c4);
            } else {
                int kr = id >> 5, nc = (id & 31) << 2;
                cpasync16(smaddr(bs + kr * 136 + nc),
                          B + (size_t)(kbase + kr) * ldb + n0 + nc);
            }
        }
    };

    float acc[4][8][4];
    #pragma unroll
    for (int mt = 0; mt < 4; mt++)
        #pragma unroll
        for (int nt = 0; nt < 8; nt++)
            #pragma unroll
            for (int r = 0; r < 4; r++) acc[mt][nt][r] = 0.f;

    // Prologue: fill 3 stages (NKT >= 64 for all calls here)
    load_stage(0, 0); CP_COMMIT();
    load_stage(1, 1); CP_COMMIT();
    load_stage(2, 2); CP_COMMIT();

    for (int kt = 0; kt < NKT; kt++) {
        CP_WAIT2();                  // stage kt's group complete
        __syncthreads();             // all warps done with stage (kt-1)%4

        const uint32_t* as = reinterpret_cast<const uint32_t*>(sm + (kt & 3) * STAGE_FLOATS);
        const uint32_t* bs = as + AS_FLOATS;

        #pragma unroll
        for (int ks = 0; ks < 2; ks++) {
            const int kk = ks * 8;
            uint32_t af[4][4], bf[8][2];
            #pragma unroll
            for (int mt = 0; mt < 4; mt++) {
                int r = wm * 64 + mt * 16 + g;
                af[mt][0] = as[r * 20 + kk + tg];
                af[mt][1] = as[(r + 8) * 20 + kk + tg];
                af[mt][2] = as[r * 20 + kk + tg + 4];
                af[mt][3] = as[(r + 8) * 20 + kk + tg + 4];
            }
            #pragma unroll
            for (int nt = 0; nt < 8; nt++) {
                int c = wn * 64 + nt * 8 + g;
                if (BNT) {
                    bf[nt][0] = bs[c * 20 + kk + tg];
                    bf[nt][1] = bs[c * 20 + kk + tg + 4];
                } else {
                    bf[nt][0] = bs[(kk + tg) * 136 + c];
                    bf[nt][1] = bs[(kk + tg + 4) * 136 + c];
                }
            }
            #pragma unroll
            for (int mt = 0; mt < 4; mt++)
                #pragma unroll
                for (int nt = 0; nt < 8; nt++)
                    mma_tf32(acc[mt][nt], af[mt], bf[nt]);
        }

        if (kt + 3 < NKT) load_stage(kt + 3, (kt + 3) & 3);
        CP_COMMIT();                 // one group per iteration (may be empty)
    }

    // ---------------- Epilogue ----------------
    if (EMODE == 2) {
        // exp + row-sum accumulation (fixed-point atomics -> deterministic)
        float rp0[4] = {0.f, 0.f, 0.f, 0.f};
        float rp1[4] = {0.f, 0.f, 0.f, 0.f};
        #pragma unroll
        for (int nt = 0; nt < 8; nt++) {
            const int c = n0 + wn * 64 + nt * 8 + tg * 2;
            #pragma unroll
            for (int mt = 0; mt < 4; mt++) {
                const int r0 = m0 + wm * 64 + mt * 16 + g;
                float e0 = roundtf(__expf(alpha * acc[mt][nt][0]));
                float e1 = roundtf(__expf(alpha * acc[mt][nt][1]));
                float e2 = roundtf(__expf(alpha * acc[mt][nt][2]));
                float e3 = roundtf(__expf(alpha * acc[mt][nt][3]));
                rp0[mt] += e0 + e1;
                rp1[mt] += e2 + e3;
                float2 v0; v0.x = e0; v0.y = e1;
                float2 v1; v1.x = e2; v1.y = e3;
                *(float2*)(C + (size_t)r0 * ldc + c) = v0;
                *(float2*)(C + (size_t)(r0 + 8) * ldc + c) = v1;
            }
        }
        #pragma unroll
        for (int mt = 0; mt < 4; mt++) {
            float p0 = rp0[mt], p1 = rp1[mt];
            p0 += __shfl_xor_sync(0xffffffffu, p0, 1);
            p0 += __shfl_xor_sync(0xffffffffu, p0, 2);
            p1 += __shfl_xor_sync(0xffffffffu, p1, 1);
            p1 += __shfl_xor_sync(0xffffffffu, p1, 2);
            if (tg == 0) {
                const int r0 = m0 + wm * 64 + mt * 16 + g;
                atomicAdd(&rs[r0], __float2int_rn(p0 * RS_SCALE));
                atomicAdd(&rs[r0 + 8], __float2int_rn(p1 * RS_SCALE));
            }
        }
    } else if (EMODE == 3) {
        // row softmax normalization: out = roundtf(acc * RS_SCALE / rowsum)
        #pragma unroll
        for (int mt = 0; mt < 4; mt++) {
            const int r0 = m0 + wm * 64 + mt * 16 + g;
            const float inv0 = RS_SCALE / (float)rs[r0];
            const float inv1 = RS_SCALE / (float)rs[r0 + 8];
            #pragma unroll
            for (int nt = 0; nt < 8; nt++) {
                const int c = n0 + wn * 64 + nt * 8 + tg * 2;
                float2 v0, v1;
                v0.x = roundtf(acc[mt][nt][0] * inv0);
                v0.y = roundtf(acc[mt][nt][1] * inv0);
                v1.x = roundtf(acc[mt][nt][2] * inv1);
                v1.y = roundtf(acc[mt][nt][3] * inv1);
                *(float2*)(C + (size_t)r0 * ldc + c) = v0;
                *(float2*)(C + (size_t)(r0 + 8) * ldc + c) = v1;
            }
        }
    } else {
        #pragma unroll
        for (int nt = 0; nt < 8; nt++) {
            const int c = n0 + wn * 64 + nt * 8 + tg * 2;
            float b0 = 0.f, b1 = 0.f;
            if (bp) { b0 = bp[c]; b1 = bp[c + 1]; }
            #pragma unroll
            for (int mt = 0; mt < 4; mt++) {
                const int r0 = m0 + wm * 64 + mt * 16 + g;
                float2 v0, v1;
                v0.x = alpha * acc[mt][nt][0] + b0;
                v0.y = alpha * acc[mt][nt][1] + b1;
                v1.x = alpha * acc[mt][nt][2] + b0;
                v1.y = alpha * acc[mt][nt][3] + b1;
                if (EMODE == 1) {
                    v0.x = roundtf(v0.x); v0.y = roundtf(v0.y);
                    v1.x = roundtf(v1.x); v1.y = roundtf(v1.y);
                }
                *(float2*)(C + (size_t)r0 * ldc + c) = v0;
                *(float2*)(C + (size_t)(r0 + 8) * ldc + c) = v1;
            }
        }
    }
}

// ---------------------------------------------------------------------------
// out = LayerNorm(a + b) * gamma + beta  (rows of D=1024, biased var, eps=1e-5)
// ROUND: tf32-round the stored output (when it feeds a GEMM as operand).
// ---------------------------------------------------------------------------
template<bool ROUND>
__global__ void __launch_bounds__(256) add_ln_kernel(
    const float* __restrict__ A, const float* __restrict__ Bv,
    const float* __restrict__ gamma, const float* __restrict__ beta,
    float* __restrict__ O)
{
    __shared__ float sh1[32], sh2[32];
    __shared__ float2 stats;
    const size_t base = (size_t)blockIdx.x * DIM;
    const int tid = threadIdx.x;

    float4 a = ((const float4*)(A + base))[tid];
    float4 b = ((const float4*)(Bv + base))[tid];
    float s0 = a.x + b.x, s1 = a.y + b.y, s2 = a.z + b.z, s3 = a.w + b.w;

    float sum = s0 + s1 + s2 + s3;
    float sq = s0 * s0 + s1 * s1 + s2 * s2 + s3 * s3;
    sum = warpReduceSum(sum);
    sq = warpReduceSum(sq);
    if ((tid & 31) == 0) { sh1[tid >> 5] = sum; sh2[tid >> 5] = sq; }
    __syncthreads();
    if (tid < 32) {
        float t1 = (tid < 8) ? sh1[tid] : 0.f;
        float t2 = (tid < 8) ? sh2[tid] : 0.f;
        t1 = warpReduceSum(t1);
        t2 = warpReduceSum(t2);
        if (tid == 0) {
            float mean = t1 * (1.0f / DIM);
            float var = t2 * (1.0f / DIM) - mean * mean;
            stats.x = mean;
            stats.y = rsqrtf(var + 1e-5f);
        }
    }
    __syncthreads();
    const float mean = stats.x, rsc = stats.y;

    float4 gg = ((const float4*)gamma)[tid];
    float4 bb = ((const float4*)beta)[tid];
    float4 o;
    o.x = (s0 - mean) * rsc * gg.x + bb.x;
    o.y = (s1 - mean) * rsc * gg.y + bb.y;
    o.z = (s2 - mean) * rsc * gg.z + bb.z;
    o.w = (s3 - mean) * rsc * gg.w + bb.w;
    if (ROUND) {
        o.x = roundtf(o.x); o.y = roundtf(o.y);
        o.z = roundtf(o.z); o.w = roundtf(o.w);
    }
    ((float4*)(O + base))[tid] = o;
}

// ---------------------------------------------------------------------------
// Launch
// ---------------------------------------------------------------------------
#define SMEM_NN ((AS_FLOATS + BS_FLOATS_NN) * 4 * 4)   // 75776 B
#define SMEM_NT ((AS_FLOATS + BS_FLOATS_NT) * 4 * 4)   // 81920 B

extern "C" void kernel_launch(void* const* d_in, const int* in_sizes, int n_in,
                              void* d_out, int out_size)
{
    (void)in_sizes; (void)n_in; (void)out_size;
    const float* x   = (const float*)d_in[0];
    const float* Wq  = (const float*)d_in[1];
    const float* bq  = (const float*)d_in[2];
    const float* Wk  = (const float*)d_in[3];
    const float* bk  = (const float*)d_in[4];
    const float* Wv  = (const float*)d_in[5];
    const float* bv  = (const float*)d_in[6];
    const float* W1  = (const float*)d_in[7];
    const float* b1  = (const float*)d_in[8];
    const float* g1  = (const float*)d_in[9];
    const float* be1 = (const float*)d_in[10];
    const float* W2  = (const float*)d_in[11];
    const float* b2  = (const float*)d_in[12];
    const float* g2  = (const float*)d_in[13];
    const float* be2 = (const float*)d_in[14];
    float* out = (float*)d_out;

    float* base1;
    cudaGetSymbolAddress((void**)&base1, g_scratch);

    float* q  = base1 + OFF_Q;
    float* k  = base1 + OFF_K;
    float* v  = base1 + OFF_V;
    float* sc = base1 + OFF_SC;
    float* hd = base1 + OFF_Q;                         // heads (q dead)
    float* pj = base1 + OFF_K;                         // proj  (k dead)
    float* y  = base1 + OFF_K + (size_t)TOK * DIM;
    float* z2 = base1 + OFF_K + (size_t)2 * TOK * DIM;
    int*   rowsum = (int*)(base1 + OFF_RS);

    // Phase-1 aliases in the (not-yet-written) scores region:
    float* xr  = base1 + OFF_SC;                       // 8388608
    float* wqr = base1 + OFF_SC + (size_t)8388608;
    float* wkr = base1 + OFF_SC + (size_t)12582912;
    float* wvr = base1 + OFF_SC + (size_t)16777216;
    // Phase-3 aliases (scores dead after PV GEMM):
    float* w1r = base1 + OFF_SC;                       // 4194304
    float* w2r = base1 + OFF_SC + (size_t)4194304;     // 1048576

    cudaFuncSetAttribute(tc_gemm<0, false, 1>,
        cudaFuncAttributeMaxDynamicSharedMemorySize, SMEM_NN);
    cudaFuncSetAttribute(tc_gemm<0, false, 0>,
        cudaFuncAttributeMaxDynamicSharedMemorySize, SMEM_NN);
    cudaFuncSetAttribute(tc_gemm<0, false, 3>,
        cudaFuncAttributeMaxDynamicSharedMemorySize, SMEM_NN);
    cudaFuncSetAttribute(tc_gemm<0, true, 0>,
        cudaFuncAttributeMaxDynamicSharedMemorySize, SMEM_NN);
    cudaFuncSetAttribute(tc_gemm<1, false, 2>,
        cudaFuncAttributeMaxDynamicSharedMemorySize, SMEM_NT);

    const long long MM = (long long)DIM * DIM;
    const long long HEAD_QKV = (long long)TOK * DIM;   // per-head q/k/v stride
    const long long BLK_ATT  = (long long)SEQ * DIM;   // per-z [s][d] block
    const long long BLK_SC   = (long long)SEQ * SEQ;   // per-z score block
    dim3 blk(128);

    // ---- Phase 1: tf32 pre-rounding of x, Wq, Wk, Wv (into scores region) ----
    round_kernel<<<8192, 256>>>(x,  xr,  (int)(8388608 / 4));
    round_kernel<<<4096, 256>>>(Wq, wqr, (int)(4194304 / 4));
    round_kernel<<<4096, 256>>>(Wk, wkr, (int)(4194304 / 4));
    round_kernel<<<4096, 256>>>(Wv, wvr, (int)(4194304 / 4));
    zero_kernel<<<128, 256>>>(rowsum, NHEAD * NBATCH * SEQ);

    // ---- QKV projections (NN, rounded epilogue) ----
    tc_gemm<0, false, 1><<<dim3(8, 64, 4), blk, SMEM_NN>>>(
        xr, 0, wqr, MM, bq, DIM, q, HEAD_QKV, nullptr, DIM, DIM, DIM, DIM, 1.0f);
    tc_gemm<0, false, 1><<<dim3(8, 64, 4), blk, SMEM_NN>>>(
        xr, 0, wkr, MM, bk, DIM, k, HEAD_QKV, nullptr, DIM, DIM, DIM, DIM, 1.0f);
    tc_gemm<0, false, 1><<<dim3(8, 64, 4), blk, SMEM_NN>>>(
        xr, 0, wvr, MM, bv, DIM, v, HEAD_QKV, nullptr, DIM, DIM, DIM, DIM, 1.0f);

    // ---- P[z] = exp(q[z] @ k[z]^T / 32), rowsums -> rowsum[] (NT, fused) ----
    tc_gemm<1, false, 2><<<dim3(16, 16, 16), blk, SMEM_NT>>>(
        q, BLK_ATT, k, BLK_ATT, nullptr, 0, sc, BLK_SC, rowsum,
        DIM, DIM, DIM, SEQ, 0.03125f);

    // ---- heads[z] = (P[z] @ v[z]) / rowsum  (NN, row-scaled + rounded) ----
    tc_gemm<0, false, 3><<<dim3(8, 16, 16), blk, SMEM_NN>>>(
        sc, BLK_SC, v, BLK_ATT, nullptr, 0, hd, BLK_ATT, rowsum,
        SEQ, SEQ, DIM, DIM, 1.0f);

    // ---- Phase 3: round W1, W2 into the now-dead scores region ----
    round_kernel<<<4096, 256>>>(W1, w1r, (int)(4194304 / 4));
    round_kernel<<<1024, 256>>>(W2, w2r, (int)(1048576 / 4));

    // ---- proj = concat(heads) @ W1 + b1  (NN gather; feeds LN, no rounding) ----
    tc_gemm<0, true, 0><<<dim3(8, 64, 1), blk, SMEM_NN>>>(
        hd, 0, w1r, 0, b1, 0, pj, 0, nullptr, NHEAD * DIM, 0, DIM, DIM, 1.0f);

    // ---- y = LN(x + proj), tf32-rounded (feeds W2 GEMM) ----
    add_ln_kernel<true><<<TOK, 256>>>(x, pj, g1, be1, y);

    // ---- z2 = y @ W2 + b2  (NN; feeds final LN, no rounding) ----
    tc_gemm<0, false, 0><<<dim3(8, 64, 1), blk, SMEM_NN>>>(
        y, 0, w2r, 0, b2, 0, z2, 0, nullptr, DIM, DIM, DIM, DIM, 1.0f);

    // ---- out = LN(y + z2) ----
    add_ln_kernel<false><<<TOK, 256>>>(y, z2, g2, be2, out);
}

// round 12
// speedup vs baseline: 2.0637x; 1.2614x over previous
#include <cuda_runtime.h>
#include <cuda_bf16.h>
#include <cstdint>
#include <cstddef>

// Problem shape (fixed): B=4, S=2048, D=1024, H=4
#define TOK    8192
#define DIM    1024
#define NHEAD  4
#define SEQ    2048
#define NBATCH 4

// ---------------------------------------------------------------------------
// Scratch: ONE device-global symbol (640 MB + rowsum). Liveness aliasing:
//   [OFF_Q )  q bf16 [h][t][d] (32MB used)  -> region reused as heads f32 after QK^T
//   [OFF_K )  k bf16 (32MB)                 -> region reused as proj/y/z2 f32
//   [OFF_V )  v bf16 (32MB) ; vt bf16 [z][d][s] at OFF_V + 16777216 floats (64MB off)
//   [OFF_SC)  P bf16 [z][s][t] (128MB); also hosts (phase 1) xr/wqr/wkr/wvr f32
//             and (phase 3, P dead) w1r/w2r f32.
//   [OFF_RS)  rowsum int32 [z][s]
// All launches on one stream; ordering makes every alias hazard-free.
// ---------------------------------------------------------------------------
#define OFF_Q  ((size_t)0)
#define OFF_K  ((size_t)33554432)
#define OFF_V  ((size_t)67108864)
#define OFF_SC ((size_t)100663296)
#define OFF_RS ((size_t)167772160)
#define SCRATCH_FLOATS ((size_t)167804928)
__device__ float g_scratch[SCRATCH_FLOATS];

#define RS_SCALE 16384.0f

// ---------------------------------------------------------------------------
// Helpers
// ---------------------------------------------------------------------------
__device__ __forceinline__ uint32_t f2tf(float x) {
    uint32_t y;
    asm("cvt.rna.tf32.f32 %0, %1;" : "=r"(y) : "f"(x));
    return y;
}
__device__ __forceinline__ float roundtf(float x) {
    return __uint_as_float(f2tf(x));
}

__device__ __forceinline__ void mma_tf32(float acc[4], const uint32_t a[4], const uint32_t b[2]) {
    asm volatile(
        "mma.sync.aligned.m16n8k8.row.col.f32.tf32.tf32.f32 "
        "{%0,%1,%2,%3}, {%4,%5,%6,%7}, {%8,%9}, {%0,%1,%2,%3};\n"
        : "+f"(acc[0]), "+f"(acc[1]), "+f"(acc[2]), "+f"(acc[3])
        : "r"(a[0]), "r"(a[1]), "r"(a[2]), "r"(a[3]), "r"(b[0]), "r"(b[1]));
}

__device__ __forceinline__ void mma_bf16(float acc[4], const uint32_t a[4], const uint32_t b[2]) {
    asm volatile(
        "mma.sync.aligned.m16n8k16.row.col.f32.bf16.bf16.f32 "
        "{%0,%1,%2,%3}, {%4,%5,%6,%7}, {%8,%9}, {%0,%1,%2,%3};\n"
        : "+f"(acc[0]), "+f"(acc[1]), "+f"(acc[2]), "+f"(acc[3])
        : "r"(a[0]), "r"(a[1]), "r"(a[2]), "r"(a[3]), "r"(b[0]), "r"(b[1]));
}

__device__ __forceinline__ uint32_t smaddr(const void* p) {
    return (uint32_t)__cvta_generic_to_shared(p);
}

__device__ __forceinline__ void cpasync16(uint32_t dst, const void* src) {
    asm volatile("cp.async.cg.shared.global [%0], [%1], 16;" :: "r"(dst), "l"(src));
}
#define CP_COMMIT() asm volatile("cp.async.commit_group;" ::: "memory")
#define CP_WAIT2()  asm volatile("cp.async.wait_group 2;"  ::: "memory")

__device__ __forceinline__ float warpReduceSum(float v) {
    #pragma unroll
    for (int o = 16; o > 0; o >>= 1) v += __shfl_xor_sync(0xffffffffu, v, o);
    return v;
}

// ---------------------------------------------------------------------------
// Elementwise tf32 rounding: out[i] = round_tf32(in[i]).  n4 = count/4.
// ---------------------------------------------------------------------------
__global__ void __launch_bounds__(256) round_kernel(
    const float* __restrict__ in, float* __restrict__ out, int n4)
{
    int i = blockIdx.x * blockDim.x + threadIdx.x;
    if (i < n4) {
        float4 v = ((const float4*)in)[i];
        v.x = roundtf(v.x); v.y = roundtf(v.y);
        v.z = roundtf(v.z); v.w = roundtf(v.w);
        ((float4*)out)[i] = v;
    }
}

__global__ void __launch_bounds__(256) zero_kernel(int* __restrict__ p, int n)
{
    int i = blockIdx.x * blockDim.x + threadIdx.x;
    if (i < n) p[i] = 0;
}

// ---------------------------------------------------------------------------
// Batched bf16 transpose: out[z][D][S] = in[z][S][D]^T.  Block (32,8).
// ---------------------------------------------------------------------------
__global__ void __launch_bounds__(256) transpose_bf16(
    const __nv_bfloat16* __restrict__ in, __nv_bfloat16* __restrict__ out,
    long long sIn, long long sOut)
{
    __shared__ int t[32][33];
    const int z = blockIdx.z;
    in += (size_t)z * sIn;
    out += (size_t)z * sOut;
    const int d0 = blockIdx.x * 32, s0 = blockIdx.y * 32;
    #pragma unroll
    for (int i = 0; i < 32; i += 8)
        t[threadIdx.y + i][threadIdx.x] =
            (int)*(const unsigned short*)(in + (size_t)(s0 + threadIdx.y + i) * DIM + d0 + threadIdx.x);
    __syncthreads();
    #pragma unroll
    for (int i = 0; i < 32; i += 8)
        *(unsigned short*)(out + (size_t)(d0 + threadIdx.y + i) * SEQ + s0 + threadIdx.x) =
            (unsigned short)t[threadIdx.x][threadIdx.y + i];
}

// ---------------------------------------------------------------------------
// TF32 mma.sync GEMM (NN / gather): C[z] = f( A[z] @ B[z] + bias )
// Operands pre-rounded tf32 -> no cvt in mainloop.
// EMODE: 0 = f32 out; 1 = tf32-rounded f32 out; 4 = bf16 out (ldc/sC in bf16 elems)
// CTA 128x128, BK=16, 128 threads, 4 warps (2x2), warp 64x64, 2 CTAs/SM.
// ---------------------------------------------------------------------------
#define AS_FLOATS 2560                     // 128 * 20
#define BS_FLOATS_NN 2176                  // 16 * 136

template<bool GATHER, int EMODE>
__global__ void __launch_bounds__(128, 2)
tc_gemm(const float* __restrict__ A, long long sA,
        const float* __restrict__ B, long long sB,
        const float* __restrict__ bias, long long sBias,
        void* __restrict__ Cv, long long sC,
        int K, int lda, int ldb, int ldc)
{
    constexpr int STAGE_FLOATS = AS_FLOATS + BS_FLOATS_NN;
    extern __shared__ float sm[];

    const int tid = threadIdx.x;
    const int z = blockIdx.z;
    if (!GATHER) A += (size_t)z * sA;
    B += (size_t)z * sB;
    const float* bp = bias ? bias + (size_t)z * sBias : nullptr;
    float* Cf = (EMODE == 4) ? nullptr : ((float*)Cv + (size_t)z * sC);
    __nv_bfloat16* Cb = (EMODE == 4) ? ((__nv_bfloat16*)Cv + (size_t)z * sC) : nullptr;

    const int m0 = blockIdx.y * 128;
    const int n0 = blockIdx.x * 128;
    const int NKT = K >> 4;

    const int lane = tid & 31, warp = tid >> 5;
    const int wm = warp >> 1, wn = warp & 1;   // 2x2 -> warp 64x64
    const int g = lane >> 2, tg = lane & 3;

    auto load_stage = [&](int kt, int st) {
        float* as = sm + st * STAGE_FLOATS;
        float* bs = as + AS_FLOATS;
        const int kbase = kt * 16;
        #pragma unroll
        for (int i = 0; i < 4; i++) {                // A: 128 x 16
            int id = tid + i * 128;
            int m = id >> 2, c4 = (id & 3) << 2;
            const float* src;
            if (GATHER) {
                int kk = kbase + c4;
                src = A + ((size_t)(kk >> 10)) * ((size_t)TOK * DIM)
                        + (size_t)(m0 + m) * DIM + (kk & (DIM - 1));
            } else {
                src = A + (size_t)(m0 + m) * lda + kbase + c4;
            }
            cpasync16(smaddr(as + m * 20 + c4), src);
        }
        #pragma unroll
        for (int i = 0; i < 4; i++) {                // B: 16 x 128
            int id = tid + i * 128;
            int kr = id >> 5, nc = (id & 31) << 2;
            cpasync16(smaddr(bs + kr * 136 + nc),
                      B + (size_t)(kbase + kr) * ldb + n0 + nc);
        }
    };

    float acc[4][8][4];
    #pragma unroll
    for (int mt = 0; mt < 4; mt++)
        #pragma unroll
        for (int nt = 0; nt < 8; nt++)
            #pragma unroll
            for (int r = 0; r < 4; r++) acc[mt][nt][r] = 0.f;

    load_stage(0, 0); CP_COMMIT();
    load_stage(1, 1); CP_COMMIT();
    load_stage(2, 2); CP_COMMIT();

    for (int kt = 0; kt < NKT; kt++) {
        CP_WAIT2();
        __syncthreads();

        const uint32_t* as = reinterpret_cast<const uint32_t*>(sm + (kt & 3) * STAGE_FLOATS);
        const uint32_t* bs = as + AS_FLOATS;

        #pragma unroll
        for (int ks = 0; ks < 2; ks++) {
            const int kk = ks * 8;
            uint32_t af[4][4], bf[8][2];
            #pragma unroll
            for (int mt = 0; mt < 4; mt++) {
                int r = wm * 64 + mt * 16 + g;
                af[mt][0] = as[r * 20 + kk + tg];
                af[mt][1] = as[(r + 8) * 20 + kk + tg];
                af[mt][2] = as[r * 20 + kk + tg + 4];
                af[mt][3] = as[(r + 8) * 20 + kk + tg + 4];
            }
            #pragma unroll
            for (int nt = 0; nt < 8; nt++) {
                int c = wn * 64 + nt * 8 + g;
                bf[nt][0] = bs[(kk + tg) * 136 + c];
                bf[nt][1] = bs[(kk + tg + 4) * 136 + c];
            }
            #pragma unroll
            for (int mt = 0; mt < 4; mt++)
                #pragma unroll
                for (int nt = 0; nt < 8; nt++)
                    mma_tf32(acc[mt][nt], af[mt], bf[nt]);
        }

        if (kt + 3 < NKT) load_stage(kt + 3, (kt + 3) & 3);
        CP_COMMIT();
    }

    #pragma unroll
    for (int nt = 0; nt < 8; nt++) {
        const int c = n0 + wn * 64 + nt * 8 + tg * 2;
        float b0 = 0.f, b1 = 0.f;
        if (bp) { b0 = bp[c]; b1 = bp[c + 1]; }
        #pragma unroll
        for (int mt = 0; mt < 4; mt++) {
            const int r0 = m0 + wm * 64 + mt * 16 + g;
            float v0 = acc[mt][nt][0] + b0, v1 = acc[mt][nt][1] + b1;
            float v2 = acc[mt][nt][2] + b0, v3 = acc[mt][nt][3] + b1;
            if (EMODE == 4) {
                *(__nv_bfloat162*)(Cb + (size_t)r0 * ldc + c) = __floats2bfloat162_rn(v0, v1);
                *(__nv_bfloat162*)(Cb + (size_t)(r0 + 8) * ldc + c) = __floats2bfloat162_rn(v2, v3);
            } else {
                if (EMODE == 1) {
                    v0 = roundtf(v0); v1 = roundtf(v1);
                    v2 = roundtf(v2); v3 = roundtf(v3);
                }
                float2 w0; w0.x = v0; w0.y = v1;
                float2 w1; w1.x = v2; w1.y = v3;
                *(float2*)(Cf + (size_t)r0 * ldc + c) = w0;
                *(float2*)(Cf + (size_t)(r0 + 8) * ldc + c) = w1;
            }
        }
    }
}

// ---------------------------------------------------------------------------
// BF16 mma.sync GEMM (NT): C[z] = f( A[z] @ B[z]^T )
//   A: [M][K] bf16 (K contiguous), B: [N][K] bf16 (K contiguous).
// EMODE 2: e = exp(alpha*acc) -> bf16 C; fixed-point atomic row sums to rsum.
// EMODE 3: roundtf(acc * RS_SCALE / rsum[row]) -> f32 C.
// CTA 128x128, BK=32 (two k16 steps), 128 threads, warp 64x64, 2 CTAs/SM.
// smem rows: 64B data + 16B pad = 80B (conflict-free fragment LDS).
// ---------------------------------------------------------------------------
#define BF_ROW_WORDS 20                    // 80 bytes per row
#define BF_TILE_WORDS (128 * BF_ROW_WORDS) // 2560 u32 per operand tile
#define BF_STAGE_WORDS (2 * BF_TILE_WORDS) // 5120 u32 = 20480 B

template<int EMODE>
__global__ void __launch_bounds__(128, 2)
bf_gemm(const __nv_bfloat16* __restrict__ A, long long sA,
        const __nv_bfloat16* __restrict__ B, long long sB,
        void* __restrict__ Cv, long long sC,
        int* __restrict__ rsum,
        int K, int lda, int ldb, int ldc, float alpha)
{
    extern __shared__ uint32_t smw[];

    const int tid = threadIdx.x;
    const int z = blockIdx.z;
    A += (size_t)z * sA;
    B += (size_t)z * sB;
    int* rs = rsum + (size_t)z * SEQ;
    __nv_bfloat16* Cb = (EMODE == 2) ? ((__nv_bfloat16*)Cv + (size_t)z * sC) : nullptr;
    float* Cf = (EMODE == 3) ? ((float*)Cv + (size_t)z * sC) : nullptr;

    const int m0 = blockIdx.y * 128;
    const int n0 = blockIdx.x * 128;
    const int NKT = K >> 5;

    const int lane = tid & 31, warp = tid >> 5;
    const int wm = warp >> 1, wn = warp & 1;   // 2x2 -> warp 64x64
    const int g = lane >> 2, tg = lane & 3;

    auto load_stage = [&](int kt, int st) {
        uint32_t* as = smw + st * BF_STAGE_WORDS;
        uint32_t* bs = as + BF_TILE_WORDS;
        const int kbase = kt * 32;
        #pragma unroll
        for (int i = 0; i < 4; i++) {                // A: 128 x 32 bf16 = 512 chunks
            int id = tid + i * 128;
            int m = id >> 2, q16 = id & 3;           // 4 x 16B chunks per row
            cpasync16(smaddr(as + m * BF_ROW_WORDS + q16 * 4),
                      A + (size_t)(m0 + m) * lda + kbase + q16 * 8);
        }
        #pragma unroll
        for (int i = 0; i < 4; i++) {                // B: 128 x 32 bf16
            int id = tid + i * 128;
            int n = id >> 2, q16 = id & 3;
            cpasync16(smaddr(bs + n * BF_ROW_WORDS + q16 * 4),
                      B + (size_t)(n0 + n) * ldb + kbase + q16 * 8);
        }
    };

    float acc[4][8][4];
    #pragma unroll
    for (int mt = 0; mt < 4; mt++)
        #pragma unroll
        for (int nt = 0; nt < 8; nt++)
            #pragma unroll
            for (int r = 0; r < 4; r++) acc[mt][nt][r] = 0.f;

    load_stage(0, 0); CP_COMMIT();
    load_stage(1, 1); CP_COMMIT();
    load_stage(2, 2); CP_COMMIT();

    for (int kt = 0; kt < NKT; kt++) {
        CP_WAIT2();
        __syncthreads();

        const uint32_t* as = smw + (kt & 3) * BF_STAGE_WORDS;
        const uint32_t* bs = as + BF_TILE_WORDS;

        #pragma unroll
        for (int ks = 0; ks < 2; ks++) {             // two k16 sub-steps
            const int kw = ks * 8;                   // word offset within row
            uint32_t af[4][4], bfr[8][2];
            #pragma unroll
            for (int mt = 0; mt < 4; mt++) {
                int r = wm * 64 + mt * 16 + g;
                af[mt][0] = as[r * BF_ROW_WORDS + kw + tg];
                af[mt][1] = as[(r + 8) * BF_ROW_WORDS + kw + tg];
                af[mt][2] = as[r * BF_ROW_WORDS + kw + tg + 4];
                af[mt][3] = as[(r + 8) * BF_ROW_WORDS + kw + tg + 4];
            }
            #pragma unroll
            for (int nt = 0; nt < 8; nt++) {
                int c = wn * 64 + nt * 8 + g;
                bfr[nt][0] = bs[c * BF_ROW_WORDS + kw + tg];
                bfr[nt][1] = bs[c * BF_ROW_WORDS + kw + tg + 4];
            }
            #pragma unroll
            for (int mt = 0; mt < 4; mt++)
                #pragma unroll
                for (int nt = 0; nt < 8; nt++)
                    mma_bf16(acc[mt][nt], af[mt], bfr[nt]);
        }

        if (kt + 3 < NKT) load_stage(kt + 3, (kt + 3) & 3);
        CP_COMMIT();
    }

    if (EMODE == 2) {
        float rp0[4] = {0.f, 0.f, 0.f, 0.f};
        float rp1[4] = {0.f, 0.f, 0.f, 0.f};
        #pragma unroll
        for (int nt = 0; nt < 8; nt++) {
            const int c = n0 + wn * 64 + nt * 8 + tg * 2;
            #pragma unroll
            for (int mt = 0; mt < 4; mt++) {
                const int r0 = m0 + wm * 64 + mt * 16 + g;
                __nv_bfloat162 p0 = __floats2bfloat162_rn(
                    __expf(alpha * acc[mt][nt][0]), __expf(alpha * acc[mt][nt][1]));
                __nv_bfloat162 p1 = __floats2bfloat162_rn(
                    __expf(alpha * acc[mt][nt][2]), __expf(alpha * acc[mt][nt][3]));
                *(__nv_bfloat162*)(Cb + (size_t)r0 * ldc + c) = p0;
                *(__nv_bfloat162*)(Cb + (size_t)(r0 + 8) * ldc + c) = p1;
                rp0[mt] += __low2float(p0) + __high2float(p0);
                rp1[mt] += __low2float(p1) + __high2float(p1);
            }
        }
        #pragma unroll
        for (int mt = 0; mt < 4; mt++) {
            float p0 = rp0[mt], p1 = rp1[mt];
            p0 += __shfl_xor_sync(0xffffffffu, p0, 1);
            p0 += __shfl_xor_sync(0xffffffffu, p0, 2);
            p1 += __shfl_xor_sync(0xffffffffu, p1, 1);
            p1 += __shfl_xor_sync(0xffffffffu, p1, 2);
            if (tg == 0) {
                const int r0 = m0 + wm * 64 + mt * 16 + g;
                atomicAdd(&rs[r0], __float2int_rn(p0 * RS_SCALE));
                atomicAdd(&rs[r0 + 8], __float2int_rn(p1 * RS_SCALE));
            }
        }
    } else {
        #pragma unroll
        for (int mt = 0; mt < 4; mt++) {
            const int r0 = m0 + wm * 64 + mt * 16 + g;
            const float inv0 = RS_SCALE / (float)rs[r0];
            const float inv1 = RS_SCALE / (float)rs[r0 + 8];
            #pragma unroll
            for (int nt = 0; nt < 8; nt++) {
                const int c = n0 + wn * 64 + nt * 8 + tg * 2;
                float2 v0, v1;
                v0.x = roundtf(acc[mt][nt][0] * inv0);
                v0.y = roundtf(acc[mt][nt][1] * inv0);
                v1.x = roundtf(acc[mt][nt][2] * inv1);
                v1.y = roundtf(acc[mt][nt][3] * inv1);
                *(float2*)(Cf + (size_t)r0 * ldc + c) = v0;
                *(float2*)(Cf + (size_t)(r0 + 8) * ldc + c) = v1;
            }
        }
    }
}

// ---------------------------------------------------------------------------
// out = LayerNorm(a + b) * gamma + beta  (rows of D=1024, biased var, eps=1e-5)
// ---------------------------------------------------------------------------
template<bool ROUND>
__global__ void __launch_bounds__(256) add_ln_kernel(
    const float* __restrict__ A, const float* __restrict__ Bv,
    const float* __restrict__ gamma, const float* __restrict__ beta,
    float* __restrict__ O)
{
    __shared__ float sh1[32], sh2[32];
    __shared__ float2 stats;
    const size_t base = (size_t)blockIdx.x * DIM;
    const int tid = threadIdx.x;

    float4 a = ((const float4*)(A + base))[tid];
    float4 b = ((const float4*)(Bv + base))[tid];
    float s0 = a.x + b.x, s1 = a.y + b.y, s2 = a.z + b.z, s3 = a.w + b.w;

    float sum = s0 + s1 + s2 + s3;
    float sq = s0 * s0 + s1 * s1 + s2 * s2 + s3 * s3;
    sum = warpReduceSum(sum);
    sq = warpReduceSum(sq);
    if ((tid & 31) == 0) { sh1[tid >> 5] = sum; sh2[tid >> 5] = sq; }
    __syncthreads();
    if (tid < 32) {
        float t1 = (tid < 8) ? sh1[tid] : 0.f;
        float t2 = (tid < 8) ? sh2[tid] : 0.f;
        t1 = warpReduceSum(t1);
        t2 = warpReduceSum(t2);
        if (tid == 0) {
            float mean = t1 * (1.0f / DIM);
            float var = t2 * (1.0f / DIM) - mean * mean;
            stats.x = mean;
            stats.y = rsqrtf(var + 1e-5f);
        }
    }
    __syncthreads();
    const float mean = stats.x, rsc = stats.y;

    float4 gg = ((const float4*)gamma)[tid];
    float4 bb = ((const float4*)beta)[tid];
    float4 o;
    o.x = (s0 - mean) * rsc * gg.x + bb.x;
    o.y = (s1 - mean) * rsc * gg.y + bb.y;
    o.z = (s2 - mean) * rsc * gg.z + bb.z;
    o.w = (s3 - mean) * rsc * gg.w + bb.w;
    if (ROUND) {
        o.x = roundtf(o.x); o.y = roundtf(o.y);
        o.z = roundtf(o.z); o.w = roundtf(o.w);
    }
    ((float4*)(O + base))[tid] = o;
}

// ---------------------------------------------------------------------------
// Launch
// ---------------------------------------------------------------------------
#define SMEM_NN ((AS_FLOATS + BS_FLOATS_NN) * 4 * 4)   // 75776 B
#define SMEM_BF (BF_STAGE_WORDS * 4 * 4)               // 81920 B

extern "C" void kernel_launch(void* const* d_in, const int* in_sizes, int n_in,
                              void* d_out, int out_size)
{
    (void)in_sizes; (void)n_in; (void)out_size;
    const float* x   = (const float*)d_in[0];
    const float* Wq  = (const float*)d_in[1];
    const float* bq  = (const float*)d_in[2];
    const float* Wk  = (const float*)d_in[3];
    const float* bk  = (const float*)d_in[4];
    const float* Wv  = (const float*)d_in[5];
    const float* bv  = (const float*)d_in[6];
    const float* W1  = (const float*)d_in[7];
    const float* b1  = (const float*)d_in[8];
    const float* g1  = (const float*)d_in[9];
    const float* be1 = (const float*)d_in[10];
    const float* W2  = (const float*)d_in[11];
    const float* b2  = (const float*)d_in[12];
    const float* g2  = (const float*)d_in[13];
    const float* be2 = (const float*)d_in[14];
    float* out = (float*)d_out;

    float* base1;
    cudaGetSymbolAddress((void**)&base1, g_scratch);

    __nv_bfloat16* qb = (__nv_bfloat16*)(base1 + OFF_Q);
    __nv_bfloat16* kb = (__nv_bfloat16*)(base1 + OFF_K);
    __nv_bfloat16* vb = (__nv_bfloat16*)(base1 + OFF_V);
    __nv_bfloat16* vt = (__nv_bfloat16*)(base1 + OFF_V + (size_t)16777216);
    __nv_bfloat16* P  = (__nv_bfloat16*)(base1 + OFF_SC);
    float* hd = base1 + OFF_Q;                         // heads f32 (q bf16 dead)
    float* pj = base1 + OFF_K;                         // proj  (k bf16 dead)
    float* y  = base1 + OFF_K + (size_t)TOK * DIM;
    float* z2 = base1 + OFF_K + (size_t)2 * TOK * DIM;
    int*   rowsum = (int*)(base1 + OFF_RS);

    // Phase-1 aliases in the (not-yet-written) P region:
    float* xr  = base1 + OFF_SC;
    float* wqr = base1 + OFF_SC + (size_t)8388608;
    float* wkr = base1 + OFF_SC + (size_t)12582912;
    float* wvr = base1 + OFF_SC + (size_t)16777216;
    // Phase-3 aliases (P dead after PV):
    float* w1r = base1 + OFF_SC;
    float* w2r = base1 + OFF_SC + (size_t)4194304;

    cudaFuncSetAttribute(tc_gemm<false, 4>,
        cudaFuncAttributeMaxDynamicSharedMemorySize, SMEM_NN);
    cudaFuncSetAttribute(tc_gemm<false, 0>,
        cudaFuncAttributeMaxDynamicSharedMemorySize, SMEM_NN);
    cudaFuncSetAttribute(tc_gemm<true, 0>,
        cudaFuncAttributeMaxDynamicSharedMemorySize, SMEM_NN);
    cudaFuncSetAttribute(bf_gemm<2>,
        cudaFuncAttributeMaxDynamicSharedMemorySize, SMEM_BF);
    cudaFuncSetAttribute(bf_gemm<3>,
        cudaFuncAttributeMaxDynamicSharedMemorySize, SMEM_BF);

    const long long MM = (long long)DIM * DIM;
    const long long HEAD_QKV = (long long)TOK * DIM;   // per-head stride (elems)
    const long long BLK_ATT  = (long long)SEQ * DIM;   // per-z [s][d] (elems)
    const long long BLK_SC   = (long long)SEQ * SEQ;   // per-z P block (elems)
    dim3 blk(128);

    // ---- Phase 1: tf32 pre-rounding of x, Wq, Wk, Wv; zero rowsums ----
    round_kernel<<<8192, 256>>>(x,  xr,  (int)(8388608 / 4));
    round_kernel<<<4096, 256>>>(Wq, wqr, (int)(4194304 / 4));
    round_kernel<<<4096, 256>>>(Wk, wkr, (int)(4194304 / 4));
    round_kernel<<<4096, 256>>>(Wv, wvr, (int)(4194304 / 4));
    zero_kernel<<<128, 256>>>(rowsum, NHEAD * NBATCH * SEQ);

    // ---- QKV projections (tf32 NN, bf16 output) ----
    tc_gemm<false, 4><<<dim3(8, 64, 4), blk, SMEM_NN>>>(
        xr, 0, wqr, MM, bq, DIM, qb, HEAD_QKV, DIM, DIM, DIM, DIM);
    tc_gemm<false, 4><<<dim3(8, 64, 4), blk, SMEM_NN>>>(
        xr, 0, wkr, MM, bk, DIM, kb, HEAD_QKV, DIM, DIM, DIM, DIM);
    tc_gemm<false, 4><<<dim3(8, 64, 4), blk, SMEM_NN>>>(
        xr, 0, wvr, MM, bv, DIM, vb, HEAD_QKV, DIM, DIM, DIM, DIM);

    // ---- vt[z][d][s] = v[z][s][d]^T (bf16) ----
    transpose_bf16<<<dim3(32, 64, 16), dim3(32, 8)>>>(vb, vt, BLK_ATT, BLK_ATT);

    // ---- P[z] = exp(q @ k^T / 32) bf16, rowsums (bf16 NT, fused) ----
    bf_gemm<2><<<dim3(16, 16, 16), blk, SMEM_BF>>>(
        qb, BLK_ATT, kb, BLK_ATT, P, BLK_SC, rowsum,
        DIM, DIM, DIM, SEQ, 0.03125f);

    // ---- heads[z] = (P @ vt^T) / rowsum  (bf16 NT, f32 rounded out) ----
    bf_gemm<3><<<dim3(8, 16, 16), blk, SMEM_BF>>>(
        P, BLK_SC, vt, BLK_ATT, hd, BLK_ATT, rowsum,
        SEQ, SEQ, SEQ, DIM, 1.0f);

    // ---- Phase 3: round W1, W2 into the now-dead P region ----
    round_kernel<<<4096, 256>>>(W1, w1r, (int)(4194304 / 4));
    round_kernel<<<1024, 256>>>(W2, w2r, (int)(1048576 / 4));

    // ---- proj = concat(heads) @ W1 + b1 (tf32 gather; feeds LN) ----
    tc_gemm<true, 0><<<dim3(8, 64, 1), blk, SMEM_NN>>>(
        hd, 0, w1r, 0, b1, 0, pj, 0, NHEAD * DIM, 0, DIM, DIM);

    // ---- y = LN(x + proj), tf32-rounded ----
    add_ln_kernel<true><<<TOK, 256>>>(x, pj, g1, be1, y);

    // ---- z2 = y @ W2 + b2 (tf32 NN) ----
    tc_gemm<false, 0><<<dim3(8, 64, 1), blk, SMEM_NN>>>(
        y, 0, w2r, 0, b2, 0, z2, 0, DIM, DIM, DIM, DIM);

    // ---- out = LN(y + z2) ----
    add_ln_kernel<false><<<TOK, 256>>>(y, z2, g2, be2, out);
}

// round 15
// speedup vs baseline: 2.5521x; 1.2367x over previous
#include <cuda_runtime.h>
#include <cuda_bf16.h>
#include <cstdint>
#include <cstddef>

// Problem shape (fixed): B=4, S=2048, D=1024, H=4
#define TOK    8192
#define DIM    1024
#define NHEAD  4
#define SEQ    2048
#define NBATCH 4

// ---------------------------------------------------------------------------
// Scratch: ONE device-global symbol (640 MB + rowsum). Liveness aliasing:
//   [OFF_Q )  q bf16 [h][t][d]  -> region reused as heads f32 after QK^T
//   [OFF_K )  k bf16            -> region reused as proj/y/z2 f32
//   [OFF_V )  v bf16 ; vt bf16 [z][d][s] at OFF_V + 16777216 floats
//   [OFF_SC)  P bf16 [z][s][t] (first 33.5M floats).
//   [FREE0 )  upper half of SC region (33.5M floats, never touched by P).
//     Float offsets from FREE0 (sizes in floats; all disjoint, total 15.7M):
//       xb   bf16 @ 0         (4194304 floats used)
//       wqtb bf16 @ 4194304   (2097152)   4 heads x 1024 x 1024 bf16
//       wktb bf16 @ 6291456   (2097152)
//       wvtb bf16 @ 8388608   (2097152)
//       w1r  f32  @ 10485760  (4194304)
//       w2r  f32  @ 14680064  (1048576)
//   [OFF_RS)  rowsum int32 [z][s]
// All launches on one stream; ordering makes every alias hazard-free.
// ---------------------------------------------------------------------------
#define OFF_Q  ((size_t)0)
#define OFF_K  ((size_t)33554432)
#define OFF_V  ((size_t)67108864)
#define OFF_SC ((size_t)100663296)
#define FREE0  ((size_t)134217728)
#define OFF_RS ((size_t)167772160)
#define SCRATCH_FLOATS ((size_t)167804928)
__device__ float g_scratch[SCRATCH_FLOATS];

#define RS_SCALE 16384.0f

// ---------------------------------------------------------------------------
// Helpers
// ---------------------------------------------------------------------------
__device__ __forceinline__ uint32_t f2tf(float x) {
    uint32_t y;
    asm("cvt.rna.tf32.f32 %0, %1;" : "=r"(y) : "f"(x));
    return y;
}
__device__ __forceinline__ float roundtf(float x) {
    return __uint_as_float(f2tf(x));
}

__device__ __forceinline__ void mma_tf32(float acc[4], const uint32_t a[4], const uint32_t b[2]) {
    asm volatile(
        "mma.sync.aligned.m16n8k8.row.col.f32.tf32.tf32.f32 "
        "{%0,%1,%2,%3}, {%4,%5,%6,%7}, {%8,%9}, {%0,%1,%2,%3};\n"
        : "+f"(acc[0]), "+f"(acc[1]), "+f"(acc[2]), "+f"(acc[3])
        : "r"(a[0]), "r"(a[1]), "r"(a[2]), "r"(a[3]), "r"(b[0]), "r"(b[1]));
}

__device__ __forceinline__ void mma_bf16(float acc[4], const uint32_t a[4], const uint32_t b[2]) {
    asm volatile(
        "mma.sync.aligned.m16n8k16.row.col.f32.bf16.bf16.f32 "
        "{%0,%1,%2,%3}, {%4,%5,%6,%7}, {%8,%9}, {%0,%1,%2,%3};\n"
        : "+f"(acc[0]), "+f"(acc[1]), "+f"(acc[2]), "+f"(acc[3])
        : "r"(a[0]), "r"(a[1]), "r"(a[2]), "r"(a[3]), "r"(b[0]), "r"(b[1]));
}

__device__ __forceinline__ uint32_t smaddr(const void* p) {
    return (uint32_t)__cvta_generic_to_shared(p);
}

__device__ __forceinline__ void cpasync16(uint32_t dst, const void* src) {
    asm volatile("cp.async.cg.shared.global [%0], [%1], 16;" :: "r"(dst), "l"(src));
}
#define CP_COMMIT() asm volatile("cp.async.commit_group;" ::: "memory")
#define CP_WAIT2()  asm volatile("cp.async.wait_group 2;"  ::: "memory")

__device__ __forceinline__ float warpReduceSum(float v) {
    #pragma unroll
    for (int o = 16; o > 0; o >>= 1) v += __shfl_xor_sync(0xffffffffu, v, o);
    return v;
}

// ---------------------------------------------------------------------------
// Elementwise tf32 rounding: out[i] = round_tf32(in[i]).  n4 = count/4.
// ---------------------------------------------------------------------------
__global__ void __launch_bounds__(256) round_kernel(
    const float* __restrict__ in, float* __restrict__ out, int n4)
{
    int i = blockIdx.x * blockDim.x + threadIdx.x;
    if (i < n4) {
        float4 v = ((const float4*)in)[i];
        v.x = roundtf(v.x); v.y = roundtf(v.y);
        v.z = roundtf(v.z); v.w = roundtf(v.w);
        ((float4*)out)[i] = v;
    }
}

// f32 -> bf16 elementwise.  n4 = count/4.
__global__ void __launch_bounds__(256) cvt_bf16_kernel(
    const float* __restrict__ in, __nv_bfloat16* __restrict__ out, int n4)
{
    int i = blockIdx.x * blockDim.x + threadIdx.x;
    if (i < n4) {
        float4 v = ((const float4*)in)[i];
        __nv_bfloat162 lo = __floats2bfloat162_rn(v.x, v.y);
        __nv_bfloat162 hi = __floats2bfloat162_rn(v.z, v.w);
        ((__nv_bfloat162*)out)[i * 2] = lo;
        ((__nv_bfloat162*)out)[i * 2 + 1] = hi;
    }
}

// Batched f32 -> bf16 transpose: out[z][N][K] = bf16(in[z][K][N]).
__global__ void __launch_bounds__(256) cvt_transpose_bf16(
    const float* __restrict__ in, __nv_bfloat16* __restrict__ out,
    int R, int C, long long sIn, long long sOut)
{
    __shared__ float t[32][33];
    const int z = blockIdx.z;
    in += (size_t)z * sIn;
    out += (size_t)z * sOut;
    const int c0 = blockIdx.x * 32, r0 = blockIdx.y * 32;
    #pragma unroll
    for (int i = 0; i < 32; i += 8)
        t[threadIdx.y + i][threadIdx.x] =
            in[(size_t)(r0 + threadIdx.y + i) * C + c0 + threadIdx.x];
    __syncthreads();
    #pragma unroll
    for (int i = 0; i < 32; i += 8)
        out[(size_t)(c0 + threadIdx.y + i) * R + r0 + threadIdx.x] =
            __float2bfloat16(t[threadIdx.x][threadIdx.y + i]);
}

__global__ void __launch_bounds__(256) zero_kernel(int* __restrict__ p, int n)
{
    int i = blockIdx.x * blockDim.x + threadIdx.x;
    if (i < n) p[i] = 0;
}

// ---------------------------------------------------------------------------
// Batched bf16 transpose: out[z][D][S] = in[z][S][D]^T.  Block (32,8).
// ---------------------------------------------------------------------------
__global__ void __launch_bounds__(256) transpose_bf16(
    const __nv_bfloat16* __restrict__ in, __nv_bfloat16* __restrict__ out,
    long long sIn, long long sOut)
{
    __shared__ int t[32][33];
    const int z = blockIdx.z;
    in += (size_t)z * sIn;
    out += (size_t)z * sOut;
    const int d0 = blockIdx.x * 32, s0 = blockIdx.y * 32;
    #pragma unroll
    for (int i = 0; i < 32; i += 8)
        t[threadIdx.y + i][threadIdx.x] =
            (int)*(const unsigned short*)(in + (size_t)(s0 + threadIdx.y + i) * DIM + d0 + threadIdx.x);
    __syncthreads();
    #pragma unroll
    for (int i = 0; i < 32; i += 8)
        *(unsigned short*)(out + (size_t)(d0 + threadIdx.y + i) * SEQ + s0 + threadIdx.x) =
            (unsigned short)t[threadIdx.x][threadIdx.y + i];
}

// ---------------------------------------------------------------------------
// TF32 mma.sync GEMM (NN / gather): C[z] = f( A[z] @ B[z] + bias )
// EMODE: 0 = f32 out; 1 = tf32-rounded f32 out.
// CTA 128x128, BK=16, 128 threads, 4 warps (2x2), warp 64x64, 2 CTAs/SM.
// ---------------------------------------------------------------------------
#define AS_FLOATS 2560                     // 128 * 20
#define BS_FLOATS_NN 2176                  // 16 * 136

template<bool GATHER, int EMODE>
__global__ void __launch_bounds__(128, 2)
tc_gemm(const float* __restrict__ A, long long sA,
        const float* __restrict__ B, long long sB,
        const float* __restrict__ bias, long long sBias,
        float* __restrict__ C, long long sC,
        int K, int lda, int ldb, int ldc)
{
    constexpr int STAGE_FLOATS = AS_FLOATS + BS_FLOATS_NN;
    extern __shared__ float sm[];

    const int tid = threadIdx.x;
    const int z = blockIdx.z;
    if (!GATHER) A += (size_t)z * sA;
    B += (size_t)z * sB;
    C += (size_t)z * sC;
    const float* bp = bias ? bias + (size_t)z * sBias : nullptr;

    const int m0 = blockIdx.y * 128;
    const int n0 = blockIdx.x * 128;
    const int NKT = K >> 4;

    const int lane = tid & 31, warp = tid >> 5;
    const int wm = warp >> 1, wn = warp & 1;   // 2x2 -> warp 64x64
    const int g = lane >> 2, tg = lane & 3;

    auto load_stage = [&](int kt, int st) {
        float* as = sm + st * STAGE_FLOATS;
        float* bs = as + AS_FLOATS;
        const int kbase = kt * 16;
        #pragma unroll
        for (int i = 0; i < 4; i++) {                // A: 128 x 16
            int id = tid + i * 128;
            int m = id >> 2, c4 = (id & 3) << 2;
            const float* src;
            if (GATHER) {
                int kk = kbase + c4;
                src = A + ((size_t)(kk >> 10)) * ((size_t)TOK * DIM)
                        + (size_t)(m0 + m) * DIM + (kk & (DIM - 1));
            } else {
                src = A + (size_t)(m0 + m) * lda + kbase + c4;
            }
            cpasync16(smaddr(as + m * 20 + c4), src);
        }
        #pragma unroll
        for (int i = 0; i < 4; i++) {                // B: 16 x 128
            int id = tid + i * 128;
            int kr = id >> 5, nc = (id & 31) << 2;
            cpasync16(smaddr(bs + kr * 136 + nc),
                      B + (size_t)(kbase + kr) * ldb + n0 + nc);
        }
    };

    float acc[4][8][4];
    #pragma unroll
    for (int mt = 0; mt < 4; mt++)
        #pragma unroll
        for (int nt = 0; nt < 8; nt++)
            #pragma unroll
            for (int r = 0; r < 4; r++) acc[mt][nt][r] = 0.f;

    load_stage(0, 0); CP_COMMIT();
    load_stage(1, 1); CP_COMMIT();
    load_stage(2, 2); CP_COMMIT();

    for (int kt = 0; kt < NKT; kt++) {
        CP_WAIT2();
        __syncthreads();

        const uint32_t* as = reinterpret_cast<const uint32_t*>(sm + (kt & 3) * STAGE_FLOATS);
        const uint32_t* bs = as + AS_FLOATS;

        #pragma unroll
        for (int ks = 0; ks < 2; ks++) {
            const int kk = ks * 8;
            uint32_t af[4][4], bf[8][2];
            #pragma unroll
            for (int mt = 0; mt < 4; mt++) {
                int r = wm * 64 + mt * 16 + g;
                af[mt][0] = as[r * 20 + kk + tg];
                af[mt][1] = as[(r + 8) * 20 + kk + tg];
                af[mt][2] = as[r * 20 + kk + tg + 4];
                af[mt][3] = as[(r + 8) * 20 + kk + tg + 4];
            }
            #pragma unroll
            for (int nt = 0; nt < 8; nt++) {
                int c = wn * 64 + nt * 8 + g;
                bf[nt][0] = bs[(kk + tg) * 136 + c];
                bf[nt][1] = bs[(kk + tg + 4) * 136 + c];
            }
            #pragma unroll
            for (int mt = 0; mt < 4; mt++)
                #pragma unroll
                for (int nt = 0; nt < 8; nt++)
                    mma_tf32(acc[mt][nt], af[mt], bf[nt]);
        }

        if (kt + 3 < NKT) load_stage(kt + 3, (kt + 3) & 3);
        CP_COMMIT();
    }

    #pragma unroll
    for (int nt = 0; nt < 8; nt++) {
        const int c = n0 + wn * 64 + nt * 8 + tg * 2;
        float b0 = 0.f, b1 = 0.f;
        if (bp) { b0 = bp[c]; b1 = bp[c + 1]; }
        #pragma unroll
        for (int mt = 0; mt < 4; mt++) {
            const int r0 = m0 + wm * 64 + mt * 16 + g;
            float v0 = acc[mt][nt][0] + b0, v1 = acc[mt][nt][1] + b1;
            float v2 = acc[mt][nt][2] + b0, v3 = acc[mt][nt][3] + b1;
            if (EMODE == 1) {
                v0 = roundtf(v0); v1 = roundtf(v1);
                v2 = roundtf(v2); v3 = roundtf(v3);
            }
            float2 w0; w0.x = v0; w0.y = v1;
            float2 w1; w1.x = v2; w1.y = v3;
            *(float2*)(C + (size_t)r0 * ldc + c) = w0;
            *(float2*)(C + (size_t)(r0 + 8) * ldc + c) = w1;
        }
    }
}

// ---------------------------------------------------------------------------
// BF16 mma.sync GEMM (NT): C[z] = f( A[z] @ B[z]^T )
//   A: [M][K] bf16 (K contiguous), B: [N][K] bf16 (K contiguous).
// EMODE 2: e = exp(alpha*acc) -> bf16 C; fixed-point atomic row sums to rsum.
// EMODE 3: roundtf(acc * RS_SCALE / rsum[row]) -> f32 C.
// EMODE 4: bf16(acc + bias) -> bf16 C.  (QKV projections)
// CTA 128x128, BK=32 (two k16 steps), 128 threads, warp 64x64, 2 CTAs/SM.
// smem rows: 64B data + 16B pad = 80B (conflict-free fragment LDS).
// ---------------------------------------------------------------------------
#define BF_ROW_WORDS 20                    // 80 bytes per row
#define BF_TILE_WORDS (128 * BF_ROW_WORDS) // 2560 u32 per operand tile
#define BF_STAGE_WORDS (2 * BF_TILE_WORDS) // 5120 u32 = 20480 B

template<int EMODE>
__global__ void __launch_bounds__(128, 2)
bf_gemm(const __nv_bfloat16* __restrict__ A, long long sA,
        const __nv_bfloat16* __restrict__ B, long long sB,
        const float* __restrict__ bias, long long sBias,
        void* __restrict__ Cv, long long sC,
        int* __restrict__ rsum,
        int K, int lda, int ldb, int ldc, float alpha)
{
    extern __shared__ uint32_t smw[];

    const int tid = threadIdx.x;
    const int z = blockIdx.z;
    if (sA) A += (size_t)z * sA;
    B += (size_t)z * sB;
    const float* bp = bias ? bias + (size_t)z * sBias : nullptr;
    __nv_bfloat16* Cb = (EMODE == 2 || EMODE == 4)
        ? ((__nv_bfloat16*)Cv + (size_t)z * sC) : nullptr;
    float* Cf = (EMODE == 3) ? ((float*)Cv + (size_t)z * sC) : nullptr;

    const int m0 = blockIdx.y * 128;
    const int n0 = blockIdx.x * 128;
    const int NKT = K >> 5;

    const int lane = tid & 31, warp = tid >> 5;
    const int wm = warp >> 1, wn = warp & 1;   // 2x2 -> warp 64x64
    const int g = lane >> 2, tg = lane & 3;

    auto load_stage = [&](int kt, int st) {
        uint32_t* as = smw + st * BF_STAGE_WORDS;
        uint32_t* bs = as + BF_TILE_WORDS;
        const int kbase = kt * 32;
        #pragma unroll
        for (int i = 0; i < 4; i++) {                // A: 128 x 32 bf16
            int id = tid + i * 128;
            int m = id >> 2, q16 = id & 3;
            cpasync16(smaddr(as + m * BF_ROW_WORDS + q16 * 4),
                      A + (size_t)(m0 + m) * lda + kbase + q16 * 8);
        }
        #pragma unroll
        for (int i = 0; i < 4; i++) {                // B: 128 x 32 bf16
            int id = tid + i * 128;
            int n = id >> 2, q16 = id & 3;
            cpasync16(smaddr(bs + n * BF_ROW_WORDS + q16 * 4),
                      B + (size_t)(n0 + n) * ldb + kbase + q16 * 8);
        }
    };

    float acc[4][8][4];
    #pragma unroll
    for (int mt = 0; mt < 4; mt++)
        #pragma unroll
        for (int nt = 0; nt < 8; nt++)
            #pragma unroll
            for (int r = 0; r < 4; r++) acc[mt][nt][r] = 0.f;

    load_stage(0, 0); CP_COMMIT();
    load_stage(1, 1); CP_COMMIT();
    load_stage(2, 2); CP_COMMIT();

    for (int kt = 0; kt < NKT; kt++) {
        CP_WAIT2();
        __syncthreads();

        const uint32_t* as = smw + (kt & 3) * BF_STAGE_WORDS;
        const uint32_t* bs = as + BF_TILE_WORDS;

        #pragma unroll
        for (int ks = 0; ks < 2; ks++) {             // two k16 sub-steps
            const int kw = ks * 8;
            uint32_t af[4][4], bfr[8][2];
            #pragma unroll
            for (int mt = 0; mt < 4; mt++) {
                int r = wm * 64 + mt * 16 + g;
                af[mt][0] = as[r * BF_ROW_WORDS + kw + tg];
                af[mt][1] = as[(r + 8) * BF_ROW_WORDS + kw + tg];
                af[mt][2] = as[r * BF_ROW_WORDS + kw + tg + 4];
                af[mt][3] = as[(r + 8) * BF_ROW_WORDS + kw + tg + 4];
            }
            #pragma unroll
            for (int nt = 0; nt < 8; nt++) {
                int c = wn * 64 + nt * 8 + g;
                bfr[nt][0] = bs[c * BF_ROW_WORDS + kw + tg];
                bfr[nt][1] = bs[c * BF_ROW_WORDS + kw + tg + 4];
            }
            #pragma unroll
            for (int mt = 0; mt < 4; mt++)
                #pragma unroll
                for (int nt = 0; nt < 8; nt++)
                    mma_bf16(acc[mt][nt], af[mt], bfr[nt]);
        }

        if (kt + 3 < NKT) load_stage(kt + 3, (kt + 3) & 3);
        CP_COMMIT();
    }

    if (EMODE == 2) {
        int* rs = rsum + (size_t)z * SEQ;
        float rp0[4] = {0.f, 0.f, 0.f, 0.f};
        float rp1[4] = {0.f, 0.f, 0.f, 0.f};
        #pragma unroll
        for (int nt = 0; nt < 8; nt++) {
            const int c = n0 + wn * 64 + nt * 8 + tg * 2;
            #pragma unroll
            for (int mt = 0; mt < 4; mt++) {
                const int r0 = m0 + wm * 64 + mt * 16 + g;
                __nv_bfloat162 p0 = __floats2bfloat162_rn(
                    __expf(alpha * acc[mt][nt][0]), __expf(alpha * acc[mt][nt][1]));
                __nv_bfloat162 p1 = __floats2bfloat162_rn(
                    __expf(alpha * acc[mt][nt][2]), __expf(alpha * acc[mt][nt][3]));
                *(__nv_bfloat162*)(Cb + (size_t)r0 * ldc + c) = p0;
                *(__nv_bfloat162*)(Cb + (size_t)(r0 + 8) * ldc + c) = p1;
                rp0[mt] += __low2float(p0) + __high2float(p0);
                rp1[mt] += __low2float(p1) + __high2float(p1);
            }
        }
        #pragma unroll
        for (int mt = 0; mt < 4; mt++) {
            float p0 = rp0[mt], p1 = rp1[mt];
            p0 += __shfl_xor_sync(0xffffffffu, p0, 1);
            p0 += __shfl_xor_sync(0xffffffffu, p0, 2);
            p1 += __shfl_xor_sync(0xffffffffu, p1, 1);
            p1 += __shfl_xor_sync(0xffffffffu, p1, 2);
            if (tg == 0) {
                const int r0 = m0 + wm * 64 + mt * 16 + g;
                atomicAdd(&rs[r0], __float2int_rn(p0 * RS_SCALE));
                atomicAdd(&rs[r0 + 8], __float2int_rn(p1 * RS_SCALE));
            }
        }
    } else if (EMODE == 3) {
        int* rs = rsum + (size_t)z * SEQ;
        #pragma unroll
        for (int mt = 0; mt < 4; mt++) {
            const int r0 = m0 + wm * 64 + mt * 16 + g;
            const float inv0 = RS_SCALE / (float)rs[r0];
            const float inv1 = RS_SCALE / (float)rs[r0 + 8];
            #pragma unroll
            for (int nt = 0; nt < 8; nt++) {
                const int c = n0 + wn * 64 + nt * 8 + tg * 2;
                float2 v0, v1;
                v0.x = roundtf(acc[mt][nt][0] * inv0);
                v0.y = roundtf(acc[mt][nt][1] * inv0);
                v1.x = roundtf(acc[mt][nt][2] * inv1);
                v1.y = roundtf(acc[mt][nt][3] * inv1);
                *(float2*)(Cf + (size_t)r0 * ldc + c) = v0;
                *(float2*)(Cf + (size_t)(r0 + 8) * ldc + c) = v1;
            }
        }
    } else {   // EMODE 4: bias + bf16 store
        #pragma unroll
        for (int nt = 0; nt < 8; nt++) {
            const int c = n0 + wn * 64 + nt * 8 + tg * 2;
            float b0 = 0.f, b1 = 0.f;
            if (bp) { b0 = bp[c]; b1 = bp[c + 1]; }
            #pragma unroll
            for (int mt = 0; mt < 4; mt++) {
                const int r0 = m0 + wm * 64 + mt * 16 + g;
                *(__nv_bfloat162*)(Cb + (size_t)r0 * ldc + c) =
                    __floats2bfloat162_rn(acc[mt][nt][0] + b0, acc[mt][nt][1] + b1);
                *(__nv_bfloat162*)(Cb + (size_t)(r0 + 8) * ldc + c) =
                    __floats2bfloat162_rn(acc[mt][nt][2] + b0, acc[mt][nt][3] + b1);
            }
        }
    }
}

// ---------------------------------------------------------------------------
// out = LayerNorm(a + b) * gamma + beta  (rows of D=1024, biased var, eps=1e-5)
// ---------------------------------------------------------------------------
template<bool ROUND>
__global__ void __launch_bounds__(256) add_ln_kernel(
    const float* __restrict__ A, const float* __restrict__ Bv,
    const float* __restrict__ gamma, const float* __restrict__ beta,
    float* __restrict__ O)
{
    __shared__ float sh1[32], sh2[32];
    __shared__ float2 stats;
    const size_t base = (size_t)blockIdx.x * DIM;
    const int tid = threadIdx.x;

    float4 a = ((const float4*)(A + base))[tid];
    float4 b = ((const float4*)(Bv + base))[tid];
    float s0 = a.x + b.x, s1 = a.y + b.y, s2 = a.z + b.z, s3 = a.w + b.w;

    float sum = s0 + s1 + s2 + s3;
    float sq = s0 * s0 + s1 * s1 + s2 * s2 + s3 * s3;
    sum = warpReduceSum(sum);
    sq = warpReduceSum(sq);
    if ((tid & 31) == 0) { sh1[tid >> 5] = sum; sh2[tid >> 5] = sq; }
    __syncthreads();
    if (tid < 32) {
        float t1 = (tid < 8) ? sh1[tid] : 0.f;
        float t2 = (tid < 8) ? sh2[tid] : 0.f;
        t1 = warpReduceSum(t1);
        t2 = warpReduceSum(t2);
        if (tid == 0) {
            float mean = t1 * (1.0f / DIM);
            float var = t2 * (1.0f / DIM) - mean * mean;
            stats.x = mean;
            stats.y = rsqrtf(var + 1e-5f);
        }
    }
    __syncthreads();
    const float mean = stats.x, rsc = stats.y;

    float4 gg = ((const float4*)gamma)[tid];
    float4 bb = ((const float4*)beta)[tid];
    float4 o;
    o.x = (s0 - mean) * rsc * gg.x + bb.x;
    o.y = (s1 - mean) * rsc * gg.y + bb.y;
    o.z = (s2 - mean) * rsc * gg.z + bb.z;
    o.w = (s3 - mean) * rsc * gg.w + bb.w;
    if (ROUND) {
        o.x = roundtf(o.x); o.y = roundtf(o.y);
        o.z = roundtf(o.z); o.w = roundtf(o.w);
    }
    ((float4*)(O + base))[tid] = o;
}

// ---------------------------------------------------------------------------
// Launch
// ---------------------------------------------------------------------------
#define SMEM_NN ((AS_FLOATS + BS_FLOATS_NN) * 4 * 4)   // 75776 B
#define SMEM_BF (BF_STAGE_WORDS * 4 * 4)               // 81920 B

extern "C" void kernel_launch(void* const* d_in, const int* in_sizes, int n_in,
                              void* d_out, int out_size)
{
    (void)in_sizes; (void)n_in; (void)out_size;
    const float* x   = (const float*)d_in[0];
    const float* Wq  = (const float*)d_in[1];
    const float* bq  = (const float*)d_in[2];
    const float* Wk  = (const float*)d_in[3];
    const float* bk  = (const float*)d_in[4];
    const float* Wv  = (const float*)d_in[5];
    const float* bv  = (const float*)d_in[6];
    const float* W1  = (const float*)d_in[7];
    const float* b1  = (const float*)d_in[8];
    const float* g1  = (const float*)d_in[9];
    const float* be1 = (const float*)d_in[10];
    const float* W2  = (const float*)d_in[11];
    const float* b2  = (const float*)d_in[12];
    const float* g2  = (const float*)d_in[13];
    const float* be2 = (const float*)d_in[14];
    float* out = (float*)d_out;

    float* base1;
    cudaGetSymbolAddress((void**)&base1, g_scratch);

    __nv_bfloat16* qb = (__nv_bfloat16*)(base1 + OFF_Q);
    __nv_bfloat16* kb = (__nv_bfloat16*)(base1 + OFF_K);
    __nv_bfloat16* vb = (__nv_bfloat16*)(base1 + OFF_V);
    __nv_bfloat16* vt = (__nv_bfloat16*)(base1 + OFF_V + (size_t)16777216);
    __nv_bfloat16* P  = (__nv_bfloat16*)(base1 + OFF_SC);
    float* hd = base1 + OFF_Q;                         // heads f32 (q bf16 dead)
    float* pj = base1 + OFF_K;                         // proj  (k bf16 dead)
    float* y  = base1 + OFF_K + (size_t)TOK * DIM;
    float* z2 = base1 + OFF_K + (size_t)2 * TOK * DIM;
    int*   rowsum = (int*)(base1 + OFF_RS);

    // FREE region conversion buffers (float offsets; sizes verified disjoint):
    __nv_bfloat16* xb   = (__nv_bfloat16*)(base1 + FREE0);                     // 8.39M bf16
    __nv_bfloat16* wqtb = (__nv_bfloat16*)(base1 + FREE0 + (size_t)4194304);   // 4.19M bf16
    __nv_bfloat16* wktb = (__nv_bfloat16*)(base1 + FREE0 + (size_t)6291456);   // 4.19M bf16
    __nv_bfloat16* wvtb = (__nv_bfloat16*)(base1 + FREE0 + (size_t)8388608);   // 4.19M bf16
    float* w1r = base1 + FREE0 + (size_t)10485760;                             // 4.19M f32
    float* w2r = base1 + FREE0 + (size_t)14680064;                             // 1.05M f32

    cudaFuncSetAttribute(tc_gemm<false, 0>,
        cudaFuncAttributeMaxDynamicSharedMemorySize, SMEM_NN);
    cudaFuncSetAttribute(tc_gemm<true, 0>,
        cudaFuncAttributeMaxDynamicSharedMemorySize, SMEM_NN);
    cudaFuncSetAttribute(bf_gemm<2>,
        cudaFuncAttributeMaxDynamicSharedMemorySize, SMEM_BF);
    cudaFuncSetAttribute(bf_gemm<3>,
        cudaFuncAttributeMaxDynamicSharedMemorySize, SMEM_BF);
    cudaFuncSetAttribute(bf_gemm<4>,
        cudaFuncAttributeMaxDynamicSharedMemorySize, SMEM_BF);

    const long long MM = (long long)DIM * DIM;
    const long long HEAD_QKV = (long long)TOK * DIM;   // per-head stride (elems)
    const long long BLK_ATT  = (long long)SEQ * DIM;   // per-z [s][d] (elems)
    const long long BLK_SC   = (long long)SEQ * SEQ;   // per-z P block (elems)
    dim3 blk(128);
    dim3 tblk(32, 8);

    // ---- Conversions (FREE region; no phase constraints) ----
    cvt_bf16_kernel<<<8192, 256>>>(x, xb, (int)(8388608 / 4));
    cvt_transpose_bf16<<<dim3(32, 32, 4), tblk>>>(Wq, wqtb, DIM, DIM, MM, MM);
    cvt_transpose_bf16<<<dim3(32, 32, 4), tblk>>>(Wk, wktb, DIM, DIM, MM, MM);
    cvt_transpose_bf16<<<dim3(32, 32, 4), tblk>>>(Wv, wvtb, DIM, DIM, MM, MM);
    round_kernel<<<4096, 256>>>(W1, w1r, (int)(4194304 / 4));
    round_kernel<<<1024, 256>>>(W2, w2r, (int)(1048576 / 4));
    zero_kernel<<<128, 256>>>(rowsum, NHEAD * NBATCH * SEQ);

    // ---- QKV projections (bf16 NT: A = xb shared, B = W^T[h]) ----
    bf_gemm<4><<<dim3(8, 64, 4), blk, SMEM_BF>>>(
        xb, 0, wqtb, MM, bq, DIM, qb, HEAD_QKV, nullptr, DIM, DIM, DIM, DIM, 1.0f);
    bf_gemm<4><<<dim3(8, 64, 4), blk, SMEM_BF>>>(
        xb, 0, wktb, MM, bk, DIM, kb, HEAD_QKV, nullptr, DIM, DIM, DIM, DIM, 1.0f);
    bf_gemm<4><<<dim3(8, 64, 4), blk, SMEM_BF>>>(
        xb, 0, wvtb, MM, bv, DIM, vb, HEAD_QKV, nullptr, DIM, DIM, DIM, DIM, 1.0f);

    // ---- vt[z][d][s] = v[z][s][d]^T (bf16) ----
    transpose_bf16<<<dim3(32, 64, 16), tblk>>>(vb, vt, BLK_ATT, BLK_ATT);

    // ---- P[z] = exp(q @ k^T / 32) bf16, rowsums (bf16 NT, fused) ----
    bf_gemm<2><<<dim3(16, 16, 16), blk, SMEM_BF>>>(
        qb, BLK_ATT, kb, BLK_ATT, nullptr, 0, P, BLK_SC, rowsum,
        DIM, DIM, DIM, SEQ, 0.03125f);

    // ---- heads[z] = (P @ vt^T) / rowsum  (bf16 NT, f32 rounded out) ----
    bf_gemm<3><<<dim3(8, 16, 16), blk, SMEM_BF>>>(
        P, BLK_SC, vt, BLK_ATT, nullptr, 0, hd, BLK_ATT, rowsum,
        SEQ, SEQ, SEQ, DIM, 1.0f);

    // ---- proj = concat(heads) @ W1 + b1 (tf32 gather; feeds LN) ----
    tc_gemm<true, 0><<<dim3(8, 64, 1), blk, SMEM_NN>>>(
        hd, 0, w1r, 0, b1, 0, pj, 0, NHEAD * DIM, 0, DIM, DIM);

    // ---- y = LN(x + proj), tf32-rounded ----
    add_ln_kernel<true><<<TOK, 256>>>(x, pj, g1, be1, y);

    // ---- z2 = y @ W2 + b2 (tf32 NN) ----
    tc_gemm<false, 0><<<dim3(8, 64, 1), blk, SMEM_NN>>>(
        y, 0, w2r, 0, b2, 0, z2, 0, DIM, DIM, DIM, DIM);

    // ---- out = LN(y + z2) ----
    add_ln_kernel<false><<<TOK, 256>>>(y, z2, g2, be2, out);
}

// round 16
// speedup vs baseline: 3.3475x; 1.3116x over previous
#include <cuda_runtime.h>
#include <cuda_bf16.h>
#include <cstdint>
#include <cstddef>

// Problem shape (fixed): B=4, S=2048, D=1024, H=4
#define TOK    8192
#define DIM    1024
#define NHEAD  4
#define SEQ    2048
#define NBATCH 4

// ---------------------------------------------------------------------------
// Scratch: ONE device-global symbol (640 MB + rowsum). Liveness aliasing:
//   [OFF_Q )  q bf16 [h][t][d]  -> reused as heads bf16 after QK^T
//   [OFF_K )  k bf16            -> reused as pj/y/z2 f32 after QK^T
//   [OFF_V )  v bf16 ; vt bf16 [z][d][s] at OFF_V + 16777216 floats
//   [OFF_SC)  P bf16 [z][s][t] (first 33.5M floats).
//   [FREE0 )  upper half of SC region (33.5M floats, never touched by P).
//     Float offsets from FREE0 (all disjoint, total 13.6M):
//       xb   bf16 @ 0         (4194304 floats)
//       wqtb bf16 @ 4194304   (2097152)
//       wktb bf16 @ 6291456   (2097152)
//       wvtb bf16 @ 8388608   (2097152)
//       w1tb bf16 @ 10485760  (2097152)   [1024][4096] bf16
//       w2r  f32  @ 12582912  (1048576)
//   [OFF_RS)  rowsum int32 [z][s]
// All launches on one stream; ordering makes every alias hazard-free.
// ---------------------------------------------------------------------------
#define OFF_Q  ((size_t)0)
#define OFF_K  ((size_t)33554432)
#define OFF_V  ((size_t)67108864)
#define OFF_SC ((size_t)100663296)
#define FREE0  ((size_t)134217728)
#define OFF_RS ((size_t)167772160)
#define SCRATCH_FLOATS ((size_t)167804928)
__device__ float g_scratch[SCRATCH_FLOATS];

#define RS_SCALE 16384.0f

// ---------------------------------------------------------------------------
// Helpers
// ---------------------------------------------------------------------------
__device__ __forceinline__ uint32_t f2tf(float x) {
    uint32_t y;
    asm("cvt.rna.tf32.f32 %0, %1;" : "=r"(y) : "f"(x));
    return y;
}
__device__ __forceinline__ float roundtf(float x) {
    return __uint_as_float(f2tf(x));
}

__device__ __forceinline__ void mma_tf32(float acc[4], const uint32_t a[4], const uint32_t b[2]) {
    asm volatile(
        "mma.sync.aligned.m16n8k8.row.col.f32.tf32.tf32.f32 "
        "{%0,%1,%2,%3}, {%4,%5,%6,%7}, {%8,%9}, {%0,%1,%2,%3};\n"
        : "+f"(acc[0]), "+f"(acc[1]), "+f"(acc[2]), "+f"(acc[3])
        : "r"(a[0]), "r"(a[1]), "r"(a[2]), "r"(a[3]), "r"(b[0]), "r"(b[1]));
}

__device__ __forceinline__ void mma_bf16(float acc[4], const uint32_t a[4], const uint32_t b[2]) {
    asm volatile(
        "mma.sync.aligned.m16n8k16.row.col.f32.bf16.bf16.f32 "
        "{%0,%1,%2,%3}, {%4,%5,%6,%7}, {%8,%9}, {%0,%1,%2,%3};\n"
        : "+f"(acc[0]), "+f"(acc[1]), "+f"(acc[2]), "+f"(acc[3])
        : "r"(a[0]), "r"(a[1]), "r"(a[2]), "r"(a[3]), "r"(b[0]), "r"(b[1]));
}

__device__ __forceinline__ void ldsm_x4(uint32_t r[4], uint32_t addr) {
    asm volatile("ldmatrix.sync.aligned.m8n8.x4.shared.b16 {%0,%1,%2,%3}, [%4];"
        : "=r"(r[0]), "=r"(r[1]), "=r"(r[2]), "=r"(r[3]) : "r"(addr));
}

__device__ __forceinline__ uint32_t smaddr(const void* p) {
    return (uint32_t)__cvta_generic_to_shared(p);
}

__device__ __forceinline__ void cpasync16(uint32_t dst, const void* src) {
    asm volatile("cp.async.cg.shared.global [%0], [%1], 16;" :: "r"(dst), "l"(src));
}
#define CP_COMMIT() asm volatile("cp.async.commit_group;" ::: "memory")
#define CP_WAIT2()  asm volatile("cp.async.wait_group 2;"  ::: "memory")

__device__ __forceinline__ float warpReduceSum(float v) {
    #pragma unroll
    for (int o = 16; o > 0; o >>= 1) v += __shfl_xor_sync(0xffffffffu, v, o);
    return v;
}

// ---------------------------------------------------------------------------
// Elementwise kernels
// ---------------------------------------------------------------------------
__global__ void __launch_bounds__(256) round_kernel(
    const float* __restrict__ in, float* __restrict__ out, int n4)
{
    int i = blockIdx.x * blockDim.x + threadIdx.x;
    if (i < n4) {
        float4 v = ((const float4*)in)[i];
        v.x = roundtf(v.x); v.y = roundtf(v.y);
        v.z = roundtf(v.z); v.w = roundtf(v.w);
        ((float4*)out)[i] = v;
    }
}

__global__ void __launch_bounds__(256) cvt_bf16_kernel(
    const float* __restrict__ in, __nv_bfloat16* __restrict__ out, int n4)
{
    int i = blockIdx.x * blockDim.x + threadIdx.x;
    if (i < n4) {
        float4 v = ((const float4*)in)[i];
        ((__nv_bfloat162*)out)[i * 2]     = __floats2bfloat162_rn(v.x, v.y);
        ((__nv_bfloat162*)out)[i * 2 + 1] = __floats2bfloat162_rn(v.z, v.w);
    }
}

// Batched f32 -> bf16 transpose: out[C][R] = bf16(in[R][C]) per z.
__global__ void __launch_bounds__(256) cvt_transpose_bf16(
    const float* __restrict__ in, __nv_bfloat16* __restrict__ out,
    int R, int C, long long sIn, long long sOut)
{
    __shared__ float t[32][33];
    const int z = blockIdx.z;
    in += (size_t)z * sIn;
    out += (size_t)z * sOut;
    const int c0 = blockIdx.x * 32, r0 = blockIdx.y * 32;
    #pragma unroll
    for (int i = 0; i < 32; i += 8)
        t[threadIdx.y + i][threadIdx.x] =
            in[(size_t)(r0 + threadIdx.y + i) * C + c0 + threadIdx.x];
    __syncthreads();
    #pragma unroll
    for (int i = 0; i < 32; i += 8)
        out[(size_t)(c0 + threadIdx.y + i) * R + r0 + threadIdx.x] =
            __float2bfloat16(t[threadIdx.x][threadIdx.y + i]);
}

__global__ void __launch_bounds__(256) zero_kernel(int* __restrict__ p, int n)
{
    int i = blockIdx.x * blockDim.x + threadIdx.x;
    if (i < n) p[i] = 0;
}

// Batched bf16 transpose: out[z][D][S] = in[z][S][D]^T.
__global__ void __launch_bounds__(256) transpose_bf16(
    const __nv_bfloat16* __restrict__ in, __nv_bfloat16* __restrict__ out,
    long long sIn, long long sOut)
{
    __shared__ int t[32][33];
    const int z = blockIdx.z;
    in += (size_t)z * sIn;
    out += (size_t)z * sOut;
    const int d0 = blockIdx.x * 32, s0 = blockIdx.y * 32;
    #pragma unroll
    for (int i = 0; i < 32; i += 8)
        t[threadIdx.y + i][threadIdx.x] =
            (int)*(const unsigned short*)(in + (size_t)(s0 + threadIdx.y + i) * DIM + d0 + threadIdx.x);
    __syncthreads();
    #pragma unroll
    for (int i = 0; i < 32; i += 8)
        *(unsigned short*)(out + (size_t)(d0 + threadIdx.y + i) * SEQ + s0 + threadIdx.x) =
            (unsigned short)t[threadIdx.x][threadIdx.y + i];
}

// ---------------------------------------------------------------------------
// TF32 mma.sync GEMM (NN): C[z] = A[z] @ B[z] + bias.  (W2 only.)
// CTA 128x128, BK=16, 128 threads, warp 64x64, 2 CTAs/SM.
// ---------------------------------------------------------------------------
#define AS_FLOATS 2560                     // 128 * 20
#define BS_FLOATS_NN 2176                  // 16 * 136

__global__ void __launch_bounds__(128, 2)
tc_gemm(const float* __restrict__ A, long long sA,
        const float* __restrict__ B, long long sB,
        const float* __restrict__ bias, long long sBias,
        float* __restrict__ C, long long sC,
        int K, int lda, int ldb, int ldc)
{
    constexpr int STAGE_FLOATS = AS_FLOATS + BS_FLOATS_NN;
    extern __shared__ float sm[];

    const int tid = threadIdx.x;
    const int z = blockIdx.z;
    A += (size_t)z * sA;
    B += (size_t)z * sB;
    C += (size_t)z * sC;
    const float* bp = bias ? bias + (size_t)z * sBias : nullptr;

    const int m0 = blockIdx.y * 128;
    const int n0 = blockIdx.x * 128;
    const int NKT = K >> 4;

    const int lane = tid & 31, warp = tid >> 5;
    const int wm = warp >> 1, wn = warp & 1;
    const int g = lane >> 2, tg = lane & 3;

    auto load_stage = [&](int kt, int st) {
        float* as = sm + st * STAGE_FLOATS;
        float* bs = as + AS_FLOATS;
        const int kbase = kt * 16;
        #pragma unroll
        for (int i = 0; i < 4; i++) {
            int id = tid + i * 128;
            int m = id >> 2, c4 = (id & 3) << 2;
            cpasync16(smaddr(as + m * 20 + c4),
                      A + (size_t)(m0 + m) * lda + kbase + c4);
        }
        #pragma unroll
        for (int i = 0; i < 4; i++) {
            int id = tid + i * 128;
            int kr = id >> 5, nc = (id & 31) << 2;
            cpasync16(smaddr(bs + kr * 136 + nc),
                      B + (size_t)(kbase + kr) * ldb + n0 + nc);
        }
    };

    float acc[4][8][4];
    #pragma unroll
    for (int mt = 0; mt < 4; mt++)
        #pragma unroll
        for (int nt = 0; nt < 8; nt++)
            #pragma unroll
            for (int r = 0; r < 4; r++) acc[mt][nt][r] = 0.f;

    load_stage(0, 0); CP_COMMIT();
    load_stage(1, 1); CP_COMMIT();
    load_stage(2, 2); CP_COMMIT();

    for (int kt = 0; kt < NKT; kt++) {
        CP_WAIT2();
        __syncthreads();

        const uint32_t* as = reinterpret_cast<const uint32_t*>(sm + (kt & 3) * STAGE_FLOATS);
        const uint32_t* bs = as + AS_FLOATS;

        #pragma unroll
        for (int ks = 0; ks < 2; ks++) {
            const int kk = ks * 8;
            uint32_t af[4][4], bf[8][2];
            #pragma unroll
            for (int mt = 0; mt < 4; mt++) {
                int r = wm * 64 + mt * 16 + g;
                af[mt][0] = as[r * 20 + kk + tg];
                af[mt][1] = as[(r + 8) * 20 + kk + tg];
                af[mt][2] = as[r * 20 + kk + tg + 4];
                af[mt][3] = as[(r + 8) * 20 + kk + tg + 4];
            }
            #pragma unroll
            for (int nt = 0; nt < 8; nt++) {
                int c = wn * 64 + nt * 8 + g;
                bf[nt][0] = bs[(kk + tg) * 136 + c];
                bf[nt][1] = bs[(kk + tg + 4) * 136 + c];
            }
            #pragma unroll
            for (int mt = 0; mt < 4; mt++)
                #pragma unroll
                for (int nt = 0; nt < 8; nt++)
                    mma_tf32(acc[mt][nt], af[mt], bf[nt]);
        }

        if (kt + 3 < NKT) load_stage(kt + 3, (kt + 3) & 3);
        CP_COMMIT();
    }

    #pragma unroll
    for (int nt = 0; nt < 8; nt++) {
        const int c = n0 + wn * 64 + nt * 8 + tg * 2;
        float b0 = 0.f, b1 = 0.f;
        if (bp) { b0 = bp[c]; b1 = bp[c + 1]; }
        #pragma unroll
        for (int mt = 0; mt < 4; mt++) {
            const int r0 = m0 + wm * 64 + mt * 16 + g;
            float2 w0, w1;
            w0.x = acc[mt][nt][0] + b0; w0.y = acc[mt][nt][1] + b1;
            w1.x = acc[mt][nt][2] + b0; w1.y = acc[mt][nt][3] + b1;
            *(float2*)(C + (size_t)r0 * ldc + c) = w0;
            *(float2*)(C + (size_t)(r0 + 8) * ldc + c) = w1;
        }
    }
}

// ---------------------------------------------------------------------------
// BF16 mma.sync GEMM (NT, ldmatrix fragments): C[z] = f( A[z] @ B[z]^T )
//   A: [M][K] bf16 (K contiguous; GATHER = heads-concat over k), B: [N][K] bf16.
// EMODE 2: e = exp(alpha*acc) -> bf16 C; fixed-point atomic row sums to rsum.
// EMODE 4: bf16(acc + bias) -> bf16 C.            (QKV projections)
// EMODE 5: bf16(acc * RS_SCALE / rsum[row]) -> bf16 C.   (PV normalize)
// EMODE 6: f32(acc + bias) -> f32 C.              (W1 gather)
// CTA 128x128, BK=32, 128 threads, warp 64x64, 2 CTAs/SM, 4-stage cp.async.
// smem rows: 64B data + 16B pad = 80B; 5r mod 8 permutation -> LDSM conflict-free.
// ---------------------------------------------------------------------------
#define BF_ROW_WORDS 20                    // 80 bytes per row
#define BF_TILE_WORDS (128 * BF_ROW_WORDS) // 2560 u32 per operand tile
#define BF_STAGE_WORDS (2 * BF_TILE_WORDS) // 5120 u32 = 20480 B

template<int EMODE, bool GATHER>
__global__ void __launch_bounds__(128, 2)
bf_gemm(const __nv_bfloat16* __restrict__ A, long long sA,
        const __nv_bfloat16* __restrict__ B, long long sB,
        const float* __restrict__ bias, long long sBias,
        void* __restrict__ Cv, long long sC,
        int* __restrict__ rsum,
        int K, int lda, int ldb, int ldc, float alpha)
{
    extern __shared__ uint32_t smw[];

    const int tid = threadIdx.x;
    const int z = blockIdx.z;
    if (!GATHER) A += (size_t)z * sA;
    B += (size_t)z * sB;
    const float* bp = bias ? bias + (size_t)z * sBias : nullptr;
    __nv_bfloat16* Cb = (EMODE == 6) ? nullptr : ((__nv_bfloat16*)Cv + (size_t)z * sC);
    float* Cf = (EMODE == 6) ? ((float*)Cv + (size_t)z * sC) : nullptr;

    const int m0 = blockIdx.y * 128;
    const int n0 = blockIdx.x * 128;
    const int NKT = K >> 5;

    const int lane = tid & 31, warp = tid >> 5;
    const int wm = warp >> 1, wn = warp & 1;   // 2x2 -> warp 64x64
    const int g = lane >> 2, tg = lane & 3;

    auto load_stage = [&](int kt, int st) {
        uint32_t* as = smw + st * BF_STAGE_WORDS;
        uint32_t* bs = as + BF_TILE_WORDS;
        const int kbase = kt * 32;
        #pragma unroll
        for (int i = 0; i < 4; i++) {                // A: 128 x 32 bf16
            int id = tid + i * 128;
            int m = id >> 2, q16 = id & 3;
            const __nv_bfloat16* src;
            if (GATHER) {
                int kk = kbase + q16 * 8;
                src = A + ((size_t)(kk >> 10)) * ((size_t)TOK * DIM)
                        + (size_t)(m0 + m) * DIM + (kk & (DIM - 1));
            } else {
                src = A + (size_t)(m0 + m) * lda + kbase + q16 * 8;
            }
            cpasync16(smaddr(as + m * BF_ROW_WORDS + q16 * 4), src);
        }
        #pragma unroll
        for (int i = 0; i < 4; i++) {                // B: 128 x 32 bf16
            int id = tid + i * 128;
            int n = id >> 2, q16 = id & 3;
            cpasync16(smaddr(bs + n * BF_ROW_WORDS + q16 * 4),
                      B + (size_t)(n0 + n) * ldb + kbase + q16 * 8);
        }
    };

    float acc[4][8][4];
    #pragma unroll
    for (int mt = 0; mt < 4; mt++)
        #pragma unroll
        for (int nt = 0; nt < 8; nt++)
            #pragma unroll
            for (int r = 0; r < 4; r++) acc[mt][nt][r] = 0.f;

    load_stage(0, 0); CP_COMMIT();
    load_stage(1, 1); CP_COMMIT();
    load_stage(2, 2); CP_COMMIT();

    // ldmatrix per-lane byte offsets (verified against scalar fragment map):
    //   A x4: m0=[r..r+7,k0-7] m1=[r+8..,k0-7] m2=[r..,k8-15] m3=[r+8..,k8-15]
    //   B x4 (nt pair): m0=[n..n+7,k0-7] m1=[n..,k8-15] m2=[n+8..,k0-7] m3=[n+8..,k8-15]
    const uint32_t smem0 = smaddr(smw);
    const uint32_t lane_a = (uint32_t)((lane & 15) * 80 + (lane >> 4) * 16
                                       + wm * 64 * 80);
    const uint32_t lane_b = (uint32_t)(((lane & 7) + (lane >> 4) * 8) * 80
                                       + ((lane >> 3) & 1) * 16 + wn * 64 * 80);

    for (int kt = 0; kt < NKT; kt++) {
        CP_WAIT2();
        __syncthreads();

        const uint32_t stage_b = smem0 + (uint32_t)((kt & 3) * (BF_STAGE_WORDS * 4));
        const uint32_t ab = stage_b + lane_a;
        const uint32_t bb = stage_b + (uint32_t)(BF_TILE_WORDS * 4) + lane_b;

        #pragma unroll
        for (int ks = 0; ks < 2; ks++) {
            const uint32_t kbyte = (uint32_t)(ks * 32);
            uint32_t af[4][4], bfr[8][2];
            #pragma unroll
            for (int mt = 0; mt < 4; mt++)
                ldsm_x4(af[mt], ab + (uint32_t)(mt * 1280) + kbyte);
            #pragma unroll
            for (int p = 0; p < 4; p++) {
                uint32_t t[4];
                ldsm_x4(t, bb + (uint32_t)(p * 1280) + kbyte);
                bfr[2 * p][0] = t[0]; bfr[2 * p][1] = t[1];
                bfr[2 * p + 1][0] = t[2]; bfr[2 * p + 1][1] = t[3];
            }
            #pragma unroll
            for (int mt = 0; mt < 4; mt++)
                #pragma unroll
                for (int nt = 0; nt < 8; nt++)
                    mma_bf16(acc[mt][nt], af[mt], bfr[nt]);
        }

        if (kt + 3 < NKT) load_stage(kt + 3, (kt + 3) & 3);
        CP_COMMIT();
    }

    if (EMODE == 2) {
        int* rs = rsum + (size_t)z * SEQ;
        float rp0[4] = {0.f, 0.f, 0.f, 0.f};
        float rp1[4] = {0.f, 0.f, 0.f, 0.f};
        #pragma unroll
        for (int nt = 0; nt < 8; nt++) {
            const int c = n0 + wn * 64 + nt * 8 + tg * 2;
            #pragma unroll
            for (int mt = 0; mt < 4; mt++) {
                const int r0 = m0 + wm * 64 + mt * 16 + g;
                __nv_bfloat162 p0 = __floats2bfloat162_rn(
                    __expf(alpha * acc[mt][nt][0]), __expf(alpha * acc[mt][nt][1]));
                __nv_bfloat162 p1 = __floats2bfloat162_rn(
                    __expf(alpha * acc[mt][nt][2]), __expf(alpha * acc[mt][nt][3]));
                *(__nv_bfloat162*)(Cb + (size_t)r0 * ldc + c) = p0;
                *(__nv_bfloat162*)(Cb + (size_t)(r0 + 8) * ldc + c) = p1;
                rp0[mt] += __low2float(p0) + __high2float(p0);
                rp1[mt] += __low2float(p1) + __high2float(p1);
            }
        }
        #pragma unroll
        for (int mt = 0; mt < 4; mt++) {
            float p0 = rp0[mt], p1 = rp1[mt];
            p0 += __shfl_xor_sync(0xffffffffu, p0, 1);
            p0 += __shfl_xor_sync(0xffffffffu, p0, 2);
            p1 += __shfl_xor_sync(0xffffffffu, p1, 1);
            p1 += __shfl_xor_sync(0xffffffffu, p1, 2);
            if (tg == 0) {
                const int r0 = m0 + wm * 64 + mt * 16 + g;
                atomicAdd(&rs[r0], __float2int_rn(p0 * RS_SCALE));
                atomicAdd(&rs[r0 + 8], __float2int_rn(p1 * RS_SCALE));
            }
        }
    } else if (EMODE == 5) {
        int* rs = rsum + (size_t)z * SEQ;
        #pragma unroll
        for (int mt = 0; mt < 4; mt++) {
            const int r0 = m0 + wm * 64 + mt * 16 + g;
            const float inv0 = RS_SCALE / (float)rs[r0];
            const float inv1 = RS_SCALE / (float)rs[r0 + 8];
            #pragma unroll
            for (int nt = 0; nt < 8; nt++) {
                const int c = n0 + wn * 64 + nt * 8 + tg * 2;
                *(__nv_bfloat162*)(Cb + (size_t)r0 * ldc + c) =
                    __floats2bfloat162_rn(acc[mt][nt][0] * inv0, acc[mt][nt][1] * inv0);
                *(__nv_bfloat162*)(Cb + (size_t)(r0 + 8) * ldc + c) =
                    __floats2bfloat162_rn(acc[mt][nt][2] * inv1, acc[mt][nt][3] * inv1);
            }
        }
    } else if (EMODE == 6) {
        #pragma unroll
        for (int nt = 0; nt < 8; nt++) {
            const int c = n0 + wn * 64 + nt * 8 + tg * 2;
            float b0 = 0.f, b1 = 0.f;
            if (bp) { b0 = bp[c]; b1 = bp[c + 1]; }
            #pragma unroll
            for (int mt = 0; mt < 4; mt++) {
                const int r0 = m0 + wm * 64 + mt * 16 + g;
                float2 w0, w1;
                w0.x = acc[mt][nt][0] + b0; w0.y = acc[mt][nt][1] + b1;
                w1.x = acc[mt][nt][2] + b0; w1.y = acc[mt][nt][3] + b1;
                *(float2*)(Cf + (size_t)r0 * ldc + c) = w0;
                *(float2*)(Cf + (size_t)(r0 + 8) * ldc + c) = w1;
            }
        }
    } else {   // EMODE 4: bias + bf16 store
        #pragma unroll
        for (int nt = 0; nt < 8; nt++) {
            const int c = n0 + wn * 64 + nt * 8 + tg * 2;
            float b0 = 0.f, b1 = 0.f;
            if (bp) { b0 = bp[c]; b1 = bp[c + 1]; }
            #pragma unroll
            for (int mt = 0; mt < 4; mt++) {
                const int r0 = m0 + wm * 64 + mt * 16 + g;
                *(__nv_bfloat162*)(Cb + (size_t)r0 * ldc + c) =
                    __floats2bfloat162_rn(acc[mt][nt][0] + b0, acc[mt][nt][1] + b1);
                *(__nv_bfloat162*)(Cb + (size_t)(r0 + 8) * ldc + c) =
                    __floats2bfloat162_rn(acc[mt][nt][2] + b0, acc[mt][nt][3] + b1);
            }
        }
    }
}

// ---------------------------------------------------------------------------
// out = LayerNorm(a + b) * gamma + beta  (rows of D=1024, biased var, eps=1e-5)
// ---------------------------------------------------------------------------
template<bool ROUND>
__global__ void __launch_bounds__(256) add_ln_kernel(
    const float* __restrict__ A, const float* __restrict__ Bv,
    const float* __restrict__ gamma, const float* __restrict__ beta,
    float* __restrict__ O)
{
    __shared__ float sh1[32], sh2[32];
    __shared__ float2 stats;
    const size_t base = (size_t)blockIdx.x * DIM;
    const int tid = threadIdx.x;

    float4 a = ((const float4*)(A + base))[tid];
    float4 b = ((const float4*)(Bv + base))[tid];
    float s0 = a.x + b.x, s1 = a.y + b.y, s2 = a.z + b.z, s3 = a.w + b.w;

    float sum = s0 + s1 + s2 + s3;
    float sq = s0 * s0 + s1 * s1 + s2 * s2 + s3 * s3;
    sum = warpReduceSum(sum);
    sq = warpReduceSum(sq);
    if ((tid & 31) == 0) { sh1[tid >> 5] = sum; sh2[tid >> 5] = sq; }
    __syncthreads();
    if (tid < 32) {
        float t1 = (tid < 8) ? sh1[tid] : 0.f;
        float t2 = (tid < 8) ? sh2[tid] : 0.f;
        t1 = warpReduceSum(t1);
        t2 = warpReduceSum(t2);
        if (tid == 0) {
            float mean = t1 * (1.0f / DIM);
            float var = t2 * (1.0f / DIM) - mean * mean;
            stats.x = mean;
            stats.y = rsqrtf(var + 1e-5f);
        }
    }
    __syncthreads();
    const float mean = stats.x, rsc = stats.y;

    float4 gg = ((const float4*)gamma)[tid];
    float4 bb = ((const float4*)beta)[tid];
    float4 o;
    o.x = (s0 - mean) * rsc * gg.x + bb.x;
    o.y = (s1 - mean) * rsc * gg.y + bb.y;
    o.z = (s2 - mean) * rsc * gg.z + bb.z;
    o.w = (s3 - mean) * rsc * gg.w + bb.w;
    if (ROUND) {
        o.x = roundtf(o.x); o.y = roundtf(o.y);
        o.z = roundtf(o.z); o.w = roundtf(o.w);
    }
    ((float4*)(O + base))[tid] = o;
}

// ---------------------------------------------------------------------------
// Launch
// ---------------------------------------------------------------------------
#define SMEM_NN ((AS_FLOATS + BS_FLOATS_NN) * 4 * 4)   // 75776 B
#define SMEM_BF (BF_STAGE_WORDS * 4 * 4)               // 81920 B

extern "C" void kernel_launch(void* const* d_in, const int* in_sizes, int n_in,
                              void* d_out, int out_size)
{
    (void)in_sizes; (void)n_in; (void)out_size;
    const float* x   = (const float*)d_in[0];
    const float* Wq  = (const float*)d_in[1];
    const float* bq  = (const float*)d_in[2];
    const float* Wk  = (const float*)d_in[3];
    const float* bk  = (const float*)d_in[4];
    const float* Wv  = (const float*)d_in[5];
    const float* bv  = (const float*)d_in[6];
    const float* W1  = (const float*)d_in[7];
    const float* b1  = (const float*)d_in[8];
    const float* g1  = (const float*)d_in[9];
    const float* be1 = (const float*)d_in[10];
    const float* W2  = (const float*)d_in[11];
    const float* b2  = (const float*)d_in[12];
    const float* g2  = (const float*)d_in[13];
    const float* be2 = (const float*)d_in[14];
    float* out = (float*)d_out;

    float* base1;
    cudaGetSymbolAddress((void**)&base1, g_scratch);

    __nv_bfloat16* qb = (__nv_bfloat16*)(base1 + OFF_Q);
    __nv_bfloat16* kb = (__nv_bfloat16*)(base1 + OFF_K);
    __nv_bfloat16* vb = (__nv_bfloat16*)(base1 + OFF_V);
    __nv_bfloat16* vt = (__nv_bfloat16*)(base1 + OFF_V + (size_t)16777216);
    __nv_bfloat16* P  = (__nv_bfloat16*)(base1 + OFF_SC);
    __nv_bfloat16* hdb = (__nv_bfloat16*)(base1 + OFF_Q);  // heads bf16 (q dead)
    float* pj = base1 + OFF_K;                              // proj (k dead)
    float* y  = base1 + OFF_K + (size_t)TOK * DIM;
    float* z2 = base1 + OFF_K + (size_t)2 * TOK * DIM;
    int*   rowsum = (int*)(base1 + OFF_RS);

    // FREE region conversion buffers (float offsets; disjoint):
    __nv_bfloat16* xb   = (__nv_bfloat16*)(base1 + FREE0);
    __nv_bfloat16* wqtb = (__nv_bfloat16*)(base1 + FREE0 + (size_t)4194304);
    __nv_bfloat16* wktb = (__nv_bfloat16*)(base1 + FREE0 + (size_t)6291456);
    __nv_bfloat16* wvtb = (__nv_bfloat16*)(base1 + FREE0 + (size_t)8388608);
    __nv_bfloat16* w1tb = (__nv_bfloat16*)(base1 + FREE0 + (size_t)10485760);
    float* w2r = base1 + FREE0 + (size_t)12582912;

    cudaFuncSetAttribute(tc_gemm,
        cudaFuncAttributeMaxDynamicSharedMemorySize, SMEM_NN);
    cudaFuncSetAttribute(bf_gemm<2, false>,
        cudaFuncAttributeMaxDynamicSharedMemorySize, SMEM_BF);
    cudaFuncSetAttribute(bf_gemm<4, false>,
        cudaFuncAttributeMaxDynamicSharedMemorySize, SMEM_BF);
    cudaFuncSetAttribute(bf_gemm<5, false>,
        cudaFuncAttributeMaxDynamicSharedMemorySize, SMEM_BF);
    cudaFuncSetAttribute(bf_gemm<6, true>,
        cudaFuncAttributeMaxDynamicSharedMemorySize, SMEM_BF);

    const long long MM = (long long)DIM * DIM;
    const long long HEAD_QKV = (long long)TOK * DIM;   // per-head stride (elems)
    const long long BLK_ATT  = (long long)SEQ * DIM;   // per-z [s][d] (elems)
    const long long BLK_SC   = (long long)SEQ * SEQ;   // per-z P block (elems)
    dim3 blk(128);
    dim3 tblk(32, 8);

    // ---- Conversions (FREE region; no phase constraints) ----
    cvt_bf16_kernel<<<8192, 256>>>(x, xb, (int)(8388608 / 4));
    cvt_transpose_bf16<<<dim3(32, 32, 4), tblk>>>(Wq, wqtb, DIM, DIM, MM, MM);
    cvt_transpose_bf16<<<dim3(32, 32, 4), tblk>>>(Wk, wktb, DIM, DIM, MM, MM);
    cvt_transpose_bf16<<<dim3(32, 32, 4), tblk>>>(Wv, wvtb, DIM, DIM, MM, MM);
    cvt_transpose_bf16<<<dim3(32, 128, 1), tblk>>>(W1, w1tb, NHEAD * DIM, DIM, 0, 0);
    round_kernel<<<1024, 256>>>(W2, w2r, (int)(1048576 / 4));
    zero_kernel<<<128, 256>>>(rowsum, NHEAD * NBATCH * SEQ);

    // ---- QKV projections (bf16 NT: A = xb shared, B = W^T[h]) ----
    bf_gemm<4, false><<<dim3(8, 64, 4), blk, SMEM_BF>>>(
        xb, 0, wqtb, MM, bq, DIM, qb, HEAD_QKV, nullptr, DIM, DIM, DIM, DIM, 1.0f);
    bf_gemm<4, false><<<dim3(8, 64, 4), blk, SMEM_BF>>>(
        xb, 0, wktb, MM, bk, DIM, kb, HEAD_QKV, nullptr, DIM, DIM, DIM, DIM, 1.0f);
    bf_gemm<4, false><<<dim3(8, 64, 4), blk, SMEM_BF>>>(
        xb, 0, wvtb, MM, bv, DIM, vb, HEAD_QKV, nullptr, DIM, DIM, DIM, DIM, 1.0f);

    // ---- vt[z][d][s] = v[z][s][d]^T (bf16) ----
    transpose_bf16<<<dim3(32, 64, 16), tblk>>>(vb, vt, BLK_ATT, BLK_ATT);

    // ---- P[z] = exp(q @ k^T / 32) bf16, rowsums (bf16 NT, fused) ----
    bf_gemm<2, false><<<dim3(16, 16, 16), blk, SMEM_BF>>>(
        qb, BLK_ATT, kb, BLK_ATT, nullptr, 0, P, BLK_SC, rowsum,
        DIM, DIM, DIM, SEQ, 0.03125f);

    // ---- heads[z] = (P @ vt^T) / rowsum  (bf16 NT -> bf16 heads) ----
    bf_gemm<5, false><<<dim3(8, 16, 16), blk, SMEM_BF>>>(
        P, BLK_SC, vt, BLK_ATT, nullptr, 0, hdb, BLK_ATT, rowsum,
        SEQ, SEQ, SEQ, DIM, 1.0f);

    // ---- proj = concat(heads) @ W1 + b1 (bf16 gather, f32 out) ----
    bf_gemm<6, true><<<dim3(8, 64, 1), blk, SMEM_BF>>>(
        hdb, 0, w1tb, 0, b1, 0, pj, 0, nullptr,
        NHEAD * DIM, DIM, NHEAD * DIM, DIM, 1.0f);

    // ---- y = LN(x + proj), tf32-rounded (feeds tf32 W2) ----
    add_ln_kernel<true><<<TOK, 256>>>(x, pj, g1, be1, y);

    // ---- z2 = y @ W2 + b2 (tf32 NN) ----
    tc_gemm<<<dim3(8, 64, 1), blk, SMEM_NN>>>(
        y, 0, w2r, 0, b2, 0, z2, 0, DIM, DIM, DIM, DIM);

    // ---- out = LN(y + z2) ----
    add_ln_kernel<false><<<TOK, 256>>>(y, z2, g2, be2, out);
}

// round 17
// speedup vs baseline: 3.3497x; 1.0007x over previous
#include <cuda_runtime.h>
#include <cuda_bf16.h>
#include <cstdint>
#include <cstddef>

// Problem shape (fixed): B=4, S=2048, D=1024, H=4
#define TOK    8192
#define DIM    1024
#define NHEAD  4
#define SEQ    2048
#define NBATCH 4

// ---------------------------------------------------------------------------
// Scratch: ONE device-global symbol (640 MB + rowsum). Liveness aliasing:
//   [OFF_Q )  q bf16 [h][t][d]  -> reused as heads bf16 after QK^T
//   [OFF_K )  k bf16            -> reused as pj/y/z2 f32 after QK^T
//   [OFF_V )  v bf16 ; vt bf16 [z][d][s] at OFF_V + 16777216 floats
//   [OFF_SC)  P bf16 [z][s][t] (first 33.5M floats).
//   [FREE0 )  upper half of SC region (33.5M floats, never touched by P).
//     Float offsets from FREE0 (all disjoint):
//       xb   bf16 @ 0         (4194304 floats)
//       wqtb bf16 @ 4194304   (2097152)  [then wktb, wvtb contiguous]
//       wktb bf16 @ 6291456   (2097152)
//       wvtb bf16 @ 8388608   (2097152)
//       w1tb bf16 @ 10485760  (2097152)
//       w2r  f32  @ 12582912  (1048576)
//   [OFF_RS)  rowsum int32 [z][s]
// All launches on one stream; ordering makes every alias hazard-free.
// ---------------------------------------------------------------------------
#define OFF_Q  ((size_t)0)
#define OFF_K  ((size_t)33554432)
#define OFF_V  ((size_t)67108864)
#define OFF_SC ((size_t)100663296)
#define FREE0  ((size_t)134217728)
#define OFF_RS ((size_t)167772160)
#define SCRATCH_FLOATS ((size_t)167804928)
__device__ float g_scratch[SCRATCH_FLOATS];

#define RS_SCALE 16384.0f

// ---------------------------------------------------------------------------
// Helpers
// ---------------------------------------------------------------------------
__device__ __forceinline__ uint32_t f2tf(float x) {
    uint32_t y;
    asm("cvt.rna.tf32.f32 %0, %1;" : "=r"(y) : "f"(x));
    return y;
}
__device__ __forceinline__ float roundtf(float x) {
    return __uint_as_float(f2tf(x));
}

__device__ __forceinline__ void mma_tf32(float acc[4], const uint32_t a[4], const uint32_t b[2]) {
    asm volatile(
        "mma.sync.aligned.m16n8k8.row.col.f32.tf32.tf32.f32 "
        "{%0,%1,%2,%3}, {%4,%5,%6,%7}, {%8,%9}, {%0,%1,%2,%3};\n"
        : "+f"(acc[0]), "+f"(acc[1]), "+f"(acc[2]), "+f"(acc[3])
        : "r"(a[0]), "r"(a[1]), "r"(a[2]), "r"(a[3]), "r"(b[0]), "r"(b[1]));
}

__device__ __forceinline__ void mma_bf16(float acc[4], const uint32_t a[4], const uint32_t b[2]) {
    asm volatile(
        "mma.sync.aligned.m16n8k16.row.col.f32.bf16.bf16.f32 "
        "{%0,%1,%2,%3}, {%4,%5,%6,%7}, {%8,%9}, {%0,%1,%2,%3};\n"
        : "+f"(acc[0]), "+f"(acc[1]), "+f"(acc[2]), "+f"(acc[3])
        : "r"(a[0]), "r"(a[1]), "r"(a[2]), "r"(a[3]), "r"(b[0]), "r"(b[1]));
}

__device__ __forceinline__ void ldsm_x4(uint32_t r[4], uint32_t addr) {
    asm volatile("ldmatrix.sync.aligned.m8n8.x4.shared.b16 {%0,%1,%2,%3}, [%4];"
        : "=r"(r[0]), "=r"(r[1]), "=r"(r[2]), "=r"(r[3]) : "r"(addr));
}

__device__ __forceinline__ uint32_t smaddr(const void* p) {
    return (uint32_t)__cvta_generic_to_shared(p);
}

__device__ __forceinline__ void cpasync16(uint32_t dst, const void* src) {
    asm volatile("cp.async.cg.shared.global [%0], [%1], 16;" :: "r"(dst), "l"(src));
}
#define CP_COMMIT() asm volatile("cp.async.commit_group;" ::: "memory")
#define CP_WAIT2()  asm volatile("cp.async.wait_group 2;"  ::: "memory")
#define CP_WAIT3()  asm volatile("cp.async.wait_group 3;"  ::: "memory")

__device__ __forceinline__ float warpReduceSum(float v) {
    #pragma unroll
    for (int o = 16; o > 0; o >>= 1) v += __shfl_xor_sync(0xffffffffu, v, o);
    return v;
}

// ---------------------------------------------------------------------------
// Elementwise kernels
// ---------------------------------------------------------------------------
__global__ void __launch_bounds__(256) round_kernel(
    const float* __restrict__ in, float* __restrict__ out, int n4)
{
    int i = blockIdx.x * blockDim.x + threadIdx.x;
    if (i < n4) {
        float4 v = ((const float4*)in)[i];
        v.x = roundtf(v.x); v.y = roundtf(v.y);
        v.z = roundtf(v.z); v.w = roundtf(v.w);
        ((float4*)out)[i] = v;
    }
}

__global__ void __launch_bounds__(256) cvt_bf16_kernel(
    const float* __restrict__ in, __nv_bfloat16* __restrict__ out, int n4)
{
    int i = blockIdx.x * blockDim.x + threadIdx.x;
    if (i < n4) {
        float4 v = ((const float4*)in)[i];
        ((__nv_bfloat162*)out)[i * 2]     = __floats2bfloat162_rn(v.x, v.y);
        ((__nv_bfloat162*)out)[i * 2 + 1] = __floats2bfloat162_rn(v.z, v.w);
    }
}

// Batched f32 -> bf16 transpose: out[C][R] = bf16(in[R][C]) per z.
__global__ void __launch_bounds__(256) cvt_transpose_bf16(
    const float* __restrict__ in, __nv_bfloat16* __restrict__ out,
    int R, int C, long long sIn, long long sOut)
{
    __shared__ float t[32][33];
    const int z = blockIdx.z;
    in += (size_t)z * sIn;
    out += (size_t)z * sOut;
    const int c0 = blockIdx.x * 32, r0 = blockIdx.y * 32;
    #pragma unroll
    for (int i = 0; i < 32; i += 8)
        t[threadIdx.y + i][threadIdx.x] =
            in[(size_t)(r0 + threadIdx.y + i) * C + c0 + threadIdx.x];
    __syncthreads();
    #pragma unroll
    for (int i = 0; i < 32; i += 8)
        out[(size_t)(c0 + threadIdx.y + i) * R + r0 + threadIdx.x] =
            __float2bfloat16(t[threadIdx.x][threadIdx.y + i]);
}

__global__ void __launch_bounds__(256) zero_kernel(int* __restrict__ p, int n)
{
    int i = blockIdx.x * blockDim.x + threadIdx.x;
    if (i < n) p[i] = 0;
}

// Batched bf16 transpose: out[z][D][S] = in[z][S][D]^T.
__global__ void __launch_bounds__(256) transpose_bf16(
    const __nv_bfloat16* __restrict__ in, __nv_bfloat16* __restrict__ out,
    long long sIn, long long sOut)
{
    __shared__ int t[32][33];
    const int z = blockIdx.z;
    in += (size_t)z * sIn;
    out += (size_t)z * sOut;
    const int d0 = blockIdx.x * 32, s0 = blockIdx.y * 32;
    #pragma unroll
    for (int i = 0; i < 32; i += 8)
        t[threadIdx.y + i][threadIdx.x] =
            (int)*(const unsigned short*)(in + (size_t)(s0 + threadIdx.y + i) * DIM + d0 + threadIdx.x);
    __syncthreads();
    #pragma unroll
    for (int i = 0; i < 32; i += 8)
        *(unsigned short*)(out + (size_t)(d0 + threadIdx.y + i) * SEQ + s0 + threadIdx.x) =
            (unsigned short)t[threadIdx.x][threadIdx.y + i];
}

// ---------------------------------------------------------------------------
// TF32 mma.sync GEMM (NN): C[z] = A[z] @ B[z] + bias.  (W2 only.)
// CTA 128x128, BK=16, 128 threads, warp 64x64, 2 CTAs/SM, 4-stage.
// ---------------------------------------------------------------------------
#define AS_FLOATS 2560                     // 128 * 20
#define BS_FLOATS_NN 2176                  // 16 * 136

__global__ void __launch_bounds__(128, 2)
tc_gemm(const float* __restrict__ A, long long sA,
        const float* __restrict__ B, long long sB,
        const float* __restrict__ bias, long long sBias,
        float* __restrict__ C, long long sC,
        int K, int lda, int ldb, int ldc)
{
    constexpr int STAGE_FLOATS = AS_FLOATS + BS_FLOATS_NN;
    extern __shared__ float sm[];

    const int tid = threadIdx.x;
    const int z = blockIdx.z;
    A += (size_t)z * sA;
    B += (size_t)z * sB;
    C += (size_t)z * sC;
    const float* bp = bias ? bias + (size_t)z * sBias : nullptr;

    const int m0 = blockIdx.y * 128;
    const int n0 = blockIdx.x * 128;
    const int NKT = K >> 4;

    const int lane = tid & 31, warp = tid >> 5;
    const int wm = warp >> 1, wn = warp & 1;
    const int g = lane >> 2, tg = lane & 3;

    auto load_stage = [&](int kt, int st) {
        float* as = sm + st * STAGE_FLOATS;
        float* bs = as + AS_FLOATS;
        const int kbase = kt * 16;
        #pragma unroll
        for (int i = 0; i < 4; i++) {
            int id = tid + i * 128;
            int m = id >> 2, c4 = (id & 3) << 2;
            cpasync16(smaddr(as + m * 20 + c4),
                      A + (size_t)(m0 + m) * lda + kbase + c4);
        }
        #pragma unroll
        for (int i = 0; i < 4; i++) {
            int id = tid + i * 128;
            int kr = id >> 5, nc = (id & 31) << 2;
            cpasync16(smaddr(bs + kr * 136 + nc),
                      B + (size_t)(kbase + kr) * ldb + n0 + nc);
        }
    };

    float acc[4][8][4];
    #pragma unroll
    for (int mt = 0; mt < 4; mt++)
        #pragma unroll
        for (int nt = 0; nt < 8; nt++)
            #pragma unroll
            for (int r = 0; r < 4; r++) acc[mt][nt][r] = 0.f;

    load_stage(0, 0); CP_COMMIT();
    load_stage(1, 1); CP_COMMIT();
    load_stage(2, 2); CP_COMMIT();

    for (int kt = 0; kt < NKT; kt++) {
        CP_WAIT2();
        __syncthreads();

        const uint32_t* as = reinterpret_cast<const uint32_t*>(sm + (kt & 3) * STAGE_FLOATS);
        const uint32_t* bs = as + AS_FLOATS;

        #pragma unroll
        for (int ks = 0; ks < 2; ks++) {
            const int kk = ks * 8;
            uint32_t af[4][4], bf[8][2];
            #pragma unroll
            for (int mt = 0; mt < 4; mt++) {
                int r = wm * 64 + mt * 16 + g;
                af[mt][0] = as[r * 20 + kk + tg];
                af[mt][1] = as[(r + 8) * 20 + kk + tg];
                af[mt][2] = as[r * 20 + kk + tg + 4];
                af[mt][3] = as[(r + 8) * 20 + kk + tg + 4];
            }
            #pragma unroll
            for (int nt = 0; nt < 8; nt++) {
                int c = wn * 64 + nt * 8 + g;
                bf[nt][0] = bs[(kk + tg) * 136 + c];
                bf[nt][1] = bs[(kk + tg + 4) * 136 + c];
            }
            #pragma unroll
            for (int mt = 0; mt < 4; mt++)
                #pragma unroll
                for (int nt = 0; nt < 8; nt++)
                    mma_tf32(acc[mt][nt], af[mt], bf[nt]);
        }

        if (kt + 3 < NKT) load_stage(kt + 3, (kt + 3) & 3);
        CP_COMMIT();
    }

    #pragma unroll
    for (int nt = 0; nt < 8; nt++) {
        const int c = n0 + wn * 64 + nt * 8 + tg * 2;
        float b0 = 0.f, b1 = 0.f;
        if (bp) { b0 = bp[c]; b1 = bp[c + 1]; }
        #pragma unroll
        for (int mt = 0; mt < 4; mt++) {
            const int r0 = m0 + wm * 64 + mt * 16 + g;
            float2 w0, w1;
            w0.x = acc[mt][nt][0] + b0; w0.y = acc[mt][nt][1] + b1;
            w1.x = acc[mt][nt][2] + b0; w1.y = acc[mt][nt][3] + b1;
            *(float2*)(C + (size_t)r0 * ldc + c) = w0;
            *(float2*)(C + (size_t)(r0 + 8) * ldc + c) = w1;
        }
    }
}

// ---------------------------------------------------------------------------
// BF16 mma.sync GEMM (NT, ldmatrix fragments): C[z] = f( A[z] @ B[z]^T )
//   A: [M][K] bf16 (K contiguous; GATHER = heads-concat over k), B: [N][K] bf16.
// EMODE 2: e = exp(alpha*acc) -> bf16 C; fixed-point atomic row sums to rsum.
// EMODE 4: bf16(acc + bias) -> bf16 C.            (QKV / generic)
// EMODE 5: bf16(acc * RS_SCALE / rsum[row]) -> bf16 C.   (PV normalize)
// EMODE 6: f32(acc + bias) -> f32 C.              (W1 gather)
// QKV: fused 3-projection mode; z in [0,12): sel = z>>2 picks {q,k,v} weight/
//      bias/output, h = z&3 picks the head. Callsite passes base pointers.
// CTA 128x128, BK=32, 128 threads, warp 64x64, 2 CTAs/SM, 5-stage cp.async.
// All 32 LDSM of both k16 sub-steps are hoisted ahead of the MMAs.
// smem rows: 64B data + 16B pad = 80B; 5r mod 8 permutation -> LDSM conflict-free.
// ---------------------------------------------------------------------------
#define BF_ROW_WORDS 20                    // 80 bytes per row
#define BF_TILE_WORDS (128 * BF_ROW_WORDS) // 2560 u32 per operand tile
#define BF_STAGE_WORDS (2 * BF_TILE_WORDS) // 5120 u32 = 20480 B
#define BF_NSTAGE 5

template<int EMODE, bool GATHER, bool QKV>
__global__ void __launch_bounds__(128, 2)
bf_gemm(const __nv_bfloat16* __restrict__ A, long long sA,
        const __nv_bfloat16* __restrict__ B, long long sB,
        const float* __restrict__ bias, long long sBias,
        const float* __restrict__ bias2, const float* __restrict__ bias3,
        void* __restrict__ Cv, long long sC,
        int* __restrict__ rsum,
        int K, int lda, int ldb, int ldc, float alpha)
{
    extern __shared__ uint32_t smw[];

    const int tid = threadIdx.x;
    const int z = blockIdx.z;
    const float* bp;
    __nv_bfloat16* Cb;
    float* Cf = nullptr;
    if (QKV) {
        const int sel = z >> 2, h = z & 3;
        B += (size_t)(sel * 4 + h) * 1048576;                 // [sel][h][out][in]
        Cb = (__nv_bfloat16*)Cv + (size_t)sel * 67108864
                                + (size_t)h * 8388608;        // q/k/v regions
        const float* bsel = (sel == 0) ? bias : (sel == 1) ? bias2 : bias3;
        bp = bsel + (size_t)h * DIM;
    } else {
        if (!GATHER) A += (size_t)z * sA;
        B += (size_t)z * sB;
        bp = bias ? bias + (size_t)z * sBias : nullptr;
        if (EMODE == 6) Cf = (float*)Cv + (size_t)z * sC;
        Cb = (EMODE == 6) ? nullptr : ((__nv_bfloat16*)Cv + (size_t)z * sC);
    }

    const int m0 = blockIdx.y * 128;
    const int n0 = blockIdx.x * 128;
    const int NKT = K >> 5;

    const int lane = tid & 31, warp = tid >> 5;
    const int wm = warp >> 1, wn = warp & 1;   // 2x2 -> warp 64x64
    const int g = lane >> 2, tg = lane & 3;

    auto load_stage = [&](int kt, int st) {
        uint32_t* as = smw + st * BF_STAGE_WORDS;
        uint32_t* bs = as + BF_TILE_WORDS;
        const int kbase = kt * 32;
        #pragma unroll
        for (int i = 0; i < 4; i++) {                // A: 128 x 32 bf16
            int id = tid + i * 128;
            int m = id >> 2, q16 = id & 3;
            const __nv_bfloat16* src;
            if (GATHER) {
                int kk = kbase + q16 * 8;
                src = A + ((size_t)(kk >> 10)) * ((size_t)TOK * DIM)
                        + (size_t)(m0 + m) * DIM + (kk & (DIM - 1));
            } else {
                src = A + (size_t)(m0 + m) * lda + kbase + q16 * 8;
            }
            cpasync16(smaddr(as + m * BF_ROW_WORDS + q16 * 4), src);
        }
        #pragma unroll
        for (int i = 0; i < 4; i++) {                // B: 128 x 32 bf16
            int id = tid + i * 128;
            int n = id >> 2, q16 = id & 3;
            cpasync16(smaddr(bs + n * BF_ROW_WORDS + q16 * 4),
                      B + (size_t)(n0 + n) * ldb + kbase + q16 * 8);
        }
    };

    float acc[4][8][4];
    #pragma unroll
    for (int mt = 0; mt < 4; mt++)
        #pragma unroll
        for (int nt = 0; nt < 8; nt++)
            #pragma unroll
            for (int r = 0; r < 4; r++) acc[mt][nt][r] = 0.f;

    load_stage(0, 0); CP_COMMIT();
    load_stage(1, 1); CP_COMMIT();
    load_stage(2, 2); CP_COMMIT();
    load_stage(3, 3); CP_COMMIT();

    // ldmatrix per-lane byte offsets (verified against scalar fragment map):
    //   A x4: m0=[r..r+7,k0-7] m1=[r+8..,k0-7] m2=[r..,k8-15] m3=[r+8..,k8-15]
    //   B x4 (nt pair): m0=[n..n+7,k0-7] m1=[n..,k8-15] m2=[n+8..,k0-7] m3=[n+8..,k8-15]
    const uint32_t smem0 = smaddr(smw);
    const uint32_t lane_a = (uint32_t)((lane & 15) * 80 + (lane >> 4) * 16
                                       + wm * 64 * 80);
    const uint32_t lane_b = (uint32_t)(((lane & 7) + (lane >> 4) * 8) * 80
                                       + ((lane >> 3) & 1) * 16 + wn * 64 * 80);

    int st = 0;
    for (int kt = 0; kt < NKT; kt++) {
        CP_WAIT3();
        __syncthreads();

        const uint32_t stage_b = smem0 + (uint32_t)(st * (BF_STAGE_WORDS * 4));
        const uint32_t ab = stage_b + lane_a;
        const uint32_t bb = stage_b + (uint32_t)(BF_TILE_WORDS * 4) + lane_b;

        // Hoist all 32 LDSM (both k16 sub-steps) ahead of the MMA burst.
        uint32_t af[2][4][4], bfr[2][8][2];
        #pragma unroll
        for (int ks = 0; ks < 2; ks++) {
            const uint32_t kbyte = (uint32_t)(ks * 32);
            #pragma unroll
            for (int mt = 0; mt < 4; mt++)
                ldsm_x4(af[ks][mt], ab + (uint32_t)(mt * 1280) + kbyte);
            #pragma unroll
            for (int p = 0; p < 4; p++) {
                uint32_t t[4];
                ldsm_x4(t, bb + (uint32_t)(p * 1280) + kbyte);
                bfr[ks][2 * p][0] = t[0]; bfr[ks][2 * p][1] = t[1];
                bfr[ks][2 * p + 1][0] = t[2]; bfr[ks][2 * p + 1][1] = t[3];
            }
        }
        #pragma unroll
        for (int ks = 0; ks < 2; ks++)
            #pragma unroll
            for (int mt = 0; mt < 4; mt++)
                #pragma unroll
                for (int nt = 0; nt < 8; nt++)
                    mma_bf16(acc[mt][nt], af[ks][mt], bfr[ks][nt]);

        if (kt + 4 < NKT) {
            int st2 = st + 4; if (st2 >= BF_NSTAGE) st2 -= BF_NSTAGE;
            load_stage(kt + 4, st2);
        }
        CP_COMMIT();
        if (++st == BF_NSTAGE) st = 0;
    }

    if (EMODE == 2) {
        int* rs = rsum + (size_t)z * SEQ;
        float rp0[4] = {0.f, 0.f, 0.f, 0.f};
        float rp1[4] = {0.f, 0.f, 0.f, 0.f};
        #pragma unroll
        for (int nt = 0; nt < 8; nt++) {
            const int c = n0 + wn * 64 + nt * 8 + tg * 2;
            #pragma unroll
            for (int mt = 0; mt < 4; mt++) {
                const int r0 = m0 + wm * 64 + mt * 16 + g;
                __nv_bfloat162 p0 = __floats2bfloat162_rn(
                    __expf(alpha * acc[mt][nt][0]), __expf(alpha * acc[mt][nt][1]));
                __nv_bfloat162 p1 = __floats2bfloat162_rn(
                    __expf(alpha * acc[mt][nt][2]), __expf(alpha * acc[mt][nt][3]));
                *(__nv_bfloat162*)(Cb + (size_t)r0 * ldc + c) = p0;
                *(__nv_bfloat162*)(Cb + (size_t)(r0 + 8) * ldc + c) = p1;
                rp0[mt] += __low2float(p0) + __high2float(p0);
                rp1[mt] += __low2float(p1) + __high2float(p1);
            }
        }
        #pragma unroll
        for (int mt = 0; mt < 4; mt++) {
            float p0 = rp0[mt], p1 = rp1[mt];
            p0 += __shfl_xor_sync(0xffffffffu, p0, 1);
            p0 += __shfl_xor_sync(0xffffffffu, p0, 2);
            p1 += __shfl_xor_sync(0xffffffffu, p1, 1);
            p1 += __shfl_xor_sync(0xffffffffu, p1, 2);
            if (tg == 0) {
                const int r0 = m0 + wm * 64 + mt * 16 + g;
                atomicAdd(&rs[r0], __float2int_rn(p0 * RS_SCALE));
                atomicAdd(&rs[r0 + 8], __float2int_rn(p1 * RS_SCALE));
            }
        }
    } else if (EMODE == 5) {
        int* rs = rsum + (size_t)z * SEQ;
        #pragma unroll
        for (int mt = 0; mt < 4; mt++) {
            const int r0 = m0 + wm * 64 + mt * 16 + g;
            const float inv0 = RS_SCALE / (float)rs[r0];
            const float inv1 = RS_SCALE / (float)rs[r0 + 8];
            #pragma unroll
            for (int nt = 0; nt < 8; nt++) {
                const int c = n0 + wn * 64 + nt * 8 + tg * 2;
                *(__nv_bfloat162*)(Cb + (size_t)r0 * ldc + c) =
                    __floats2bfloat162_rn(acc[mt][nt][0] * inv0, acc[mt][nt][1] * inv0);
                *(__nv_bfloat162*)(Cb + (size_t)(r0 + 8) * ldc + c) =
                    __floats2bfloat162_rn(acc[mt][nt][2] * inv1, acc[mt][nt][3] * inv1);
            }
        }
    } else if (EMODE == 6) {
        #pragma unroll
        for (int nt = 0; nt < 8; nt++) {
            const int c = n0 + wn * 64 + nt * 8 + tg * 2;
            float b0 = 0.f, b1 = 0.f;
            if (bp) { b0 = bp[c]; b1 = bp[c + 1]; }
            #pragma unroll
            for (int mt = 0; mt < 4; mt++) {
                const int r0 = m0 + wm * 64 + mt * 16 + g;
                float2 w0, w1;
                w0.x = acc[mt][nt][0] + b0; w0.y = acc[mt][nt][1] + b1;
                w1.x = acc[mt][nt][2] + b0; w1.y = acc[mt][nt][3] + b1;
                *(float2*)(Cf + (size_t)r0 * ldc + c) = w0;
                *(float2*)(Cf + (size_t)(r0 + 8) * ldc + c) = w1;
            }
        }
    } else {   // EMODE 4: bias + bf16 store
        #pragma unroll
        for (int nt = 0; nt < 8; nt++) {
            const int c = n0 + wn * 64 + nt * 8 + tg * 2;
            float b0 = 0.f, b1 = 0.f;
            if (bp) { b0 = bp[c]; b1 = bp[c + 1]; }
            #pragma unroll
            for (int mt = 0; mt < 4; mt++) {
                const int r0 = m0 + wm * 64 + mt * 16 + g;
                *(__nv_bfloat162*)(Cb + (size_t)r0 * ldc + c) =
                    __floats2bfloat162_rn(acc[mt][nt][0] + b0, acc[mt][nt][1] + b1);
                *(__nv_bfloat162*)(Cb + (size_t)(r0 + 8) * ldc + c) =
                    __floats2bfloat162_rn(acc[mt][nt][2] + b0, acc[mt][nt][3] + b1);
            }
        }
    }
}

// ---------------------------------------------------------------------------
// out = LayerNorm(a + b) * gamma + beta  (rows of D=1024, biased var, eps=1e-5)
// ---------------------------------------------------------------------------
template<bool ROUND>
__global__ void __launch_bounds__(256) add_ln_kernel(
    const float* __restrict__ A, const float* __restrict__ Bv,
    const float* __restrict__ gamma, const float* __restrict__ beta,
    float* __restrict__ O)
{
    __shared__ float sh1[32], sh2[32];
    __shared__ float2 stats;
    const size_t base = (size_t)blockIdx.x * DIM;
    const int tid = threadIdx.x;

    float4 a = ((const float4*)(A + base))[tid];
    float4 b = ((const float4*)(Bv + base))[tid];
    float s0 = a.x + b.x, s1 = a.y + b.y, s2 = a.z + b.z, s3 = a.w + b.w;

    float sum = s0 + s1 + s2 + s3;
    float sq = s0 * s0 + s1 * s1 + s2 * s2 + s3 * s3;
    sum = warpReduceSum(sum);
    sq = warpReduceSum(sq);
    if ((tid & 31) == 0) { sh1[tid >> 5] = sum; sh2[tid >> 5] = sq; }
    __syncthreads();
    if (tid < 32) {
        float t1 = (tid < 8) ? sh1[tid] : 0.f;
        float t2 = (tid < 8) ? sh2[tid] : 0.f;
        t1 = warpReduceSum(t1);
        t2 = warpReduceSum(t2);
        if (tid == 0) {
            float mean = t1 * (1.0f / DIM);
            float var = t2 * (1.0f / DIM) - mean * mean;
            stats.x = mean;
            stats.y = rsqrtf(var + 1e-5f);
        }
    }
    __syncthreads();
    const float mean = stats.x, rsc = stats.y;

    float4 gg = ((const float4*)gamma)[tid];
    float4 bb = ((const float4*)beta)[tid];
    float4 o;
    o.x = (s0 - mean) * rsc * gg.x + bb.x;
    o.y = (s1 - mean) * rsc * gg.y + bb.y;
    o.z = (s2 - mean) * rsc * gg.z + bb.z;
    o.w = (s3 - mean) * rsc * gg.w + bb.w;
    if (ROUND) {
        o.x = roundtf(o.x); o.y = roundtf(o.y);
        o.z = roundtf(o.z); o.w = roundtf(o.w);
    }
    ((float4*)(O + base))[tid] = o;
}

// ---------------------------------------------------------------------------
// Launch
// ---------------------------------------------------------------------------
#define SMEM_NN ((AS_FLOATS + BS_FLOATS_NN) * 4 * 4)   // 75776 B
#define SMEM_BF (BF_STAGE_WORDS * 4 * BF_NSTAGE)       // 102400 B

extern "C" void kernel_launch(void* const* d_in, const int* in_sizes, int n_in,
                              void* d_out, int out_size)
{
    (void)in_sizes; (void)n_in; (void)out_size;
    const float* x   = (const float*)d_in[0];
    const float* Wq  = (const float*)d_in[1];
    const float* bq  = (const float*)d_in[2];
    const float* Wk  = (const float*)d_in[3];
    const float* bk  = (const float*)d_in[4];
    const float* Wv  = (const float*)d_in[5];
    const float* bv  = (const float*)d_in[6];
    const float* W1  = (const float*)d_in[7];
    const float* b1  = (const float*)d_in[8];
    const float* g1  = (const float*)d_in[9];
    const float* be1 = (const float*)d_in[10];
    const float* W2  = (const float*)d_in[11];
    const float* b2  = (const float*)d_in[12];
    const float* g2  = (const float*)d_in[13];
    const float* be2 = (const float*)d_in[14];
    float* out = (float*)d_out;

    float* base1;
    cudaGetSymbolAddress((void**)&base1, g_scratch);

    __nv_bfloat16* qb = (__nv_bfloat16*)(base1 + OFF_Q);
    __nv_bfloat16* kb = (__nv_bfloat16*)(base1 + OFF_K);
    __nv_bfloat16* vb = (__nv_bfloat16*)(base1 + OFF_V);
    __nv_bfloat16* vt = (__nv_bfloat16*)(base1 + OFF_V + (size_t)16777216);
    __nv_bfloat16* P  = (__nv_bfloat16*)(base1 + OFF_SC);
    __nv_bfloat16* hdb = (__nv_bfloat16*)(base1 + OFF_Q);  // heads bf16 (q dead)
    float* pj = base1 + OFF_K;                              // proj (k dead)
    float* y  = base1 + OFF_K + (size_t)TOK * DIM;
    float* z2 = base1 + OFF_K + (size_t)2 * TOK * DIM;
    int*   rowsum = (int*)(base1 + OFF_RS);

    // FREE region conversion buffers (float offsets; disjoint):
    __nv_bfloat16* xb   = (__nv_bfloat16*)(base1 + FREE0);
    __nv_bfloat16* wqtb = (__nv_bfloat16*)(base1 + FREE0 + (size_t)4194304);
    __nv_bfloat16* wktb = (__nv_bfloat16*)(base1 + FREE0 + (size_t)6291456);
    __nv_bfloat16* wvtb = (__nv_bfloat16*)(base1 + FREE0 + (size_t)8388608);
    __nv_bfloat16* w1tb = (__nv_bfloat16*)(base1 + FREE0 + (size_t)10485760);
    float* w2r = base1 + FREE0 + (size_t)12582912;

    cudaFuncSetAttribute(tc_gemm,
        cudaFuncAttributeMaxDynamicSharedMemorySize, SMEM_NN);
    cudaFuncSetAttribute(bf_gemm<2, false, false>,
        cudaFuncAttributeMaxDynamicSharedMemorySize, SMEM_BF);
    cudaFuncSetAttribute(bf_gemm<4, false, true>,
        cudaFuncAttributeMaxDynamicSharedMemorySize, SMEM_BF);
    cudaFuncSetAttribute(bf_gemm<5, false, false>,
        cudaFuncAttributeMaxDynamicSharedMemorySize, SMEM_BF);
    cudaFuncSetAttribute(bf_gemm<6, true, false>,
        cudaFuncAttributeMaxDynamicSharedMemorySize, SMEM_BF);

    const long long MM = (long long)DIM * DIM;
    const long long HEAD_QKV = (long long)TOK * DIM;   // per-head stride (elems)
    const long long BLK_ATT  = (long long)SEQ * DIM;   // per-z [s][d] (elems)
    const long long BLK_SC   = (long long)SEQ * SEQ;   // per-z P block (elems)
    dim3 blk(128);
    dim3 tblk(32, 8);

    // ---- Conversions (FREE region; no phase constraints) ----
    cvt_bf16_kernel<<<8192, 256>>>(x, xb, (int)(8388608 / 4));
    cvt_transpose_bf16<<<dim3(32, 32, 4), tblk>>>(Wq, wqtb, DIM, DIM, MM, MM);
    cvt_transpose_bf16<<<dim3(32, 32, 4), tblk>>>(Wk, wktb, DIM, DIM, MM, MM);
    cvt_transpose_bf16<<<dim3(32, 32, 4), tblk>>>(Wv, wvtb, DIM, DIM, MM, MM);
    cvt_transpose_bf16<<<dim3(32, 128, 1), tblk>>>(W1, w1tb, NHEAD * DIM, DIM, 0, 0);
    round_kernel<<<1024, 256>>>(W2, w2r, (int)(1048576 / 4));
    zero_kernel<<<128, 256>>>(rowsum, NHEAD * NBATCH * SEQ);

    // ---- QKV projections fused: z = sel*4 + h, one launch ----
    bf_gemm<4, false, true><<<dim3(8, 64, 12), blk, SMEM_BF>>>(
        xb, 0, wqtb, 0, bq, 0, bk, bv, qb, 0, nullptr,
        DIM, DIM, DIM, DIM, 1.0f);

    // ---- vt[z][d][s] = v[z][s][d]^T (bf16) ----
    transpose_bf16<<<dim3(32, 64, 16), tblk>>>(vb, vt, BLK_ATT, BLK_ATT);

    // ---- P[z] = exp(q @ k^T / 32) bf16, rowsums (bf16 NT, fused) ----
    bf_gemm<2, false, false><<<dim3(16, 16, 16), blk, SMEM_BF>>>(
        qb, BLK_ATT, kb, BLK_ATT, nullptr, 0, nullptr, nullptr, P, BLK_SC, rowsum,
        DIM, DIM, DIM, SEQ, 0.03125f);

    // ---- heads[z] = (P @ vt^T) / rowsum  (bf16 NT -> bf16 heads) ----
    bf_gemm<5, false, false><<<dim3(8, 16, 16), blk, SMEM_BF>>>(
        P, BLK_SC, vt, BLK_ATT, nullptr, 0, nullptr, nullptr, hdb, BLK_ATT, rowsum,
        SEQ, SEQ, SEQ, DIM, 1.0f);

    // ---- proj = concat(heads) @ W1 + b1 (bf16 gather, f32 out) ----
    bf_gemm<6, true, false><<<dim3(8, 64, 1), blk, SMEM_BF>>>(
        hdb, 0, w1tb, 0, b1, 0, nullptr, nullptr, pj, 0, nullptr,
        NHEAD * DIM, DIM, NHEAD * DIM, DIM, 1.0f);

    // ---- y = LN(x + proj), tf32-rounded (feeds tf32 W2) ----
    add_ln_kernel<true><<<TOK, 256>>>(x, pj, g1, be1, y);

    // ---- z2 = y @ W2 + b2 (tf32 NN) ----
    tc_gemm<<<dim3(8, 64, 1), blk, SMEM_NN>>>(
        y, 0, w2r, 0, b2, 0, z2, 0, DIM, DIM, DIM, DIM);

    // ---- out = LN(y + z2) ----
    add_ln_kernel<false><<<TOK, 256>>>(y, z2, g2, be2, out);
}